// round 4
// baseline (speedup 1.0000x reference)
#include <cuda_runtime.h>
#include <cuda_bf16.h>
#include <math.h>

// Problem constants
#define NB    32
#define DIMC  256
#define HEADS 4
#define DH    32
#define HID   128      // HEADS*DH
#define THREE 384      // 3*HID
#define NSP   4096     // 64*64 spatial
#define SCALE 0.17677669529663687f  // 32^-0.5
#define EPS   1e-5f

// Scratch (device globals; allowed, no runtime allocation)
__device__ float g_qkv[(size_t)NB * THREE * NSP];   // ~201 MB
__device__ float g_ctx[NB * HEADS * DH * DH];       // 512 KB
__device__ float g_wf [(size_t)NB * DIMC * HID];    // 4 MB

// ---------------------------------------------------------------------------
// Kernel 1: per-batch GEMM  qkv[b,o,n] = sum_c W[o,c] * x[b,c,n]
// 128x128 tile, BK=8, 256 threads, 8x8 register micro-tile
// ---------------------------------------------------------------------------
__global__ __launch_bounds__(256) void qkv_gemm(const float* __restrict__ W,
                                                const float* __restrict__ X) {
    __shared__ float As[8][128];
    __shared__ float Bs[8][128];
    const int b  = blockIdx.z;
    const int n0 = blockIdx.x * 128;
    const int m0 = blockIdx.y * 128;
    const float* Xb = X + (size_t)b * DIMC * NSP;
    float* Cb = g_qkv + (size_t)b * THREE * NSP;

    const int tid = threadIdx.x;
    const int tx = tid & 15, ty = tid >> 4;

    float acc[8][8];
#pragma unroll
    for (int i = 0; i < 8; i++)
#pragma unroll
        for (int j = 0; j < 8; j++) acc[i][j] = 0.f;

    for (int k0 = 0; k0 < DIMC; k0 += 8) {
        {   // A tile: W[m0+r][k0+k], 128x8
            int idx = tid * 4;
            int r = idx >> 3, k = idx & 7;
            float4 a = *(const float4*)&W[(m0 + r) * DIMC + k0 + k];
            As[k + 0][r] = a.x; As[k + 1][r] = a.y;
            As[k + 2][r] = a.z; As[k + 3][r] = a.w;
        }
        {   // B tile: X[k0+k][n0+nn], 8x128
            int idx = tid * 4;
            int k = idx >> 7, nn = idx & 127;
            *(float4*)&Bs[k][nn] =
                *(const float4*)&Xb[(size_t)(k0 + k) * NSP + n0 + nn];
        }
        __syncthreads();
#pragma unroll
        for (int k = 0; k < 8; k++) {
            float ra[8], rb[8];
#pragma unroll
            for (int i = 0; i < 8; i++) ra[i] = As[k][ty + 16 * i];
#pragma unroll
            for (int j = 0; j < 8; j++) rb[j] = Bs[k][tx + 16 * j];
#pragma unroll
            for (int i = 0; i < 8; i++)
#pragma unroll
                for (int j = 0; j < 8; j++) acc[i][j] += ra[i] * rb[j];
        }
        __syncthreads();
    }
#pragma unroll
    for (int i = 0; i < 8; i++) {
        int r = m0 + ty + 16 * i;
#pragma unroll
        for (int j = 0; j < 8; j++) {
            int c = n0 + tx + 16 * j;
            Cb[(size_t)r * NSP + c] = acc[i][j];
        }
    }
}

// ---------------------------------------------------------------------------
// Kernel 2: q softmax over d (axis -2), in place on rows [0,128) of qkv[b],
// then multiply by SCALE. One thread per (b,h,n); loads are coalesced across n.
// ---------------------------------------------------------------------------
__global__ __launch_bounds__(256) void q_softmax() {
    int idx = blockIdx.x * blockDim.x + threadIdx.x;  // 0 .. 32*4*4096-1
    int n  = idx & (NSP - 1);
    int bh = idx >> 12;
    int b = bh >> 2, h = bh & 3;
    float* base = g_qkv + (size_t)b * THREE * NSP + (size_t)(h * DH) * NSP + n;

    float v[DH];
    float mx = -1e30f;
#pragma unroll
    for (int d = 0; d < DH; d++) { v[d] = base[(size_t)d * NSP]; mx = fmaxf(mx, v[d]); }
    float s = 0.f;
#pragma unroll
    for (int d = 0; d < DH; d++) { v[d] = __expf(v[d] - mx); s += v[d]; }
    float inv = SCALE / s;
#pragma unroll
    for (int d = 0; d < DH; d++) base[(size_t)d * NSP] = v[d] * inv;
}

// ---------------------------------------------------------------------------
// Kernel 3: k softmax over n (axis -1), in place on rows [128,256) of qkv[b].
// One block per row; row cached in smem.
// ---------------------------------------------------------------------------
__global__ __launch_bounds__(256) void k_softmax() {
    __shared__ float buf[NSP];
    __shared__ float red[256];
    int row = blockIdx.x;              // b*128 + r
    int b = row >> 7, r = row & 127;
    float* base = g_qkv + (size_t)b * THREE * NSP + (size_t)(HID + r) * NSP;
    int tid = threadIdx.x;

    float mx = -1e30f;
    for (int i = tid; i < NSP; i += 256) { float x = base[i]; buf[i] = x; mx = fmaxf(mx, x); }
    red[tid] = mx; __syncthreads();
    for (int s = 128; s > 0; s >>= 1) {
        if (tid < s) red[tid] = fmaxf(red[tid], red[tid + s]);
        __syncthreads();
    }
    mx = red[0]; __syncthreads();

    float sum = 0.f;
    for (int i = tid; i < NSP; i += 256) { float e = __expf(buf[i] - mx); buf[i] = e; sum += e; }
    red[tid] = sum; __syncthreads();
    for (int s = 128; s > 0; s >>= 1) {
        if (tid < s) red[tid] += red[tid + s];
        __syncthreads();
    }
    float inv = 1.0f / red[0];
    __syncthreads();
    for (int i = tid; i < NSP; i += 256) base[i] = buf[i] * inv;
}

// ---------------------------------------------------------------------------
// Kernel 4: context[b,h,d,e] = sum_n k[d,n]*v[e,n]. One block per (b,h).
// 4 groups of 64 threads split the n range; 4x4 register tile per thread.
// ---------------------------------------------------------------------------
__global__ __launch_bounds__(256) void ctx_kernel() {
    __shared__ float Ks[4][32][33];
    __shared__ float Vs[4][32][33];
    __shared__ float racc[3][64][16];
    int bh = blockIdx.x;
    int b = bh >> 2, h = bh & 3;
    const float* kbase = g_qkv + (size_t)b * THREE * NSP + (size_t)(HID + h * DH) * NSP;
    const float* vbase = g_qkv + (size_t)b * THREE * NSP + (size_t)(2 * HID + h * DH) * NSP;

    int tid = threadIdx.x;
    int grp = tid >> 6;
    int t   = tid & 63;
    int td = t >> 3, te = t & 7;

    float acc[4][4];
#pragma unroll
    for (int i = 0; i < 4; i++)
#pragma unroll
        for (int j = 0; j < 4; j++) acc[i][j] = 0.f;

    const int base_n = grp * 1024;
    for (int cc = 0; cc < 1024; cc += 32) {
        int c0 = base_n + cc;
        // load 32x32 K and V chunks for this group (scalar stores into padded smem)
#pragma unroll
        for (int m = 0; m < 4; m++) {
            int fi = m * 64 + t;          // float4 index in 32x32 tile
            int dd = fi >> 3;
            int nn = (fi & 7) * 4;
            float4 kv = *(const float4*)&kbase[(size_t)dd * NSP + c0 + nn];
            float4 vv = *(const float4*)&vbase[(size_t)dd * NSP + c0 + nn];
            Ks[grp][dd][nn+0] = kv.x; Ks[grp][dd][nn+1] = kv.y;
            Ks[grp][dd][nn+2] = kv.z; Ks[grp][dd][nn+3] = kv.w;
            Vs[grp][dd][nn+0] = vv.x; Vs[grp][dd][nn+1] = vv.y;
            Vs[grp][dd][nn+2] = vv.z; Vs[grp][dd][nn+3] = vv.w;
        }
        __syncthreads();
#pragma unroll 4
        for (int n = 0; n < 32; n++) {
            float ka[4], vb[4];
#pragma unroll
            for (int i = 0; i < 4; i++) ka[i] = Ks[grp][td * 4 + i][n];
#pragma unroll
            for (int j = 0; j < 4; j++) vb[j] = Vs[grp][te * 4 + j][n];
#pragma unroll
            for (int i = 0; i < 4; i++)
#pragma unroll
                for (int j = 0; j < 4; j++) acc[i][j] += ka[i] * vb[j];
        }
        __syncthreads();
    }

    if (grp > 0) {
#pragma unroll
        for (int i = 0; i < 4; i++)
#pragma unroll
            for (int j = 0; j < 4; j++) racc[grp - 1][t][i * 4 + j] = acc[i][j];
    }
    __syncthreads();
    if (grp == 0) {
#pragma unroll
        for (int gg = 0; gg < 3; gg++)
#pragma unroll
            for (int i = 0; i < 4; i++)
#pragma unroll
                for (int j = 0; j < 4; j++) acc[i][j] += racc[gg][t][i * 4 + j];
#pragma unroll
        for (int i = 0; i < 4; i++)
#pragma unroll
            for (int j = 0; j < 4; j++)
                g_ctx[((size_t)bh * DH + td * 4 + i) * DH + te * 4 + j] = acc[i][j];
    }
}

// ---------------------------------------------------------------------------
// Kernel 5: fused weight Wf[b,o,h*32+d] = sum_e w_out[o,h*32+e]*ctx[b,h,d,e]
// One block per batch, thread = output row o.
// ---------------------------------------------------------------------------
__global__ __launch_bounds__(256) void wf_kernel(const float* __restrict__ w_out) {
    __shared__ float cs[HEADS][DH][DH];   // 16 KB
    int b = blockIdx.x;
    int tid = threadIdx.x;
    for (int i = tid; i < HEADS * DH * DH; i += 256)
        ((float*)cs)[i] = g_ctx[(size_t)b * HEADS * DH * DH + i];
    __syncthreads();

    int o = tid;   // 0..255
    float* dst = g_wf + ((size_t)b * DIMC + o) * HID;
#pragma unroll
    for (int h = 0; h < HEADS; h++) {
        float w[DH];
#pragma unroll
        for (int e = 0; e < DH; e++) w[e] = w_out[o * HID + h * DH + e];
#pragma unroll 4
        for (int d = 0; d < DH; d++) {
            float s = 0.f;
#pragma unroll
            for (int e = 0; e < DH; e++) s += w[e] * cs[h][d][e];
            dst[h * DH + d] = s;
        }
    }
}

// ---------------------------------------------------------------------------
// Kernel 6: out[b,o,n] = sum_j Wf[b,o,j]*q[b,j,n] + b_out[o], then LayerNorm
// over o (256) per (b,n), * g + beta. Block owns a full 256 x 64 column tile.
// ---------------------------------------------------------------------------
__global__ __launch_bounds__(256) void out_ln(const float* __restrict__ b_out,
                                              const float* __restrict__ gamma,
                                              const float* __restrict__ beta,
                                              float* __restrict__ out) {
    __shared__ float As[8][256];
    __shared__ float Bs[8][64];
    __shared__ float rsum[32][64];
    __shared__ float rsq [32][64];
    __shared__ float mean_s[64], rstd_s[64];

    const int b  = blockIdx.y;
    const int n0 = blockIdx.x * 64;
    const float* Wf = g_wf + (size_t)b * DIMC * HID;
    const float* Q  = g_qkv + (size_t)b * THREE * NSP;   // rows [0,128) hold softmaxed q*SCALE

    const int tid = threadIdx.x;
    const int tx = tid & 7, ty = tid >> 3;   // 8 x 32

    float acc[8][8];
#pragma unroll
    for (int i = 0; i < 8; i++)
#pragma unroll
        for (int j = 0; j < 8; j++) acc[i][j] = 0.f;

    for (int k0 = 0; k0 < HID; k0 += 8) {
        {   // A tile: Wf[o][k0..k0+7], each thread loads its own row o = tid
            float4 a0 = *(const float4*)&Wf[tid * HID + k0];
            float4 a1 = *(const float4*)&Wf[tid * HID + k0 + 4];
            As[0][tid] = a0.x; As[1][tid] = a0.y; As[2][tid] = a0.z; As[3][tid] = a0.w;
            As[4][tid] = a1.x; As[5][tid] = a1.y; As[6][tid] = a1.z; As[7][tid] = a1.w;
        }
        {   // B tile: Q[k0+k][n0+nn], 8x64
            int idx = tid * 2;
            int k = idx >> 6, nn = idx & 63;
            float2 v = *(const float2*)&Q[(size_t)(k0 + k) * NSP + n0 + nn];
            Bs[k][nn] = v.x; Bs[k][nn + 1] = v.y;
        }
        __syncthreads();
#pragma unroll
        for (int k = 0; k < 8; k++) {
            float ra[8], rb[8];
#pragma unroll
            for (int i = 0; i < 8; i++) ra[i] = As[k][ty + 32 * i];
#pragma unroll
            for (int j = 0; j < 8; j++) rb[j] = Bs[k][tx + 8 * j];
#pragma unroll
            for (int i = 0; i < 8; i++)
#pragma unroll
                for (int j = 0; j < 8; j++) acc[i][j] += ra[i] * rb[j];
        }
        __syncthreads();
    }

    // + b_out[o]
#pragma unroll
    for (int i = 0; i < 8; i++) {
        float bo = b_out[ty + 32 * i];
#pragma unroll
        for (int j = 0; j < 8; j++) acc[i][j] += bo;
    }

    // per-column partial stats (8 columns per thread, 8 rows each)
#pragma unroll
    for (int j = 0; j < 8; j++) {
        int c = tx + 8 * j;
        float ps = 0.f, pq = 0.f;
#pragma unroll
        for (int i = 0; i < 8; i++) { float v = acc[i][j]; ps += v; pq += v * v; }
        rsum[ty][c] = ps;
        rsq [ty][c] = pq;
    }
    __syncthreads();
    if (tid < 64) {
        float s = 0.f, q = 0.f;
#pragma unroll 8
        for (int t = 0; t < 32; t++) { s += rsum[t][tid]; q += rsq[t][tid]; }
        float mean = s * (1.0f / 256.0f);
        float var  = q * (1.0f / 256.0f) - mean * mean;
        mean_s[tid] = mean;
        rstd_s[tid] = rsqrtf(var + EPS);
    }
    __syncthreads();

#pragma unroll
    for (int i = 0; i < 8; i++) {
        int o = ty + 32 * i;
        float gv = gamma[o], bv = beta[o];
        float* orow = out + ((size_t)b * DIMC + o) * NSP + n0;
#pragma unroll
        for (int j = 0; j < 8; j++) {
            int c = tx + 8 * j;
            orow[c] = (acc[i][j] - mean_s[c]) * rstd_s[c] * gv + bv;
        }
    }
}

// ---------------------------------------------------------------------------
extern "C" void kernel_launch(void* const* d_in, const int* in_sizes, int n_in,
                              void* d_out, int out_size) {
    const float* x     = (const float*)d_in[0];
    const float* w_qkv = (const float*)d_in[1];
    const float* w_out = (const float*)d_in[2];
    const float* b_out = (const float*)d_in[3];
    const float* g     = (const float*)d_in[4];
    const float* bb    = (const float*)d_in[5];
    float* out = (float*)d_out;

    qkv_gemm<<<dim3(NSP / 128, THREE / 128, NB), 256>>>(w_qkv, x);
    q_softmax<<<(NB * HEADS * NSP) / 256, 256>>>();
    k_softmax<<<NB * HID, 256>>>();
    ctx_kernel<<<NB * HEADS, 256>>>();
    wf_kernel<<<NB, 256>>>(w_out);
    out_ln<<<dim3(NSP / 64, NB), 256>>>(b_out, g, bb, out);
}

// round 9
// speedup vs baseline: 2.3358x; 2.3358x over previous
#include <cuda_runtime.h>
#include <cuda_bf16.h>
#include <math.h>
#include <stdint.h>

// Problem constants
#define NB    32
#define DIMC  256
#define HEADS 4
#define DH    32
#define HID   128      // HEADS*DH
#define THREE 384      // 3*HID
#define NSP   4096     // 64*64 spatial
#define SCALE 0.17677669529663687f  // 32^-0.5
#define EPS   1e-5f

// Scratch (device globals)
__device__ float g_qkv[(size_t)NB * THREE * NSP];   // ~201 MB
__device__ float g_ctx[NB * HEADS * DH * DH];       // 512 KB
__device__ float g_wf [(size_t)NB * DIMC * HID];    // 4 MB

// ---------------------------------------------------------------------------
// Helpers: tf32 convert (round-to-nearest) + m16n8k8 tf32 MMA
// ---------------------------------------------------------------------------
__device__ __forceinline__ uint32_t f2tf32(float f) {
    uint32_t u;
    asm("cvt.rna.tf32.f32 %0, %1;" : "=r"(u) : "f"(f));
    return u;
}
__device__ __forceinline__ void mma_tf32(float* d, const uint32_t* a, const uint32_t* b) {
    asm volatile(
        "mma.sync.aligned.m16n8k8.row.col.f32.tf32.tf32.f32 "
        "{%0,%1,%2,%3}, {%4,%5,%6,%7}, {%8,%9}, {%0,%1,%2,%3};\n"
        : "+f"(d[0]), "+f"(d[1]), "+f"(d[2]), "+f"(d[3])
        : "r"(a[0]), "r"(a[1]), "r"(a[2]), "r"(a[3]), "r"(b[0]), "r"(b[1]));
}

// Fragment layout (m16n8k8 tf32), lane = 4*g + tg, g in [0,8), tg in [0,4):
//  A: a0=A[g][tg]  a1=A[g+8][tg]  a2=A[g][tg+4]  a3=A[g+8][tg+4]
//  B: b0=B[tg][g]  b1=B[tg+4][g]          (B is k x n, "col" major)
//  C: c0=C[g][2tg] c1=C[g][2tg+1] c2=C[g+8][2tg] c3=C[g+8][2tg+1]

#define QA_LD 36    // A smem pitch: bank = 4g+tg  (conflict-free)
#define QB_LD 136   // B smem pitch: bank = 8tg+g  (conflict-free)

// ---------------------------------------------------------------------------
// Kernel 1 (tf32 mma): qkv[b,o,n] = sum_c W[o,c] * X[b,c,n]
// CTA 128x128, BK=32, 8 warps (2M x 4N), warp tile 64x32.
// ---------------------------------------------------------------------------
__global__ __launch_bounds__(256) void qkv_mma(const float* __restrict__ W,
                                               const float* __restrict__ X) {
    __shared__ uint32_t As[128 * QA_LD];   // 18.0 KB (tf32 bits)
    __shared__ uint32_t Bs[32 * QB_LD];    // 17.0 KB

    const int b  = blockIdx.z;
    const int m0 = blockIdx.y * 128;       // within 384
    const int n0 = blockIdx.x * 128;
    const float* Xb = X + (size_t)b * DIMC * NSP;
    float* Cb = g_qkv + (size_t)b * THREE * NSP;

    const int tid = threadIdx.x, wid = tid >> 5, lane = tid & 31;
    const int wm = wid >> 2, wn = wid & 3;     // 2 x 4 warps
    const int g = lane >> 2, tg = lane & 3;

    float acc[4][4][4];
#pragma unroll
    for (int i = 0; i < 4; ++i)
#pragma unroll
        for (int j = 0; j < 4; ++j)
#pragma unroll
            for (int e = 0; e < 4; ++e) acc[i][j][e] = 0.f;

#pragma unroll 1
    for (int k0 = 0; k0 < DIMC; k0 += 32) {
        // A: W[m0+row][k0 + q*4 ..], 128 rows x 32 k
#pragma unroll
        for (int j = 0; j < 4; ++j) {
            int fi = j * 256 + tid;                 // 1024 float4s
            int row = fi >> 3, q = fi & 7;
            float4 v = *(const float4*)(W + (size_t)(m0 + row) * DIMC + k0 + q * 4);
            uint32_t* d = &As[row * QA_LD + q * 4];
            d[0] = f2tf32(v.x); d[1] = f2tf32(v.y);
            d[2] = f2tf32(v.z); d[3] = f2tf32(v.w);
        }
        // B: X[k0+k][n0+nn], 32 k x 128 n
#pragma unroll
        for (int j = 0; j < 4; ++j) {
            int fi = j * 256 + tid;
            int k = fi >> 5, nn = (fi & 31) * 4;
            float4 v = *(const float4*)(Xb + (size_t)(k0 + k) * NSP + n0 + nn);
            uint32_t* d = &Bs[k * QB_LD + nn];
            d[0] = f2tf32(v.x); d[1] = f2tf32(v.y);
            d[2] = f2tf32(v.z); d[3] = f2tf32(v.w);
        }
        __syncthreads();

#pragma unroll
        for (int ks = 0; ks < 32; ks += 8) {
            uint32_t af[4][4], bf[4][2];
#pragma unroll
            for (int i = 0; i < 4; ++i) {
                int r = wm * 64 + i * 16;
                af[i][0] = As[(r + g)     * QA_LD + ks + tg];
                af[i][1] = As[(r + g + 8) * QA_LD + ks + tg];
                af[i][2] = As[(r + g)     * QA_LD + ks + tg + 4];
                af[i][3] = As[(r + g + 8) * QA_LD + ks + tg + 4];
            }
#pragma unroll
            for (int jn = 0; jn < 4; ++jn) {
                int c = wn * 32 + jn * 8 + g;
                bf[jn][0] = Bs[(ks + tg)     * QB_LD + c];
                bf[jn][1] = Bs[(ks + tg + 4) * QB_LD + c];
            }
#pragma unroll
            for (int i = 0; i < 4; ++i)
#pragma unroll
                for (int jn = 0; jn < 4; ++jn)
                    mma_tf32(acc[i][jn], af[i], bf[jn]);
        }
        __syncthreads();
    }

    // Epilogue: direct float2 stores (32B/sector per quad)
#pragma unroll
    for (int i = 0; i < 4; ++i) {
        int r0 = m0 + wm * 64 + i * 16 + g;
#pragma unroll
        for (int jn = 0; jn < 4; ++jn) {
            int c = n0 + wn * 32 + jn * 8 + tg * 2;
            *(float2*)&Cb[(size_t)r0 * NSP + c] =
                make_float2(acc[i][jn][0], acc[i][jn][1]);
            *(float2*)&Cb[(size_t)(r0 + 8) * NSP + c] =
                make_float2(acc[i][jn][2], acc[i][jn][3]);
        }
    }
}

// ---------------------------------------------------------------------------
// Kernel 2: q softmax over d (unchanged)
// ---------------------------------------------------------------------------
__global__ __launch_bounds__(256) void q_softmax() {
    int idx = blockIdx.x * blockDim.x + threadIdx.x;
    int n  = idx & (NSP - 1);
    int bh = idx >> 12;
    int b = bh >> 2, h = bh & 3;
    float* base = g_qkv + (size_t)b * THREE * NSP + (size_t)(h * DH) * NSP + n;

    float v[DH];
    float mx = -1e30f;
#pragma unroll
    for (int d = 0; d < DH; d++) { v[d] = base[(size_t)d * NSP]; mx = fmaxf(mx, v[d]); }
    float s = 0.f;
#pragma unroll
    for (int d = 0; d < DH; d++) { v[d] = __expf(v[d] - mx); s += v[d]; }
    float inv = SCALE / s;
#pragma unroll
    for (int d = 0; d < DH; d++) base[(size_t)d * NSP] = v[d] * inv;
}

// ---------------------------------------------------------------------------
// Kernel 3: k softmax over n (unchanged)
// ---------------------------------------------------------------------------
__global__ __launch_bounds__(256) void k_softmax() {
    __shared__ float buf[NSP];
    __shared__ float red[256];
    int row = blockIdx.x;
    int b = row >> 7, r = row & 127;
    float* base = g_qkv + (size_t)b * THREE * NSP + (size_t)(HID + r) * NSP;
    int tid = threadIdx.x;

    float mx = -1e30f;
    for (int i = tid; i < NSP; i += 256) { float x = base[i]; buf[i] = x; mx = fmaxf(mx, x); }
    red[tid] = mx; __syncthreads();
    for (int s = 128; s > 0; s >>= 1) {
        if (tid < s) red[tid] = fmaxf(red[tid], red[tid + s]);
        __syncthreads();
    }
    mx = red[0]; __syncthreads();

    float sum = 0.f;
    for (int i = tid; i < NSP; i += 256) { float e = __expf(buf[i] - mx); buf[i] = e; sum += e; }
    red[tid] = sum; __syncthreads();
    for (int s = 128; s > 0; s >>= 1) {
        if (tid < s) red[tid] += red[tid + s];
        __syncthreads();
    }
    float inv = 1.0f / red[0];
    __syncthreads();
    for (int i = tid; i < NSP; i += 256) base[i] = buf[i] * inv;
}

// ---------------------------------------------------------------------------
// Kernel 4: context (unchanged)
// ---------------------------------------------------------------------------
__global__ __launch_bounds__(256) void ctx_kernel() {
    __shared__ float Ks[4][32][33];
    __shared__ float Vs[4][32][33];
    __shared__ float racc[3][64][16];
    int bh = blockIdx.x;
    int b = bh >> 2, h = bh & 3;
    const float* kbase = g_qkv + (size_t)b * THREE * NSP + (size_t)(HID + h * DH) * NSP;
    const float* vbase = g_qkv + (size_t)b * THREE * NSP + (size_t)(2 * HID + h * DH) * NSP;

    int tid = threadIdx.x;
    int grp = tid >> 6;
    int t   = tid & 63;
    int td = t >> 3, te = t & 7;

    float acc[4][4];
#pragma unroll
    for (int i = 0; i < 4; i++)
#pragma unroll
        for (int j = 0; j < 4; j++) acc[i][j] = 0.f;

    const int base_n = grp * 1024;
    for (int cc = 0; cc < 1024; cc += 32) {
        int c0 = base_n + cc;
#pragma unroll
        for (int m = 0; m < 4; m++) {
            int fi = m * 64 + t;
            int dd = fi >> 3;
            int nn = (fi & 7) * 4;
            float4 kv = *(const float4*)&kbase[(size_t)dd * NSP + c0 + nn];
            float4 vv = *(const float4*)&vbase[(size_t)dd * NSP + c0 + nn];
            Ks[grp][dd][nn+0] = kv.x; Ks[grp][dd][nn+1] = kv.y;
            Ks[grp][dd][nn+2] = kv.z; Ks[grp][dd][nn+3] = kv.w;
            Vs[grp][dd][nn+0] = vv.x; Vs[grp][dd][nn+1] = vv.y;
            Vs[grp][dd][nn+2] = vv.z; Vs[grp][dd][nn+3] = vv.w;
        }
        __syncthreads();
#pragma unroll 4
        for (int n = 0; n < 32; n++) {
            float ka[4], vb[4];
#pragma unroll
            for (int i = 0; i < 4; i++) ka[i] = Ks[grp][td * 4 + i][n];
#pragma unroll
            for (int j = 0; j < 4; j++) vb[j] = Vs[grp][te * 4 + j][n];
#pragma unroll
            for (int i = 0; i < 4; i++)
#pragma unroll
                for (int j = 0; j < 4; j++) acc[i][j] += ka[i] * vb[j];
        }
        __syncthreads();
    }

    if (grp > 0) {
#pragma unroll
        for (int i = 0; i < 4; i++)
#pragma unroll
            for (int j = 0; j < 4; j++) racc[grp - 1][t][i * 4 + j] = acc[i][j];
    }
    __syncthreads();
    if (grp == 0) {
#pragma unroll
        for (int gg = 0; gg < 3; gg++)
#pragma unroll
            for (int i = 0; i < 4; i++)
#pragma unroll
                for (int j = 0; j < 4; j++) acc[i][j] += racc[gg][t][i * 4 + j];
#pragma unroll
        for (int i = 0; i < 4; i++)
#pragma unroll
            for (int j = 0; j < 4; j++)
                g_ctx[((size_t)bh * DH + td * 4 + i) * DH + te * 4 + j] = acc[i][j];
    }
}

// ---------------------------------------------------------------------------
// Kernel 5: fused weight Wf (unchanged)
// ---------------------------------------------------------------------------
__global__ __launch_bounds__(256) void wf_kernel(const float* __restrict__ w_out) {
    __shared__ float cs[HEADS][DH][DH];
    int b = blockIdx.x;
    int tid = threadIdx.x;
    for (int i = tid; i < HEADS * DH * DH; i += 256)
        ((float*)cs)[i] = g_ctx[(size_t)b * HEADS * DH * DH + i];
    __syncthreads();

    int o = tid;
    float* dst = g_wf + ((size_t)b * DIMC + o) * HID;
#pragma unroll
    for (int h = 0; h < HEADS; h++) {
        float w[DH];
#pragma unroll
        for (int e = 0; e < DH; e++) w[e] = w_out[o * HID + h * DH + e];
#pragma unroll 4
        for (int d = 0; d < DH; d++) {
            float s = 0.f;
#pragma unroll
            for (int e = 0; e < DH; e++) s += w[e] * cs[h][d][e];
            dst[h * DH + d] = s;
        }
    }
}

// ---------------------------------------------------------------------------
// Kernel 6 (tf32 mma + fused LN): out[b,o,n] = Wf[b]·q[b] + b_out, LN over o.
// CTA 256(M) x 64(N), K=128, BK=32. 8 warps (4M x 2N), warp tile 64x32.
// ---------------------------------------------------------------------------
#define OA_LD 36
#define OB_LD 72    // bank = 8tg+g, conflict-free
#define OUT_DYN ((256 * OA_LD + 32 * OB_LD) * 4)   // 46080 bytes

__global__ __launch_bounds__(256) void out_ln_mma(const float* __restrict__ b_out,
                                                  const float* __restrict__ gamma,
                                                  const float* __restrict__ beta,
                                                  float* __restrict__ out) {
    extern __shared__ uint32_t dynbuf[];
    uint32_t* As = dynbuf;                 // 256 x OA_LD
    uint32_t* Bs = dynbuf + 256 * OA_LD;   // 32 x OB_LD
    __shared__ float s_sum[4][64];
    __shared__ float s_sq [4][64];
    __shared__ float s_mean[64], s_rstd[64];

    const int b  = blockIdx.y;
    const int n0 = blockIdx.x * 64;
    const float* A = g_wf + (size_t)b * DIMC * HID;   // 256 x 128
    const float* Q = g_qkv + (size_t)b * THREE * NSP; // rows [0,128): softmaxed q*SCALE

    const int tid = threadIdx.x, wid = tid >> 5, lane = tid & 31;
    const int wm = wid >> 1, wn = wid & 1;    // 4 x 2 warps
    const int g = lane >> 2, tg = lane & 3;

    float acc[4][4][4];
#pragma unroll
    for (int i = 0; i < 4; ++i)
#pragma unroll
        for (int j = 0; j < 4; ++j)
#pragma unroll
            for (int e = 0; e < 4; ++e) acc[i][j][e] = 0.f;

#pragma unroll 1
    for (int k0 = 0; k0 < HID; k0 += 32) {
        // A: Wf[row][k0..k0+31], 256 rows
#pragma unroll
        for (int j = 0; j < 8; ++j) {
            int fi = j * 256 + tid;                 // 2048 float4s
            int row = fi >> 3, q = fi & 7;
            float4 v = *(const float4*)(A + (size_t)row * HID + k0 + q * 4);
            uint32_t* d = &As[row * OA_LD + q * 4];
            d[0] = f2tf32(v.x); d[1] = f2tf32(v.y);
            d[2] = f2tf32(v.z); d[3] = f2tf32(v.w);
        }
        // B: Q[k0+k][n0+nn], 32 k x 64 n
#pragma unroll
        for (int j = 0; j < 2; ++j) {
            int fi = j * 256 + tid;                 // 512 float4s
            int k = fi >> 4, nn = (fi & 15) * 4;
            float4 v = *(const float4*)(Q + (size_t)(k0 + k) * NSP + n0 + nn);
            uint32_t* d = &Bs[k * OB_LD + nn];
            d[0] = f2tf32(v.x); d[1] = f2tf32(v.y);
            d[2] = f2tf32(v.z); d[3] = f2tf32(v.w);
        }
        __syncthreads();

#pragma unroll
        for (int ks = 0; ks < 32; ks += 8) {
            uint32_t af[4][4], bf[4][2];
#pragma unroll
            for (int i = 0; i < 4; ++i) {
                int r = wm * 64 + i * 16;
                af[i][0] = As[(r + g)     * OA_LD + ks + tg];
                af[i][1] = As[(r + g + 8) * OA_LD + ks + tg];
                af[i][2] = As[(r + g)     * OA_LD + ks + tg + 4];
                af[i][3] = As[(r + g + 8) * OA_LD + ks + tg + 4];
            }
#pragma unroll
            for (int jn = 0; jn < 4; ++jn) {
                int c = wn * 32 + jn * 8 + g;
                bf[jn][0] = Bs[(ks + tg)     * OB_LD + c];
                bf[jn][1] = Bs[(ks + tg + 4) * OB_LD + c];
            }
#pragma unroll
            for (int i = 0; i < 4; ++i)
#pragma unroll
                for (int jn = 0; jn < 4; ++jn)
                    mma_tf32(acc[i][jn], af[i], bf[jn]);
        }
        __syncthreads();
    }

    // Add bias into accumulators
#pragma unroll
    for (int i = 0; i < 4; ++i) {
        float bo0 = b_out[wm * 64 + i * 16 + g];
        float bo1 = b_out[wm * 64 + i * 16 + g + 8];
#pragma unroll
        for (int jn = 0; jn < 4; ++jn) {
            acc[i][jn][0] += bo0; acc[i][jn][1] += bo0;
            acc[i][jn][2] += bo1; acc[i][jn][3] += bo1;
        }
    }

    // Per-column (n) stats over the 256 channels.
    // This thread owns cols {jn*8 + tg*2 + e} (8 cols) x rows {i,half} (8 rows).
    float ps[8], pq[8];
#pragma unroll
    for (int c = 0; c < 8; ++c) { ps[c] = 0.f; pq[c] = 0.f; }
#pragma unroll
    for (int i = 0; i < 4; ++i)
#pragma unroll
        for (int jn = 0; jn < 4; ++jn)
#pragma unroll
            for (int e = 0; e < 2; ++e) {
                float v0 = acc[i][jn][e];       // row g
                float v1 = acc[i][jn][2 + e];   // row g+8
                ps[jn * 2 + e] += v0 + v1;
                pq[jn * 2 + e] += v0 * v0 + v1 * v1;
            }
    // Reduce over g (lanes differing in bits 2..4)
#pragma unroll
    for (int c = 0; c < 8; ++c) {
#pragma unroll
        for (int off = 4; off < 32; off <<= 1) {
            ps[c] += __shfl_xor_sync(0xffffffffu, ps[c], off);
            pq[c] += __shfl_xor_sync(0xffffffffu, pq[c], off);
        }
    }
    if (g == 0) {
#pragma unroll
        for (int jn = 0; jn < 4; ++jn)
#pragma unroll
            for (int e = 0; e < 2; ++e) {
                int col = wn * 32 + jn * 8 + tg * 2 + e;
                s_sum[wm][col] = ps[jn * 2 + e];
                s_sq [wm][col] = pq[jn * 2 + e];
            }
    }
    __syncthreads();
    if (tid < 64) {
        float s = s_sum[0][tid] + s_sum[1][tid] + s_sum[2][tid] + s_sum[3][tid];
        float q = s_sq [0][tid] + s_sq [1][tid] + s_sq [2][tid] + s_sq [3][tid];
        float mean = s * (1.0f / 256.0f);
        float var  = q * (1.0f / 256.0f) - mean * mean;
        s_mean[tid] = mean;
        s_rstd[tid] = rsqrtf(var + EPS);
    }
    __syncthreads();

    // Normalize + store
#pragma unroll
    for (int i = 0; i < 4; ++i) {
        int o0 = wm * 64 + i * 16 + g;
        float g0 = gamma[o0], b0v = beta[o0];
        float g1 = gamma[o0 + 8], b1v = beta[o0 + 8];
#pragma unroll
        for (int jn = 0; jn < 4; ++jn) {
            int cl = wn * 32 + jn * 8 + tg * 2;
            float m0 = s_mean[cl],     r0 = s_rstd[cl];
            float m1 = s_mean[cl + 1], r1 = s_rstd[cl + 1];
            *(float2*)&out[((size_t)b * DIMC + o0) * NSP + n0 + cl] =
                make_float2((acc[i][jn][0] - m0) * r0 * g0 + b0v,
                            (acc[i][jn][1] - m1) * r1 * g0 + b0v);
            *(float2*)&out[((size_t)b * DIMC + o0 + 8) * NSP + n0 + cl] =
                make_float2((acc[i][jn][2] - m0) * r0 * g1 + b1v,
                            (acc[i][jn][3] - m1) * r1 * g1 + b1v);
        }
    }
}

// ---------------------------------------------------------------------------
extern "C" void kernel_launch(void* const* d_in, const int* in_sizes, int n_in,
                              void* d_out, int out_size) {
    const float* x     = (const float*)d_in[0];
    const float* w_qkv = (const float*)d_in[1];
    const float* w_out = (const float*)d_in[2];
    const float* b_out = (const float*)d_in[3];
    const float* g     = (const float*)d_in[4];
    const float* bb    = (const float*)d_in[5];
    float* out = (float*)d_out;

    qkv_mma<<<dim3(NSP / 128, THREE / 128, NB), 256>>>(w_qkv, x);
    q_softmax<<<(NB * HEADS * NSP) / 256, 256>>>();
    k_softmax<<<NB * HID, 256>>>();
    ctx_kernel<<<NB * HEADS, 256>>>();
    wf_kernel<<<NB, 256>>>(w_out);
    out_ln_mma<<<dim3(NSP / 64, NB), 256, OUT_DYN>>>(b_out, g, bb, out);
}

// round 10
// speedup vs baseline: 2.5289x; 1.0826x over previous
#include <cuda_runtime.h>
#include <cuda_bf16.h>
#include <math.h>
#include <stdint.h>

// Problem constants
#define NB    32
#define DIMC  256
#define HEADS 4
#define DH    32
#define HID   128      // HEADS*DH
#define THREE 384      // 3*HID
#define NSP   4096     // 64*64 spatial
#define SCALE 0.17677669529663687f  // 32^-0.5
#define EPS   1e-5f
#define NSLICE 8       // ctx n-split

// Scratch (device globals)
__device__ float g_qkv [(size_t)NB * THREE * NSP];              // ~201 MB
__device__ float g_ctxp[(size_t)NSLICE * NB * HEADS * DH * DH]; // 4 MB
__device__ float g_wf  [(size_t)NB * DIMC * HID];               // 4 MB

// ---------------------------------------------------------------------------
// Helpers: tf32 convert (round-to-nearest) + m16n8k8 tf32 MMA
// ---------------------------------------------------------------------------
__device__ __forceinline__ uint32_t f2tf32(float f) {
    uint32_t u;
    asm("cvt.rna.tf32.f32 %0, %1;" : "=r"(u) : "f"(f));
    return u;
}
__device__ __forceinline__ void mma_tf32(float* d, const uint32_t* a, const uint32_t* b) {
    asm volatile(
        "mma.sync.aligned.m16n8k8.row.col.f32.tf32.tf32.f32 "
        "{%0,%1,%2,%3}, {%4,%5,%6,%7}, {%8,%9}, {%0,%1,%2,%3};\n"
        : "+f"(d[0]), "+f"(d[1]), "+f"(d[2]), "+f"(d[3])
        : "r"(a[0]), "r"(a[1]), "r"(a[2]), "r"(a[3]), "r"(b[0]), "r"(b[1]));
}

// Fragment layout (m16n8k8 tf32), lane = 4*g + tg, g in [0,8), tg in [0,4):
//  A: a0=A[g][tg]  a1=A[g+8][tg]  a2=A[g][tg+4]  a3=A[g+8][tg+4]
//  B: b0=B[tg][g]  b1=B[tg+4][g]
//  C: c0=C[g][2tg] c1=C[g][2tg+1] c2=C[g+8][2tg] c3=C[g+8][2tg+1]

#define QA_LD 36    // A smem pitch: bank = 4g+tg  (conflict-free)
#define QB_LD 136   // B smem pitch: bank = 8tg+g  (conflict-free)

// ---------------------------------------------------------------------------
// Kernel 1 (tf32 mma): qkv[b,o,n] = sum_c W[o,c] * X[b,c,n]
// CTA 128x128, BK=32, 8 warps (2M x 4N), warp tile 64x32.
// For blockIdx.y==0 (q rows), softmax over d=32 per head is fused into the
// epilogue via in-register + shfl reduction, then scaled by SCALE.
// ---------------------------------------------------------------------------
__global__ __launch_bounds__(256) void qkv_mma(const float* __restrict__ W,
                                               const float* __restrict__ X) {
    __shared__ uint32_t As[128 * QA_LD];   // 18.0 KB (tf32 bits)
    __shared__ uint32_t Bs[32 * QB_LD];    // 17.0 KB

    const int b  = blockIdx.z;
    const int m0 = blockIdx.y * 128;       // within 384
    const int n0 = blockIdx.x * 128;
    const float* Xb = X + (size_t)b * DIMC * NSP;
    float* Cb = g_qkv + (size_t)b * THREE * NSP;

    const int tid = threadIdx.x, wid = tid >> 5, lane = tid & 31;
    const int wm = wid >> 2, wn = wid & 3;     // 2 x 4 warps
    const int g = lane >> 2, tg = lane & 3;

    float acc[4][4][4];
#pragma unroll
    for (int i = 0; i < 4; ++i)
#pragma unroll
        for (int j = 0; j < 4; ++j)
#pragma unroll
            for (int e = 0; e < 4; ++e) acc[i][j][e] = 0.f;

#pragma unroll 1
    for (int k0 = 0; k0 < DIMC; k0 += 32) {
        // A: W[m0+row][k0 + q*4 ..], 128 rows x 32 k
#pragma unroll
        for (int j = 0; j < 4; ++j) {
            int fi = j * 256 + tid;                 // 1024 float4s
            int row = fi >> 3, q = fi & 7;
            float4 v = *(const float4*)(W + (size_t)(m0 + row) * DIMC + k0 + q * 4);
            uint32_t* d = &As[row * QA_LD + q * 4];
            d[0] = f2tf32(v.x); d[1] = f2tf32(v.y);
            d[2] = f2tf32(v.z); d[3] = f2tf32(v.w);
        }
        // B: X[k0+k][n0+nn], 32 k x 128 n
#pragma unroll
        for (int j = 0; j < 4; ++j) {
            int fi = j * 256 + tid;
            int k = fi >> 5, nn = (fi & 31) * 4;
            float4 v = *(const float4*)(Xb + (size_t)(k0 + k) * NSP + n0 + nn);
            uint32_t* d = &Bs[k * QB_LD + nn];
            d[0] = f2tf32(v.x); d[1] = f2tf32(v.y);
            d[2] = f2tf32(v.z); d[3] = f2tf32(v.w);
        }
        __syncthreads();

#pragma unroll
        for (int ks = 0; ks < 32; ks += 8) {
            uint32_t af[4][4], bf[4][2];
#pragma unroll
            for (int i = 0; i < 4; ++i) {
                int r = wm * 64 + i * 16;
                af[i][0] = As[(r + g)     * QA_LD + ks + tg];
                af[i][1] = As[(r + g + 8) * QA_LD + ks + tg];
                af[i][2] = As[(r + g)     * QA_LD + ks + tg + 4];
                af[i][3] = As[(r + g + 8) * QA_LD + ks + tg + 4];
            }
#pragma unroll
            for (int jn = 0; jn < 4; ++jn) {
                int c = wn * 32 + jn * 8 + g;
                bf[jn][0] = Bs[(ks + tg)     * QB_LD + c];
                bf[jn][1] = Bs[(ks + tg + 4) * QB_LD + c];
            }
#pragma unroll
            for (int i = 0; i < 4; ++i)
#pragma unroll
                for (int jn = 0; jn < 4; ++jn)
                    mma_tf32(acc[i][jn], af[i], bf[jn]);
        }
        __syncthreads();
    }

    // Fused q softmax (only the m-block holding rows [0,128) = q).
    // For a fixed column, a head's 32 d-values live in 4 thread-local accs
    // (i in {ib, ib+1}, halves) x 8 lanes differing in g (lane bits 2..4).
    if (m0 == 0) {
#pragma unroll
        for (int jn = 0; jn < 4; ++jn)
#pragma unroll
            for (int e = 0; e < 2; ++e)
#pragma unroll
                for (int hd = 0; hd < 2; ++hd) {
                    const int ib = hd * 2;
                    float v0 = acc[ib][jn][e],     v1 = acc[ib][jn][2 + e];
                    float v2 = acc[ib + 1][jn][e], v3 = acc[ib + 1][jn][2 + e];
                    float m = fmaxf(fmaxf(v0, v1), fmaxf(v2, v3));
#pragma unroll
                    for (int off = 4; off < 32; off <<= 1)
                        m = fmaxf(m, __shfl_xor_sync(0xffffffffu, m, off));
                    v0 = __expf(v0 - m); v1 = __expf(v1 - m);
                    v2 = __expf(v2 - m); v3 = __expf(v3 - m);
                    float s = (v0 + v1) + (v2 + v3);
#pragma unroll
                    for (int off = 4; off < 32; off <<= 1)
                        s += __shfl_xor_sync(0xffffffffu, s, off);
                    float inv = SCALE / s;
                    acc[ib][jn][e]         = v0 * inv;
                    acc[ib][jn][2 + e]     = v1 * inv;
                    acc[ib + 1][jn][e]     = v2 * inv;
                    acc[ib + 1][jn][2 + e] = v3 * inv;
                }
    }

    // Epilogue: direct float2 stores
#pragma unroll
    for (int i = 0; i < 4; ++i) {
        int r0 = m0 + wm * 64 + i * 16 + g;
#pragma unroll
        for (int jn = 0; jn < 4; ++jn) {
            int c = n0 + wn * 32 + jn * 8 + tg * 2;
            *(float2*)&Cb[(size_t)r0 * NSP + c] =
                make_float2(acc[i][jn][0], acc[i][jn][1]);
            *(float2*)&Cb[(size_t)(r0 + 8) * NSP + c] =
                make_float2(acc[i][jn][2], acc[i][jn][3]);
        }
    }
}

// ---------------------------------------------------------------------------
// Kernel 3: k softmax over n (unchanged)
// ---------------------------------------------------------------------------
__global__ __launch_bounds__(256) void k_softmax() {
    __shared__ float buf[NSP];
    __shared__ float red[256];
    int row = blockIdx.x;
    int b = row >> 7, r = row & 127;
    float* base = g_qkv + (size_t)b * THREE * NSP + (size_t)(HID + r) * NSP;
    int tid = threadIdx.x;

    float mx = -1e30f;
    for (int i = tid; i < NSP; i += 256) { float x = base[i]; buf[i] = x; mx = fmaxf(mx, x); }
    red[tid] = mx; __syncthreads();
    for (int s = 128; s > 0; s >>= 1) {
        if (tid < s) red[tid] = fmaxf(red[tid], red[tid + s]);
        __syncthreads();
    }
    mx = red[0]; __syncthreads();

    float sum = 0.f;
    for (int i = tid; i < NSP; i += 256) { float e = __expf(buf[i] - mx); buf[i] = e; sum += e; }
    red[tid] = sum; __syncthreads();
    for (int s = 128; s > 0; s >>= 1) {
        if (tid < s) red[tid] += red[tid + s];
        __syncthreads();
    }
    float inv = 1.0f / red[0];
    __syncthreads();
    for (int i = tid; i < NSP; i += 256) base[i] = buf[i] * inv;
}

// ---------------------------------------------------------------------------
// Kernel 4: context partials. grid = (NB*HEADS, NSLICE); each block covers
// 512 n-positions (4 groups x 128), writes a 32x32 partial to g_ctxp.
// ---------------------------------------------------------------------------
__global__ __launch_bounds__(256) void ctx_slice() {
    __shared__ float Ks[4][32][33];
    __shared__ float Vs[4][32][33];
    __shared__ float racc[3][64][16];
    int bh = blockIdx.x;
    int sl = blockIdx.y;
    int b = bh >> 2, h = bh & 3;
    const float* kbase = g_qkv + (size_t)b * THREE * NSP + (size_t)(HID + h * DH) * NSP;
    const float* vbase = g_qkv + (size_t)b * THREE * NSP + (size_t)(2 * HID + h * DH) * NSP;

    int tid = threadIdx.x;
    int grp = tid >> 6;
    int t   = tid & 63;
    int td = t >> 3, te = t & 7;

    float acc[4][4];
#pragma unroll
    for (int i = 0; i < 4; i++)
#pragma unroll
        for (int j = 0; j < 4; j++) acc[i][j] = 0.f;

    const int base_n = sl * (NSP / NSLICE) + grp * 128;
#pragma unroll 1
    for (int cc = 0; cc < 128; cc += 32) {
        int c0 = base_n + cc;
#pragma unroll
        for (int m = 0; m < 4; m++) {
            int fi = m * 64 + t;
            int dd = fi >> 3;
            int nn = (fi & 7) * 4;
            float4 kv = *(const float4*)&kbase[(size_t)dd * NSP + c0 + nn];
            float4 vv = *(const float4*)&vbase[(size_t)dd * NSP + c0 + nn];
            Ks[grp][dd][nn+0] = kv.x; Ks[grp][dd][nn+1] = kv.y;
            Ks[grp][dd][nn+2] = kv.z; Ks[grp][dd][nn+3] = kv.w;
            Vs[grp][dd][nn+0] = vv.x; Vs[grp][dd][nn+1] = vv.y;
            Vs[grp][dd][nn+2] = vv.z; Vs[grp][dd][nn+3] = vv.w;
        }
        __syncthreads();
#pragma unroll 4
        for (int n = 0; n < 32; n++) {
            float ka[4], vb[4];
#pragma unroll
            for (int i = 0; i < 4; i++) ka[i] = Ks[grp][td * 4 + i][n];
#pragma unroll
            for (int j = 0; j < 4; j++) vb[j] = Vs[grp][te * 4 + j][n];
#pragma unroll
            for (int i = 0; i < 4; i++)
#pragma unroll
                for (int j = 0; j < 4; j++) acc[i][j] += ka[i] * vb[j];
        }
        __syncthreads();
    }

    if (grp > 0) {
#pragma unroll
        for (int i = 0; i < 4; i++)
#pragma unroll
            for (int j = 0; j < 4; j++) racc[grp - 1][t][i * 4 + j] = acc[i][j];
    }
    __syncthreads();
    if (grp == 0) {
#pragma unroll
        for (int gg = 0; gg < 3; gg++)
#pragma unroll
            for (int i = 0; i < 4; i++)
#pragma unroll
                for (int j = 0; j < 4; j++) acc[i][j] += racc[gg][t][i * 4 + j];
        float* dst = g_ctxp + ((size_t)sl * NB * HEADS + bh) * (DH * DH);
#pragma unroll
        for (int i = 0; i < 4; i++)
#pragma unroll
            for (int j = 0; j < 4; j++)
                dst[(td * 4 + i) * DH + te * 4 + j] = acc[i][j];
    }
}

// ---------------------------------------------------------------------------
// Kernel 5: fused weight Wf; sums the NSLICE ctx partials while loading.
// ---------------------------------------------------------------------------
__global__ __launch_bounds__(256) void wf_kernel(const float* __restrict__ w_out) {
    __shared__ float cs[HEADS][DH][DH];
    int b = blockIdx.x;
    int tid = threadIdx.x;
    const size_t slice_stride = (size_t)NB * HEADS * DH * DH;
    const size_t base = (size_t)b * HEADS * DH * DH;
    for (int i = tid; i < HEADS * DH * DH; i += 256) {
        float s = 0.f;
#pragma unroll
        for (int sl = 0; sl < NSLICE; ++sl)
            s += g_ctxp[sl * slice_stride + base + i];
        ((float*)cs)[i] = s;
    }
    __syncthreads();

    int o = tid;
    float* dst = g_wf + ((size_t)b * DIMC + o) * HID;
#pragma unroll
    for (int h = 0; h < HEADS; h++) {
        float w[DH];
#pragma unroll
        for (int e = 0; e < DH; e++) w[e] = w_out[o * HID + h * DH + e];
#pragma unroll 4
        for (int d = 0; d < DH; d++) {
            float s = 0.f;
#pragma unroll
            for (int e = 0; e < DH; e++) s += w[e] * cs[h][d][e];
            dst[h * DH + d] = s;
        }
    }
}

// ---------------------------------------------------------------------------
// Kernel 6 (tf32 mma + fused LN): out[b,o,n] = Wf[b]·q[b] + b_out, LN over o.
// CTA 256(M) x 64(N), K=128, BK=32. 8 warps (4M x 2N), warp tile 64x32.
// ---------------------------------------------------------------------------
#define OA_LD 36
#define OB_LD 72    // bank = 8tg+g, conflict-free
#define OUT_DYN ((256 * OA_LD + 32 * OB_LD) * 4)   // 46080 bytes

__global__ __launch_bounds__(256) void out_ln_mma(const float* __restrict__ b_out,
                                                  const float* __restrict__ gamma,
                                                  const float* __restrict__ beta,
                                                  float* __restrict__ out) {
    extern __shared__ uint32_t dynbuf[];
    uint32_t* As = dynbuf;                 // 256 x OA_LD
    uint32_t* Bs = dynbuf + 256 * OA_LD;   // 32 x OB_LD
    __shared__ float s_sum[4][64];
    __shared__ float s_sq [4][64];
    __shared__ float s_mean[64], s_rstd[64];

    const int b  = blockIdx.y;
    const int n0 = blockIdx.x * 64;
    const float* A = g_wf + (size_t)b * DIMC * HID;   // 256 x 128
    const float* Q = g_qkv + (size_t)b * THREE * NSP; // rows [0,128): softmaxed q*SCALE

    const int tid = threadIdx.x, wid = tid >> 5, lane = tid & 31;
    const int wm = wid >> 1, wn = wid & 1;    // 4 x 2 warps
    const int g = lane >> 2, tg = lane & 3;

    float acc[4][4][4];
#pragma unroll
    for (int i = 0; i < 4; ++i)
#pragma unroll
        for (int j = 0; j < 4; ++j)
#pragma unroll
            for (int e = 0; e < 4; ++e) acc[i][j][e] = 0.f;

#pragma unroll 1
    for (int k0 = 0; k0 < HID; k0 += 32) {
        // A: Wf[row][k0..k0+31], 256 rows
#pragma unroll
        for (int j = 0; j < 8; ++j) {
            int fi = j * 256 + tid;                 // 2048 float4s
            int row = fi >> 3, q = fi & 7;
            float4 v = *(const float4*)(A + (size_t)row * HID + k0 + q * 4);
            uint32_t* d = &As[row * OA_LD + q * 4];
            d[0] = f2tf32(v.x); d[1] = f2tf32(v.y);
            d[2] = f2tf32(v.z); d[3] = f2tf32(v.w);
        }
        // B: Q[k0+k][n0+nn], 32 k x 64 n
#pragma unroll
        for (int j = 0; j < 2; ++j) {
            int fi = j * 256 + tid;                 // 512 float4s
            int k = fi >> 4, nn = (fi & 15) * 4;
            float4 v = *(const float4*)(Q + (size_t)(k0 + k) * NSP + n0 + nn);
            uint32_t* d = &Bs[k * OB_LD + nn];
            d[0] = f2tf32(v.x); d[1] = f2tf32(v.y);
            d[2] = f2tf32(v.z); d[3] = f2tf32(v.w);
        }
        __syncthreads();

#pragma unroll
        for (int ks = 0; ks < 32; ks += 8) {
            uint32_t af[4][4], bf[4][2];
#pragma unroll
            for (int i = 0; i < 4; ++i) {
                int r = wm * 64 + i * 16;
                af[i][0] = As[(r + g)     * OA_LD + ks + tg];
                af[i][1] = As[(r + g + 8) * OA_LD + ks + tg];
                af[i][2] = As[(r + g)     * OA_LD + ks + tg + 4];
                af[i][3] = As[(r + g + 8) * OA_LD + ks + tg + 4];
            }
#pragma unroll
            for (int jn = 0; jn < 4; ++jn) {
                int c = wn * 32 + jn * 8 + g;
                bf[jn][0] = Bs[(ks + tg)     * OB_LD + c];
                bf[jn][1] = Bs[(ks + tg + 4) * OB_LD + c];
            }
#pragma unroll
            for (int i = 0; i < 4; ++i)
#pragma unroll
                for (int jn = 0; jn < 4; ++jn)
                    mma_tf32(acc[i][jn], af[i], bf[jn]);
        }
        __syncthreads();
    }

    // Add bias into accumulators
#pragma unroll
    for (int i = 0; i < 4; ++i) {
        float bo0 = b_out[wm * 64 + i * 16 + g];
        float bo1 = b_out[wm * 64 + i * 16 + g + 8];
#pragma unroll
        for (int jn = 0; jn < 4; ++jn) {
            acc[i][jn][0] += bo0; acc[i][jn][1] += bo0;
            acc[i][jn][2] += bo1; acc[i][jn][3] += bo1;
        }
    }

    // Per-column (n) stats over the 256 channels.
    float ps[8], pq[8];
#pragma unroll
    for (int c = 0; c < 8; ++c) { ps[c] = 0.f; pq[c] = 0.f; }
#pragma unroll
    for (int i = 0; i < 4; ++i)
#pragma unroll
        for (int jn = 0; jn < 4; ++jn)
#pragma unroll
            for (int e = 0; e < 2; ++e) {
                float v0 = acc[i][jn][e];       // row g
                float v1 = acc[i][jn][2 + e];   // row g+8
                ps[jn * 2 + e] += v0 + v1;
                pq[jn * 2 + e] += v0 * v0 + v1 * v1;
            }
#pragma unroll
    for (int c = 0; c < 8; ++c) {
#pragma unroll
        for (int off = 4; off < 32; off <<= 1) {
            ps[c] += __shfl_xor_sync(0xffffffffu, ps[c], off);
            pq[c] += __shfl_xor_sync(0xffffffffu, pq[c], off);
        }
    }
    if (g == 0) {
#pragma unroll
        for (int jn = 0; jn < 4; ++jn)
#pragma unroll
            for (int e = 0; e < 2; ++e) {
                int col = wn * 32 + jn * 8 + tg * 2 + e;
                s_sum[wm][col] = ps[jn * 2 + e];
                s_sq [wm][col] = pq[jn * 2 + e];
            }
    }
    __syncthreads();
    if (tid < 64) {
        float s = s_sum[0][tid] + s_sum[1][tid] + s_sum[2][tid] + s_sum[3][tid];
        float q = s_sq [0][tid] + s_sq [1][tid] + s_sq [2][tid] + s_sq [3][tid];
        float mean = s * (1.0f / 256.0f);
        float var  = q * (1.0f / 256.0f) - mean * mean;
        s_mean[tid] = mean;
        s_rstd[tid] = rsqrtf(var + EPS);
    }
    __syncthreads();

    // Normalize + store
#pragma unroll
    for (int i = 0; i < 4; ++i) {
        int o0 = wm * 64 + i * 16 + g;
        float g0 = gamma[o0], b0v = beta[o0];
        float g1 = gamma[o0 + 8], b1v = beta[o0 + 8];
#pragma unroll
        for (int jn = 0; jn < 4; ++jn) {
            int cl = wn * 32 + jn * 8 + tg * 2;
            float m0 = s_mean[cl],     r0 = s_rstd[cl];
            float m1 = s_mean[cl + 1], r1 = s_rstd[cl + 1];
            *(float2*)&out[((size_t)b * DIMC + o0) * NSP + n0 + cl] =
                make_float2((acc[i][jn][0] - m0) * r0 * g0 + b0v,
                            (acc[i][jn][1] - m1) * r1 * g0 + b0v);
            *(float2*)&out[((size_t)b * DIMC + o0 + 8) * NSP + n0 + cl] =
                make_float2((acc[i][jn][2] - m0) * r0 * g1 + b1v,
                            (acc[i][jn][3] - m1) * r1 * g1 + b1v);
        }
    }
}

// ---------------------------------------------------------------------------
extern "C" void kernel_launch(void* const* d_in, const int* in_sizes, int n_in,
                              void* d_out, int out_size) {
    const float* x     = (const float*)d_in[0];
    const float* w_qkv = (const float*)d_in[1];
    const float* w_out = (const float*)d_in[2];
    const float* b_out = (const float*)d_in[3];
    const float* g     = (const float*)d_in[4];
    const float* bb    = (const float*)d_in[5];
    float* out = (float*)d_out;

    qkv_mma<<<dim3(NSP / 128, THREE / 128, NB), 256>>>(w_qkv, x);
    k_softmax<<<NB * HID, 256>>>();
    ctx_slice<<<dim3(NB * HEADS, NSLICE), 256>>>();
    wf_kernel<<<NB, 256>>>(w_out);
    out_ln_mma<<<dim3(NSP / 64, NB), 256, OUT_DYN>>>(b_out, g, bb, out);
}

// round 11
// speedup vs baseline: 2.8927x; 1.1439x over previous
#include <cuda_runtime.h>
#include <cuda_bf16.h>
#include <math.h>
#include <stdint.h>

// Problem constants
#define NB    32
#define DIMC  256
#define HEADS 4
#define DH    32
#define HID   128      // HEADS*DH
#define THREE 384      // 3*HID
#define NSP   4096     // 64*64 spatial
#define SCALE 0.17677669529663687f  // 32^-0.5
#define EPS   1e-5f
#define NSLICE 8       // ctx n-split

// Scratch (device globals)
__device__ float g_qkv [(size_t)NB * THREE * NSP];              // ~201 MB
__device__ float g_ctxp[(size_t)NSLICE * NB * HEADS * DH * DH]; // 4 MB
__device__ float g_wf  [(size_t)NB * DIMC * HID];               // 4 MB

// ---------------------------------------------------------------------------
// Helpers: tf32 convert (round-to-nearest) + m16n8k8 tf32 MMA
// ---------------------------------------------------------------------------
__device__ __forceinline__ uint32_t f2tf32(float f) {
    uint32_t u;
    asm("cvt.rna.tf32.f32 %0, %1;" : "=r"(u) : "f"(f));
    return u;
}
__device__ __forceinline__ void mma_tf32(float* d, const uint32_t* a, const uint32_t* b) {
    asm volatile(
        "mma.sync.aligned.m16n8k8.row.col.f32.tf32.tf32.f32 "
        "{%0,%1,%2,%3}, {%4,%5,%6,%7}, {%8,%9}, {%0,%1,%2,%3};\n"
        : "+f"(d[0]), "+f"(d[1]), "+f"(d[2]), "+f"(d[3])
        : "r"(a[0]), "r"(a[1]), "r"(a[2]), "r"(a[3]), "r"(b[0]), "r"(b[1]));
}

// Fragment layout (m16n8k8 tf32), lane = 4*g + tg, g in [0,8), tg in [0,4):
//  A: a0=A[g][tg]  a1=A[g+8][tg]  a2=A[g][tg+4]  a3=A[g+8][tg+4]
//  B: b0=B[tg][g]  b1=B[tg+4][g]
//  C: c0=C[g][2tg] c1=C[g][2tg+1] c2=C[g+8][2tg] c3=C[g+8][2tg+1]

#define QA_LD 36    // A smem pitch: bank = 4g+tg  (conflict-free)
#define QB_LD 136   // B smem pitch: bank = 8tg+g  (conflict-free)
#define QKV_DYN ((2 * 128 * QA_LD + 2 * 32 * QB_LD) * 4)   // 71680 bytes

// ---------------------------------------------------------------------------
// Kernel 1 (tf32 mma, double-buffered): qkv[b,o,n] = sum_c W[o,c] * X[b,c,n]
// CTA 128x128, BK=32, 8 warps (2M x 4N). blockIdx.y==0 fuses q-softmax.
// ---------------------------------------------------------------------------
__global__ __launch_bounds__(256) void qkv_mma(const float* __restrict__ W,
                                               const float* __restrict__ X) {
    extern __shared__ uint32_t qbuf[];
    uint32_t* As = qbuf;                       // 2 x 128 x QA_LD
    uint32_t* Bs = qbuf + 2 * 128 * QA_LD;     // 2 x 32 x QB_LD

    const int b  = blockIdx.z;
    const int m0 = blockIdx.y * 128;           // within 384
    const int n0 = blockIdx.x * 128;
    const float* Xb = X + (size_t)b * DIMC * NSP;
    float* Cb = g_qkv + (size_t)b * THREE * NSP;

    const int tid = threadIdx.x, wid = tid >> 5, lane = tid & 31;
    const int wm = wid >> 2, wn = wid & 3;     // 2 x 4 warps
    const int g = lane >> 2, tg = lane & 3;

    // Per-thread load coordinates (fixed across chunks)
    const int a_row[4] = { (0 * 256 + tid) >> 3, (1 * 256 + tid) >> 3,
                           (2 * 256 + tid) >> 3, (3 * 256 + tid) >> 3 };
    const int a_q = tid & 7;
    const int b_k[4]  = { (0 * 256 + tid) >> 5, (1 * 256 + tid) >> 5,
                          (2 * 256 + tid) >> 5, (3 * 256 + tid) >> 5 };
    const int b_nn = (tid & 31) * 4;

    float4 ra[4], rb[4];
    // Prefetch chunk 0
#pragma unroll
    for (int j = 0; j < 4; ++j)
        ra[j] = *(const float4*)(W + (size_t)(m0 + a_row[j]) * DIMC + a_q * 4);
#pragma unroll
    for (int j = 0; j < 4; ++j)
        rb[j] = *(const float4*)(Xb + (size_t)b_k[j] * NSP + n0 + b_nn);
    {
        uint32_t* Ab = As; uint32_t* Bb = Bs;
#pragma unroll
        for (int j = 0; j < 4; ++j) {
            uint32_t* d = &Ab[a_row[j] * QA_LD + a_q * 4];
            d[0] = f2tf32(ra[j].x); d[1] = f2tf32(ra[j].y);
            d[2] = f2tf32(ra[j].z); d[3] = f2tf32(ra[j].w);
        }
#pragma unroll
        for (int j = 0; j < 4; ++j) {
            uint32_t* d = &Bb[b_k[j] * QB_LD + b_nn];
            d[0] = f2tf32(rb[j].x); d[1] = f2tf32(rb[j].y);
            d[2] = f2tf32(rb[j].z); d[3] = f2tf32(rb[j].w);
        }
    }
    __syncthreads();

    float acc[4][4][4];
#pragma unroll
    for (int i = 0; i < 4; ++i)
#pragma unroll
        for (int j = 0; j < 4; ++j)
#pragma unroll
            for (int e = 0; e < 4; ++e) acc[i][j][e] = 0.f;

#pragma unroll 1
    for (int ch = 0; ch < 8; ++ch) {
        // Prefetch next chunk into registers (overlaps with compute below)
        if (ch < 7) {
            const int k0 = (ch + 1) * 32;
#pragma unroll
            for (int j = 0; j < 4; ++j)
                ra[j] = *(const float4*)(W + (size_t)(m0 + a_row[j]) * DIMC + k0 + a_q * 4);
#pragma unroll
            for (int j = 0; j < 4; ++j)
                rb[j] = *(const float4*)(Xb + (size_t)(k0 + b_k[j]) * NSP + n0 + b_nn);
        }
        const uint32_t* Ab = As + (ch & 1) * 128 * QA_LD;
        const uint32_t* Bb = Bs + (ch & 1) * 32 * QB_LD;
#pragma unroll
        for (int ks = 0; ks < 32; ks += 8) {
            uint32_t af[4][4], bf[4][2];
#pragma unroll
            for (int i = 0; i < 4; ++i) {
                int r = wm * 64 + i * 16;
                af[i][0] = Ab[(r + g)     * QA_LD + ks + tg];
                af[i][1] = Ab[(r + g + 8) * QA_LD + ks + tg];
                af[i][2] = Ab[(r + g)     * QA_LD + ks + tg + 4];
                af[i][3] = Ab[(r + g + 8) * QA_LD + ks + tg + 4];
            }
#pragma unroll
            for (int jn = 0; jn < 4; ++jn) {
                int c = wn * 32 + jn * 8 + g;
                bf[jn][0] = Bb[(ks + tg)     * QB_LD + c];
                bf[jn][1] = Bb[(ks + tg + 4) * QB_LD + c];
            }
#pragma unroll
            for (int i = 0; i < 4; ++i)
#pragma unroll
                for (int jn = 0; jn < 4; ++jn)
                    mma_tf32(acc[i][jn], af[i], bf[jn]);
        }
        if (ch < 7) {
            uint32_t* An = As + ((ch + 1) & 1) * 128 * QA_LD;
            uint32_t* Bn = Bs + ((ch + 1) & 1) * 32 * QB_LD;
#pragma unroll
            for (int j = 0; j < 4; ++j) {
                uint32_t* d = &An[a_row[j] * QA_LD + a_q * 4];
                d[0] = f2tf32(ra[j].x); d[1] = f2tf32(ra[j].y);
                d[2] = f2tf32(ra[j].z); d[3] = f2tf32(ra[j].w);
            }
#pragma unroll
            for (int j = 0; j < 4; ++j) {
                uint32_t* d = &Bn[b_k[j] * QB_LD + b_nn];
                d[0] = f2tf32(rb[j].x); d[1] = f2tf32(rb[j].y);
                d[2] = f2tf32(rb[j].z); d[3] = f2tf32(rb[j].w);
            }
            __syncthreads();
        }
    }

    // Fused q softmax (only the m-block holding rows [0,128) = q).
    if (m0 == 0) {
#pragma unroll
        for (int jn = 0; jn < 4; ++jn)
#pragma unroll
            for (int e = 0; e < 2; ++e)
#pragma unroll
                for (int hd = 0; hd < 2; ++hd) {
                    const int ib = hd * 2;
                    float v0 = acc[ib][jn][e],     v1 = acc[ib][jn][2 + e];
                    float v2 = acc[ib + 1][jn][e], v3 = acc[ib + 1][jn][2 + e];
                    float m = fmaxf(fmaxf(v0, v1), fmaxf(v2, v3));
#pragma unroll
                    for (int off = 4; off < 32; off <<= 1)
                        m = fmaxf(m, __shfl_xor_sync(0xffffffffu, m, off));
                    v0 = __expf(v0 - m); v1 = __expf(v1 - m);
                    v2 = __expf(v2 - m); v3 = __expf(v3 - m);
                    float s = (v0 + v1) + (v2 + v3);
#pragma unroll
                    for (int off = 4; off < 32; off <<= 1)
                        s += __shfl_xor_sync(0xffffffffu, s, off);
                    float inv = SCALE / s;
                    acc[ib][jn][e]         = v0 * inv;
                    acc[ib][jn][2 + e]     = v1 * inv;
                    acc[ib + 1][jn][e]     = v2 * inv;
                    acc[ib + 1][jn][2 + e] = v3 * inv;
                }
    }

    // Epilogue: direct float2 stores
#pragma unroll
    for (int i = 0; i < 4; ++i) {
        int r0 = m0 + wm * 64 + i * 16 + g;
#pragma unroll
        for (int jn = 0; jn < 4; ++jn) {
            int c = n0 + wn * 32 + jn * 8 + tg * 2;
            *(float2*)&Cb[(size_t)r0 * NSP + c] =
                make_float2(acc[i][jn][0], acc[i][jn][1]);
            *(float2*)&Cb[(size_t)(r0 + 8) * NSP + c] =
                make_float2(acc[i][jn][2], acc[i][jn][3]);
        }
    }
}

// ---------------------------------------------------------------------------
// Kernel 3: k softmax over n (unchanged)
// ---------------------------------------------------------------------------
__global__ __launch_bounds__(256) void k_softmax() {
    __shared__ float buf[NSP];
    __shared__ float red[256];
    int row = blockIdx.x;
    int b = row >> 7, r = row & 127;
    float* base = g_qkv + (size_t)b * THREE * NSP + (size_t)(HID + r) * NSP;
    int tid = threadIdx.x;

    float mx = -1e30f;
    for (int i = tid; i < NSP; i += 256) { float x = base[i]; buf[i] = x; mx = fmaxf(mx, x); }
    red[tid] = mx; __syncthreads();
    for (int s = 128; s > 0; s >>= 1) {
        if (tid < s) red[tid] = fmaxf(red[tid], red[tid + s]);
        __syncthreads();
    }
    mx = red[0]; __syncthreads();

    float sum = 0.f;
    for (int i = tid; i < NSP; i += 256) { float e = __expf(buf[i] - mx); buf[i] = e; sum += e; }
    red[tid] = sum; __syncthreads();
    for (int s = 128; s > 0; s >>= 1) {
        if (tid < s) red[tid] += red[tid + s];
        __syncthreads();
    }
    float inv = 1.0f / red[0];
    __syncthreads();
    for (int i = tid; i < NSP; i += 256) base[i] = buf[i] * inv;
}

// ---------------------------------------------------------------------------
// Kernel 4: context partials (unchanged). grid = (NB*HEADS, NSLICE).
// ---------------------------------------------------------------------------
__global__ __launch_bounds__(256) void ctx_slice() {
    __shared__ float Ks[4][32][33];
    __shared__ float Vs[4][32][33];
    __shared__ float racc[3][64][16];
    int bh = blockIdx.x;
    int sl = blockIdx.y;
    int b = bh >> 2, h = bh & 3;
    const float* kbase = g_qkv + (size_t)b * THREE * NSP + (size_t)(HID + h * DH) * NSP;
    const float* vbase = g_qkv + (size_t)b * THREE * NSP + (size_t)(2 * HID + h * DH) * NSP;

    int tid = threadIdx.x;
    int grp = tid >> 6;
    int t   = tid & 63;
    int td = t >> 3, te = t & 7;

    float acc[4][4];
#pragma unroll
    for (int i = 0; i < 4; i++)
#pragma unroll
        for (int j = 0; j < 4; j++) acc[i][j] = 0.f;

    const int base_n = sl * (NSP / NSLICE) + grp * 128;
#pragma unroll 1
    for (int cc = 0; cc < 128; cc += 32) {
        int c0 = base_n + cc;
#pragma unroll
        for (int m = 0; m < 4; m++) {
            int fi = m * 64 + t;
            int dd = fi >> 3;
            int nn = (fi & 7) * 4;
            float4 kv = *(const float4*)&kbase[(size_t)dd * NSP + c0 + nn];
            float4 vv = *(const float4*)&vbase[(size_t)dd * NSP + c0 + nn];
            Ks[grp][dd][nn+0] = kv.x; Ks[grp][dd][nn+1] = kv.y;
            Ks[grp][dd][nn+2] = kv.z; Ks[grp][dd][nn+3] = kv.w;
            Vs[grp][dd][nn+0] = vv.x; Vs[grp][dd][nn+1] = vv.y;
            Vs[grp][dd][nn+2] = vv.z; Vs[grp][dd][nn+3] = vv.w;
        }
        __syncthreads();
#pragma unroll 4
        for (int n = 0; n < 32; n++) {
            float ka[4], vb[4];
#pragma unroll
            for (int i = 0; i < 4; i++) ka[i] = Ks[grp][td * 4 + i][n];
#pragma unroll
            for (int j = 0; j < 4; j++) vb[j] = Vs[grp][te * 4 + j][n];
#pragma unroll
            for (int i = 0; i < 4; i++)
#pragma unroll
                for (int j = 0; j < 4; j++) acc[i][j] += ka[i] * vb[j];
        }
        __syncthreads();
    }

    if (grp > 0) {
#pragma unroll
        for (int i = 0; i < 4; i++)
#pragma unroll
            for (int j = 0; j < 4; j++) racc[grp - 1][t][i * 4 + j] = acc[i][j];
    }
    __syncthreads();
    if (grp == 0) {
#pragma unroll
        for (int gg = 0; gg < 3; gg++)
#pragma unroll
            for (int i = 0; i < 4; i++)
#pragma unroll
                for (int j = 0; j < 4; j++) acc[i][j] += racc[gg][t][i * 4 + j];
        float* dst = g_ctxp + ((size_t)sl * NB * HEADS + bh) * (DH * DH);
#pragma unroll
        for (int i = 0; i < 4; i++)
#pragma unroll
            for (int j = 0; j < 4; j++)
                dst[(td * 4 + i) * DH + te * 4 + j] = acc[i][j];
    }
}

// ---------------------------------------------------------------------------
// Kernel 5: fused weight Wf, one block per (b,h). Sums the NSLICE ctx
// partials into smem, stages the w_out head-slice coalesced, computes
// Wf[o][h*32+d] = sum_e w_out[o][h*32+e] * ctx[d][e] from smem.
// ---------------------------------------------------------------------------
__global__ __launch_bounds__(256) void wf_kernel(const float* __restrict__ w_out) {
    __shared__ float cs[DH][DH];          // 4 KB
    __shared__ float ws[256][DH + 1];     // 33.8 KB, bank = (o+e)%32
    const int bh = blockIdx.x;
    const int b = bh >> 2, h = bh & 3;
    const int tid = threadIdx.x;

    // Sum ctx partials over slices
    {
        const size_t ss = (size_t)NB * HEADS * DH * DH;
        const size_t base = (size_t)bh * DH * DH;
        for (int i = tid; i < DH * DH; i += 256) {
            float s = 0.f;
#pragma unroll
            for (int sl = 0; sl < NSLICE; ++sl)
                s += g_ctxp[sl * ss + base + i];
            ((float*)cs)[i] = s;
        }
    }
    // Stage w_out[:, h*32 .. h*32+31] (256 rows x 8 float4, coalesced)
#pragma unroll
    for (int it = 0; it < 8; ++it) {
        int idx = it * 256 + tid;
        int row = idx >> 3, e4 = idx & 7;
        float4 v = *(const float4*)&w_out[row * HID + h * DH + e4 * 4];
        ws[row][e4 * 4 + 0] = v.x; ws[row][e4 * 4 + 1] = v.y;
        ws[row][e4 * 4 + 2] = v.z; ws[row][e4 * 4 + 3] = v.w;
    }
    __syncthreads();

    const int o = tid;
    float w[DH];
#pragma unroll
    for (int e = 0; e < DH; ++e) w[e] = ws[o][e];

    float* dst = g_wf + ((size_t)b * DIMC + o) * HID + h * DH;
#pragma unroll 4
    for (int d = 0; d < DH; d += 4) {
        float4 r;
        float s0 = 0.f, s1 = 0.f, s2 = 0.f, s3 = 0.f;
#pragma unroll
        for (int e = 0; e < DH; ++e) {
            float we = w[e];
            s0 += we * cs[d + 0][e];
            s1 += we * cs[d + 1][e];
            s2 += we * cs[d + 2][e];
            s3 += we * cs[d + 3][e];
        }
        r.x = s0; r.y = s1; r.z = s2; r.w = s3;
        *(float4*)&dst[d] = r;
    }
}

// ---------------------------------------------------------------------------
// Kernel 6 (tf32 mma + fused LN): out[b,o,n] = Wf[b]·q[b] + b_out, LN over o.
// CTA 256(M) x 64(N), K=128, BK=32. 8 warps (4M x 2N), warp tile 64x32.
// ---------------------------------------------------------------------------
#define OA_LD 36
#define OB_LD 72    // bank = 8tg+g, conflict-free
#define OUT_DYN ((256 * OA_LD + 32 * OB_LD) * 4)   // 46080 bytes

__global__ __launch_bounds__(256) void out_ln_mma(const float* __restrict__ b_out,
                                                  const float* __restrict__ gamma,
                                                  const float* __restrict__ beta,
                                                  float* __restrict__ out) {
    extern __shared__ uint32_t dynbuf[];
    uint32_t* As = dynbuf;                 // 256 x OA_LD
    uint32_t* Bs = dynbuf + 256 * OA_LD;   // 32 x OB_LD
    __shared__ float s_sum[4][64];
    __shared__ float s_sq [4][64];
    __shared__ float s_mean[64], s_rstd[64];

    const int b  = blockIdx.y;
    const int n0 = blockIdx.x * 64;
    const float* A = g_wf + (size_t)b * DIMC * HID;   // 256 x 128
    const float* Q = g_qkv + (size_t)b * THREE * NSP; // rows [0,128): softmaxed q*SCALE

    const int tid = threadIdx.x, wid = tid >> 5, lane = tid & 31;
    const int wm = wid >> 1, wn = wid & 1;    // 4 x 2 warps
    const int g = lane >> 2, tg = lane & 3;

    float acc[4][4][4];
#pragma unroll
    for (int i = 0; i < 4; ++i)
#pragma unroll
        for (int j = 0; j < 4; ++j)
#pragma unroll
            for (int e = 0; e < 4; ++e) acc[i][j][e] = 0.f;

#pragma unroll 1
    for (int k0 = 0; k0 < HID; k0 += 32) {
        // A: Wf[row][k0..k0+31], 256 rows
#pragma unroll
        for (int j = 0; j < 8; ++j) {
            int fi = j * 256 + tid;                 // 2048 float4s
            int row = fi >> 3, q = fi & 7;
            float4 v = *(const float4*)(A + (size_t)row * HID + k0 + q * 4);
            uint32_t* d = &As[row * OA_LD + q * 4];
            d[0] = f2tf32(v.x); d[1] = f2tf32(v.y);
            d[2] = f2tf32(v.z); d[3] = f2tf32(v.w);
        }
        // B: Q[k0+k][n0+nn], 32 k x 64 n
#pragma unroll
        for (int j = 0; j < 2; ++j) {
            int fi = j * 256 + tid;                 // 512 float4s
            int k = fi >> 4, nn = (fi & 15) * 4;
            float4 v = *(const float4*)(Q + (size_t)(k0 + k) * NSP + n0 + nn);
            uint32_t* d = &Bs[k * OB_LD + nn];
            d[0] = f2tf32(v.x); d[1] = f2tf32(v.y);
            d[2] = f2tf32(v.z); d[3] = f2tf32(v.w);
        }
        __syncthreads();

#pragma unroll
        for (int ks = 0; ks < 32; ks += 8) {
            uint32_t af[4][4], bf[4][2];
#pragma unroll
            for (int i = 0; i < 4; ++i) {
                int r = wm * 64 + i * 16;
                af[i][0] = As[(r + g)     * OA_LD + ks + tg];
                af[i][1] = As[(r + g + 8) * OA_LD + ks + tg];
                af[i][2] = As[(r + g)     * OA_LD + ks + tg + 4];
                af[i][3] = As[(r + g + 8) * OA_LD + ks + tg + 4];
            }
#pragma unroll
            for (int jn = 0; jn < 4; ++jn) {
                int c = wn * 32 + jn * 8 + g;
                bf[jn][0] = Bs[(ks + tg)     * OB_LD + c];
                bf[jn][1] = Bs[(ks + tg + 4) * OB_LD + c];
            }
#pragma unroll
            for (int i = 0; i < 4; ++i)
#pragma unroll
                for (int jn = 0; jn < 4; ++jn)
                    mma_tf32(acc[i][jn], af[i], bf[jn]);
        }
        __syncthreads();
    }

    // Add bias into accumulators
#pragma unroll
    for (int i = 0; i < 4; ++i) {
        float bo0 = b_out[wm * 64 + i * 16 + g];
        float bo1 = b_out[wm * 64 + i * 16 + g + 8];
#pragma unroll
        for (int jn = 0; jn < 4; ++jn) {
            acc[i][jn][0] += bo0; acc[i][jn][1] += bo0;
            acc[i][jn][2] += bo1; acc[i][jn][3] += bo1;
        }
    }

    // Per-column (n) stats over the 256 channels.
    float ps[8], pq[8];
#pragma unroll
    for (int c = 0; c < 8; ++c) { ps[c] = 0.f; pq[c] = 0.f; }
#pragma unroll
    for (int i = 0; i < 4; ++i)
#pragma unroll
        for (int jn = 0; jn < 4; ++jn)
#pragma unroll
            for (int e = 0; e < 2; ++e) {
                float v0 = acc[i][jn][e];       // row g
                float v1 = acc[i][jn][2 + e];   // row g+8
                ps[jn * 2 + e] += v0 + v1;
                pq[jn * 2 + e] += v0 * v0 + v1 * v1;
            }
#pragma unroll
    for (int c = 0; c < 8; ++c) {
#pragma unroll
        for (int off = 4; off < 32; off <<= 1) {
            ps[c] += __shfl_xor_sync(0xffffffffu, ps[c], off);
            pq[c] += __shfl_xor_sync(0xffffffffu, pq[c], off);
        }
    }
    if (g == 0) {
#pragma unroll
        for (int jn = 0; jn < 4; ++jn)
#pragma unroll
            for (int e = 0; e < 2; ++e) {
                int col = wn * 32 + jn * 8 + tg * 2 + e;
                s_sum[wm][col] = ps[jn * 2 + e];
                s_sq [wm][col] = pq[jn * 2 + e];
            }
    }
    __syncthreads();
    if (tid < 64) {
        float s = s_sum[0][tid] + s_sum[1][tid] + s_sum[2][tid] + s_sum[3][tid];
        float q = s_sq [0][tid] + s_sq [1][tid] + s_sq [2][tid] + s_sq [3][tid];
        float mean = s * (1.0f / 256.0f);
        float var  = q * (1.0f / 256.0f) - mean * mean;
        s_mean[tid] = mean;
        s_rstd[tid] = rsqrtf(var + EPS);
    }
    __syncthreads();

    // Normalize + store
#pragma unroll
    for (int i = 0; i < 4; ++i) {
        int o0 = wm * 64 + i * 16 + g;
        float g0 = gamma[o0], b0v = beta[o0];
        float g1 = gamma[o0 + 8], b1v = beta[o0 + 8];
#pragma unroll
        for (int jn = 0; jn < 4; ++jn) {
            int cl = wn * 32 + jn * 8 + tg * 2;
            float m0 = s_mean[cl],     r0 = s_rstd[cl];
            float m1 = s_mean[cl + 1], r1 = s_rstd[cl + 1];
            *(float2*)&out[((size_t)b * DIMC + o0) * NSP + n0 + cl] =
                make_float2((acc[i][jn][0] - m0) * r0 * g0 + b0v,
                            (acc[i][jn][1] - m1) * r1 * g0 + b0v);
            *(float2*)&out[((size_t)b * DIMC + o0 + 8) * NSP + n0 + cl] =
                make_float2((acc[i][jn][2] - m0) * r0 * g1 + b1v,
                            (acc[i][jn][3] - m1) * r1 * g1 + b1v);
        }
    }
}

// ---------------------------------------------------------------------------
extern "C" void kernel_launch(void* const* d_in, const int* in_sizes, int n_in,
                              void* d_out, int out_size) {
    const float* x     = (const float*)d_in[0];
    const float* w_qkv = (const float*)d_in[1];
    const float* w_out = (const float*)d_in[2];
    const float* b_out = (const float*)d_in[3];
    const float* g     = (const float*)d_in[4];
    const float* bb    = (const float*)d_in[5];
    float* out = (float*)d_out;

    cudaFuncSetAttribute(qkv_mma, cudaFuncAttributeMaxDynamicSharedMemorySize, QKV_DYN);

    qkv_mma<<<dim3(NSP / 128, THREE / 128, NB), 256, QKV_DYN>>>(w_qkv, x);
    k_softmax<<<NB * HID, 256>>>();
    ctx_slice<<<dim3(NB * HEADS, NSLICE), 256>>>();
    wf_kernel<<<NB * HEADS, 256>>>(w_out);
    out_ln_mma<<<dim3(NSP / 64, NB), 256, OUT_DYN>>>(b_out, g, bb, out);
}

// round 12
// speedup vs baseline: 3.6627x; 1.2662x over previous
#include <cuda_runtime.h>
#include <cuda_bf16.h>
#include <cuda_fp16.h>
#include <math.h>
#include <stdint.h>

// Problem constants
#define NB    32
#define DIMC  256
#define HEADS 4
#define DH    32
#define HID   128      // HEADS*DH
#define THREE 384      // 3*HID
#define NSP   4096     // 64*64 spatial
#define SCALE 0.17677669529663687f  // 32^-0.5
#define EPS   1e-5f
#define NSLICE 8       // ctx n-split

// Scratch (device globals)
__device__ float g_qkv [(size_t)NB * THREE * NSP];              // ~201 MB
__device__ float g_ctxp[(size_t)NSLICE * NB * HEADS * DH * DH]; // 4 MB
__device__ float g_wf  [(size_t)NB * DIMC * HID];               // 4 MB

// ---------------------------------------------------------------------------
// Helpers: fp16 pack + m16n8k16 f16 MMA (fp32 accumulate)
// ---------------------------------------------------------------------------
__device__ __forceinline__ uint32_t pack_h2(float lo, float hi) {
    __half2 h = __floats2half2_rn(lo, hi);   // .x = lo (low 16 bits)
    return *(uint32_t*)&h;
}
__device__ __forceinline__ void mma_f16(float* d, const uint32_t* a, const uint32_t* b) {
    asm volatile(
        "mma.sync.aligned.m16n8k16.row.col.f32.f16.f16.f32 "
        "{%0,%1,%2,%3}, {%4,%5,%6,%7}, {%8,%9}, {%0,%1,%2,%3};\n"
        : "+f"(d[0]), "+f"(d[1]), "+f"(d[2]), "+f"(d[3])
        : "r"(a[0]), "r"(a[1]), "r"(a[2]), "r"(a[3]), "r"(b[0]), "r"(b[1]));
}

// Fragment layout (m16n8k16 f16), lane = 4*g + tg:
//  A (row, 16x16): a0={A[g][2tg],A[g][2tg+1]} a1={A[g+8][..]} a2={A[g][2tg+8..]} a3={A[g+8][2tg+8..]}
//    -> half2-over-k index: a0:[g][tg] a1:[g+8][tg] a2:[g][tg+4] a3:[g+8][tg+4]
//  B (col, 16x8):  b0={B[2tg][c],B[2tg+1][c]} b1={B[2tg+8][c],B[2tg+9][c]}
//    -> packed (k even,k odd): b0:[tg][c] b1:[tg+4][c]
//  C: c0=C[g][2tg] c1=C[g][2tg+1] c2=C[g+8][2tg] c3=C[g+8][2tg+1]  (same as tf32)

#define QA_LD 20    // A half2 pitch: bank = 4g+tg (20*g = 4*(5g), 5 odd -> distinct)
#define QB_LD 136   // B half2 pitch: bank = 8tg+g (136 % 32 == 8)
#define QKV_DYN ((2 * 128 * QA_LD + 2 * 16 * QB_LD) * 4)   // 37888 bytes

// ---------------------------------------------------------------------------
// Kernel 1 (fp16 mma, double-buffered): qkv[b,o,n] = sum_c W[o,c] * X[b,c,n]
// CTA 128x128, BK=32, 8 warps (2M x 4N). blockIdx.y==0 fuses q-softmax.
// ---------------------------------------------------------------------------
__global__ __launch_bounds__(256) void qkv_mma(const float* __restrict__ W,
                                               const float* __restrict__ X) {
    extern __shared__ uint32_t qbuf[];
    uint32_t* As = qbuf;                       // 2 x 128 x QA_LD
    uint32_t* Bs = qbuf + 2 * 128 * QA_LD;     // 2 x 16 x QB_LD

    const int b  = blockIdx.z;
    const int m0 = blockIdx.y * 128;           // within 384
    const int n0 = blockIdx.x * 128;
    const float* Xb = X + (size_t)b * DIMC * NSP;
    float* Cb = g_qkv + (size_t)b * THREE * NSP;

    const int tid = threadIdx.x, wid = tid >> 5, lane = tid & 31;
    const int wm = wid >> 2, wn = wid & 3;     // 2 x 4 warps
    const int g = lane >> 2, tg = lane & 3;

    // Per-thread load coordinates (fixed across chunks)
    const int a_row[4] = { (0 * 256 + tid) >> 3, (1 * 256 + tid) >> 3,
                           (2 * 256 + tid) >> 3, (3 * 256 + tid) >> 3 };
    const int a_q = tid & 7;
    const int b_k2[2] = { (0 * 256 + tid) >> 5, (1 * 256 + tid) >> 5 }; // [0,16)
    const int b_n4 = (tid & 31) * 4;

    float4 ra[4], rb0[2], rb1[2];
    // Prefetch chunk 0
#pragma unroll
    for (int j = 0; j < 4; ++j)
        ra[j] = *(const float4*)(W + (size_t)(m0 + a_row[j]) * DIMC + a_q * 4);
#pragma unroll
    for (int j = 0; j < 2; ++j) {
        rb0[j] = *(const float4*)(Xb + (size_t)(2 * b_k2[j])     * NSP + n0 + b_n4);
        rb1[j] = *(const float4*)(Xb + (size_t)(2 * b_k2[j] + 1) * NSP + n0 + b_n4);
    }
    {
        uint32_t* Ab = As; uint32_t* Bb = Bs;
#pragma unroll
        for (int j = 0; j < 4; ++j) {
            uint32_t* d = &Ab[a_row[j] * QA_LD + a_q * 2];
            d[0] = pack_h2(ra[j].x, ra[j].y);
            d[1] = pack_h2(ra[j].z, ra[j].w);
        }
#pragma unroll
        for (int j = 0; j < 2; ++j) {
            uint32_t* d = &Bb[b_k2[j] * QB_LD + b_n4];
            d[0] = pack_h2(rb0[j].x, rb1[j].x);
            d[1] = pack_h2(rb0[j].y, rb1[j].y);
            d[2] = pack_h2(rb0[j].z, rb1[j].z);
            d[3] = pack_h2(rb0[j].w, rb1[j].w);
        }
    }
    __syncthreads();

    float acc[4][4][4];
#pragma unroll
    for (int i = 0; i < 4; ++i)
#pragma unroll
        for (int j = 0; j < 4; ++j)
#pragma unroll
            for (int e = 0; e < 4; ++e) acc[i][j][e] = 0.f;

#pragma unroll 1
    for (int ch = 0; ch < 8; ++ch) {
        // Prefetch next chunk into registers (overlaps compute)
        if (ch < 7) {
            const int k0 = (ch + 1) * 32;
#pragma unroll
            for (int j = 0; j < 4; ++j)
                ra[j] = *(const float4*)(W + (size_t)(m0 + a_row[j]) * DIMC + k0 + a_q * 4);
#pragma unroll
            for (int j = 0; j < 2; ++j) {
                rb0[j] = *(const float4*)(Xb + (size_t)(k0 + 2 * b_k2[j])     * NSP + n0 + b_n4);
                rb1[j] = *(const float4*)(Xb + (size_t)(k0 + 2 * b_k2[j] + 1) * NSP + n0 + b_n4);
            }
        }
        const uint32_t* Ab = As + (ch & 1) * 128 * QA_LD;
        const uint32_t* Bb = Bs + (ch & 1) * 16 * QB_LD;
#pragma unroll
        for (int ks2 = 0; ks2 < 16; ks2 += 8) {   // two k16 steps per 32-chunk
            uint32_t af[4][4], bf[4][2];
#pragma unroll
            for (int i = 0; i < 4; ++i) {
                int r = wm * 64 + i * 16;
                af[i][0] = Ab[(r + g)     * QA_LD + ks2 + tg];
                af[i][1] = Ab[(r + g + 8) * QA_LD + ks2 + tg];
                af[i][2] = Ab[(r + g)     * QA_LD + ks2 + tg + 4];
                af[i][3] = Ab[(r + g + 8) * QA_LD + ks2 + tg + 4];
            }
#pragma unroll
            for (int jn = 0; jn < 4; ++jn) {
                int c = wn * 32 + jn * 8 + g;
                bf[jn][0] = Bb[(ks2 + tg)     * QB_LD + c];
                bf[jn][1] = Bb[(ks2 + tg + 4) * QB_LD + c];
            }
#pragma unroll
            for (int i = 0; i < 4; ++i)
#pragma unroll
                for (int jn = 0; jn < 4; ++jn)
                    mma_f16(acc[i][jn], af[i], bf[jn]);
        }
        if (ch < 7) {
            uint32_t* An = As + ((ch + 1) & 1) * 128 * QA_LD;
            uint32_t* Bn = Bs + ((ch + 1) & 1) * 16 * QB_LD;
#pragma unroll
            for (int j = 0; j < 4; ++j) {
                uint32_t* d = &An[a_row[j] * QA_LD + a_q * 2];
                d[0] = pack_h2(ra[j].x, ra[j].y);
                d[1] = pack_h2(ra[j].z, ra[j].w);
            }
#pragma unroll
            for (int j = 0; j < 2; ++j) {
                uint32_t* d = &Bn[b_k2[j] * QB_LD + b_n4];
                d[0] = pack_h2(rb0[j].x, rb1[j].x);
                d[1] = pack_h2(rb0[j].y, rb1[j].y);
                d[2] = pack_h2(rb0[j].z, rb1[j].z);
                d[3] = pack_h2(rb0[j].w, rb1[j].w);
            }
            __syncthreads();
        }
    }

    // Fused q softmax (only the m-block holding rows [0,128) = q).
    if (m0 == 0) {
#pragma unroll
        for (int jn = 0; jn < 4; ++jn)
#pragma unroll
            for (int e = 0; e < 2; ++e)
#pragma unroll
                for (int hd = 0; hd < 2; ++hd) {
                    const int ib = hd * 2;
                    float v0 = acc[ib][jn][e],     v1 = acc[ib][jn][2 + e];
                    float v2 = acc[ib + 1][jn][e], v3 = acc[ib + 1][jn][2 + e];
                    float m = fmaxf(fmaxf(v0, v1), fmaxf(v2, v3));
#pragma unroll
                    for (int off = 4; off < 32; off <<= 1)
                        m = fmaxf(m, __shfl_xor_sync(0xffffffffu, m, off));
                    v0 = __expf(v0 - m); v1 = __expf(v1 - m);
                    v2 = __expf(v2 - m); v3 = __expf(v3 - m);
                    float s = (v0 + v1) + (v2 + v3);
#pragma unroll
                    for (int off = 4; off < 32; off <<= 1)
                        s += __shfl_xor_sync(0xffffffffu, s, off);
                    float inv = SCALE / s;
                    acc[ib][jn][e]         = v0 * inv;
                    acc[ib][jn][2 + e]     = v1 * inv;
                    acc[ib + 1][jn][e]     = v2 * inv;
                    acc[ib + 1][jn][2 + e] = v3 * inv;
                }
    }

    // Epilogue: direct float2 stores
#pragma unroll
    for (int i = 0; i < 4; ++i) {
        int r0 = m0 + wm * 64 + i * 16 + g;
#pragma unroll
        for (int jn = 0; jn < 4; ++jn) {
            int c = n0 + wn * 32 + jn * 8 + tg * 2;
            *(float2*)&Cb[(size_t)r0 * NSP + c] =
                make_float2(acc[i][jn][0], acc[i][jn][1]);
            *(float2*)&Cb[(size_t)(r0 + 8) * NSP + c] =
                make_float2(acc[i][jn][2], acc[i][jn][3]);
        }
    }
}

// ---------------------------------------------------------------------------
// Kernel 3: k softmax over n (unchanged)
// ---------------------------------------------------------------------------
__global__ __launch_bounds__(256) void k_softmax() {
    __shared__ float buf[NSP];
    __shared__ float red[256];
    int row = blockIdx.x;
    int b = row >> 7, r = row & 127;
    float* base = g_qkv + (size_t)b * THREE * NSP + (size_t)(HID + r) * NSP;
    int tid = threadIdx.x;

    float mx = -1e30f;
    for (int i = tid; i < NSP; i += 256) { float x = base[i]; buf[i] = x; mx = fmaxf(mx, x); }
    red[tid] = mx; __syncthreads();
    for (int s = 128; s > 0; s >>= 1) {
        if (tid < s) red[tid] = fmaxf(red[tid], red[tid + s]);
        __syncthreads();
    }
    mx = red[0]; __syncthreads();

    float sum = 0.f;
    for (int i = tid; i < NSP; i += 256) { float e = __expf(buf[i] - mx); buf[i] = e; sum += e; }
    red[tid] = sum; __syncthreads();
    for (int s = 128; s > 0; s >>= 1) {
        if (tid < s) red[tid] += red[tid + s];
        __syncthreads();
    }
    float inv = 1.0f / red[0];
    __syncthreads();
    for (int i = tid; i < NSP; i += 256) base[i] = buf[i] * inv;
}

// ---------------------------------------------------------------------------
// Kernel 4: context partials (unchanged). grid = (NB*HEADS, NSLICE).
// ---------------------------------------------------------------------------
__global__ __launch_bounds__(256) void ctx_slice() {
    __shared__ float Ks[4][32][33];
    __shared__ float Vs[4][32][33];
    __shared__ float racc[3][64][16];
    int bh = blockIdx.x;
    int sl = blockIdx.y;
    int b = bh >> 2, h = bh & 3;
    const float* kbase = g_qkv + (size_t)b * THREE * NSP + (size_t)(HID + h * DH) * NSP;
    const float* vbase = g_qkv + (size_t)b * THREE * NSP + (size_t)(2 * HID + h * DH) * NSP;

    int tid = threadIdx.x;
    int grp = tid >> 6;
    int t   = tid & 63;
    int td = t >> 3, te = t & 7;

    float acc[4][4];
#pragma unroll
    for (int i = 0; i < 4; i++)
#pragma unroll
        for (int j = 0; j < 4; j++) acc[i][j] = 0.f;

    const int base_n = sl * (NSP / NSLICE) + grp * 128;
#pragma unroll 1
    for (int cc = 0; cc < 128; cc += 32) {
        int c0 = base_n + cc;
#pragma unroll
        for (int m = 0; m < 4; m++) {
            int fi = m * 64 + t;
            int dd = fi >> 3;
            int nn = (fi & 7) * 4;
            float4 kv = *(const float4*)&kbase[(size_t)dd * NSP + c0 + nn];
            float4 vv = *(const float4*)&vbase[(size_t)dd * NSP + c0 + nn];
            Ks[grp][dd][nn+0] = kv.x; Ks[grp][dd][nn+1] = kv.y;
            Ks[grp][dd][nn+2] = kv.z; Ks[grp][dd][nn+3] = kv.w;
            Vs[grp][dd][nn+0] = vv.x; Vs[grp][dd][nn+1] = vv.y;
            Vs[grp][dd][nn+2] = vv.z; Vs[grp][dd][nn+3] = vv.w;
        }
        __syncthreads();
#pragma unroll 4
        for (int n = 0; n < 32; n++) {
            float ka[4], vb[4];
#pragma unroll
            for (int i = 0; i < 4; i++) ka[i] = Ks[grp][td * 4 + i][n];
#pragma unroll
            for (int j = 0; j < 4; j++) vb[j] = Vs[grp][te * 4 + j][n];
#pragma unroll
            for (int i = 0; i < 4; i++)
#pragma unroll
                for (int j = 0; j < 4; j++) acc[i][j] += ka[i] * vb[j];
        }
        __syncthreads();
    }

    if (grp > 0) {
#pragma unroll
        for (int i = 0; i < 4; i++)
#pragma unroll
            for (int j = 0; j < 4; j++) racc[grp - 1][t][i * 4 + j] = acc[i][j];
    }
    __syncthreads();
    if (grp == 0) {
#pragma unroll
        for (int gg = 0; gg < 3; gg++)
#pragma unroll
            for (int i = 0; i < 4; i++)
#pragma unroll
                for (int j = 0; j < 4; j++) acc[i][j] += racc[gg][t][i * 4 + j];
        float* dst = g_ctxp + ((size_t)sl * NB * HEADS + bh) * (DH * DH);
#pragma unroll
        for (int i = 0; i < 4; i++)
#pragma unroll
            for (int j = 0; j < 4; j++)
                dst[(td * 4 + i) * DH + te * 4 + j] = acc[i][j];
    }
}

// ---------------------------------------------------------------------------
// Kernel 5: fused weight Wf, one block per (b,h) (unchanged from R11).
// ---------------------------------------------------------------------------
__global__ __launch_bounds__(256) void wf_kernel(const float* __restrict__ w_out) {
    __shared__ float cs[DH][DH];          // 4 KB
    __shared__ float ws[256][DH + 1];     // 33.8 KB
    const int bh = blockIdx.x;
    const int b = bh >> 2, h = bh & 3;
    const int tid = threadIdx.x;

    {
        const size_t ss = (size_t)NB * HEADS * DH * DH;
        const size_t base = (size_t)bh * DH * DH;
        for (int i = tid; i < DH * DH; i += 256) {
            float s = 0.f;
#pragma unroll
            for (int sl = 0; sl < NSLICE; ++sl)
                s += g_ctxp[sl * ss + base + i];
            ((float*)cs)[i] = s;
        }
    }
#pragma unroll
    for (int it = 0; it < 8; ++it) {
        int idx = it * 256 + tid;
        int row = idx >> 3, e4 = idx & 7;
        float4 v = *(const float4*)&w_out[row * HID + h * DH + e4 * 4];
        ws[row][e4 * 4 + 0] = v.x; ws[row][e4 * 4 + 1] = v.y;
        ws[row][e4 * 4 + 2] = v.z; ws[row][e4 * 4 + 3] = v.w;
    }
    __syncthreads();

    const int o = tid;
    float w[DH];
#pragma unroll
    for (int e = 0; e < DH; ++e) w[e] = ws[o][e];

    float* dst = g_wf + ((size_t)b * DIMC + o) * HID + h * DH;
#pragma unroll 4
    for (int d = 0; d < DH; d += 4) {
        float4 r;
        float s0 = 0.f, s1 = 0.f, s2 = 0.f, s3 = 0.f;
#pragma unroll
        for (int e = 0; e < DH; ++e) {
            float we = w[e];
            s0 += we * cs[d + 0][e];
            s1 += we * cs[d + 1][e];
            s2 += we * cs[d + 2][e];
            s3 += we * cs[d + 3][e];
        }
        r.x = s0; r.y = s1; r.z = s2; r.w = s3;
        *(float4*)&dst[d] = r;
    }
}

// ---------------------------------------------------------------------------
// Kernel 6 (fp16 mma + fused LN): out[b,o,n] = Wf[b]·q[b] + b_out, LN over o.
// CTA 256(M) x 64(N), K=128, BK=32. 8 warps (4M x 2N), warp tile 64x32.
// ---------------------------------------------------------------------------
#define OA_LD 20
#define OB_LD 72    // bank = 8tg+g (72 % 32 == 8), conflict-free
#define OUT_DYN ((256 * OA_LD + 16 * OB_LD) * 4)   // 25088 bytes

__global__ __launch_bounds__(256) void out_ln_mma(const float* __restrict__ b_out,
                                                  const float* __restrict__ gamma,
                                                  const float* __restrict__ beta,
                                                  float* __restrict__ out) {
    extern __shared__ uint32_t dynbuf[];
    uint32_t* As = dynbuf;                 // 256 x OA_LD
    uint32_t* Bs = dynbuf + 256 * OA_LD;   // 16 x OB_LD
    __shared__ float s_sum[4][64];
    __shared__ float s_sq [4][64];
    __shared__ float s_mean[64], s_rstd[64];

    const int b  = blockIdx.y;
    const int n0 = blockIdx.x * 64;
    const float* A = g_wf + (size_t)b * DIMC * HID;   // 256 x 128
    const float* Q = g_qkv + (size_t)b * THREE * NSP; // rows [0,128): softmaxed q*SCALE

    const int tid = threadIdx.x, wid = tid >> 5, lane = tid & 31;
    const int wm = wid >> 1, wn = wid & 1;    // 4 x 2 warps
    const int g = lane >> 2, tg = lane & 3;

    float acc[4][4][4];
#pragma unroll
    for (int i = 0; i < 4; ++i)
#pragma unroll
        for (int j = 0; j < 4; ++j)
#pragma unroll
            for (int e = 0; e < 4; ++e) acc[i][j][e] = 0.f;

#pragma unroll 1
    for (int k0 = 0; k0 < HID; k0 += 32) {
        // A: Wf[row][k0..k0+31], 256 rows -> half2-over-k
#pragma unroll
        for (int j = 0; j < 8; ++j) {
            int fi = j * 256 + tid;                 // 2048 float4 tasks
            int row = fi >> 3, q = fi & 7;
            float4 v = *(const float4*)(A + (size_t)row * HID + k0 + q * 4);
            uint32_t* d = &As[row * OA_LD + q * 2];
            d[0] = pack_h2(v.x, v.y);
            d[1] = pack_h2(v.z, v.w);
        }
        // B: Q[k0+2k2 / +1][n0+nn], packed (k even, k odd); 256 tasks
        {
            int k2 = tid >> 4, n4 = (tid & 15) * 4;
            float4 v0 = *(const float4*)(Q + (size_t)(k0 + 2 * k2)     * NSP + n0 + n4);
            float4 v1 = *(const float4*)(Q + (size_t)(k0 + 2 * k2 + 1) * NSP + n0 + n4);
            uint32_t* d = &Bs[k2 * OB_LD + n4];
            d[0] = pack_h2(v0.x, v1.x);
            d[1] = pack_h2(v0.y, v1.y);
            d[2] = pack_h2(v0.z, v1.z);
            d[3] = pack_h2(v0.w, v1.w);
        }
        __syncthreads();

#pragma unroll
        for (int ks2 = 0; ks2 < 16; ks2 += 8) {
            uint32_t af[4][4], bf[4][2];
#pragma unroll
            for (int i = 0; i < 4; ++i) {
                int r = wm * 64 + i * 16;
                af[i][0] = As[(r + g)     * OA_LD + ks2 + tg];
                af[i][1] = As[(r + g + 8) * OA_LD + ks2 + tg];
                af[i][2] = As[(r + g)     * OA_LD + ks2 + tg + 4];
                af[i][3] = As[(r + g + 8) * OA_LD + ks2 + tg + 4];
            }
#pragma unroll
            for (int jn = 0; jn < 4; ++jn) {
                int c = wn * 32 + jn * 8 + g;
                bf[jn][0] = Bs[(ks2 + tg)     * OB_LD + c];
                bf[jn][1] = Bs[(ks2 + tg + 4) * OB_LD + c];
            }
#pragma unroll
            for (int i = 0; i < 4; ++i)
#pragma unroll
                for (int jn = 0; jn < 4; ++jn)
                    mma_f16(acc[i][jn], af[i], bf[jn]);
        }
        __syncthreads();
    }

    // Add bias into accumulators
#pragma unroll
    for (int i = 0; i < 4; ++i) {
        float bo0 = b_out[wm * 64 + i * 16 + g];
        float bo1 = b_out[wm * 64 + i * 16 + g + 8];
#pragma unroll
        for (int jn = 0; jn < 4; ++jn) {
            acc[i][jn][0] += bo0; acc[i][jn][1] += bo0;
            acc[i][jn][2] += bo1; acc[i][jn][3] += bo1;
        }
    }

    // Per-column (n) stats over the 256 channels.
    float ps[8], pq[8];
#pragma unroll
    for (int c = 0; c < 8; ++c) { ps[c] = 0.f; pq[c] = 0.f; }
#pragma unroll
    for (int i = 0; i < 4; ++i)
#pragma unroll
        for (int jn = 0; jn < 4; ++jn)
#pragma unroll
            for (int e = 0; e < 2; ++e) {
                float v0 = acc[i][jn][e];       // row g
                float v1 = acc[i][jn][2 + e];   // row g+8
                ps[jn * 2 + e] += v0 + v1;
                pq[jn * 2 + e] += v0 * v0 + v1 * v1;
            }
#pragma unroll
    for (int c = 0; c < 8; ++c) {
#pragma unroll
        for (int off = 4; off < 32; off <<= 1) {
            ps[c] += __shfl_xor_sync(0xffffffffu, ps[c], off);
            pq[c] += __shfl_xor_sync(0xffffffffu, pq[c], off);
        }
    }
    if (g == 0) {
#pragma unroll
        for (int jn = 0; jn < 4; ++jn)
#pragma unroll
            for (int e = 0; e < 2; ++e) {
                int col = wn * 32 + jn * 8 + tg * 2 + e;
                s_sum[wm][col] = ps[jn * 2 + e];
                s_sq [wm][col] = pq[jn * 2 + e];
            }
    }
    __syncthreads();
    if (tid < 64) {
        float s = s_sum[0][tid] + s_sum[1][tid] + s_sum[2][tid] + s_sum[3][tid];
        float q = s_sq [0][tid] + s_sq [1][tid] + s_sq [2][tid] + s_sq [3][tid];
        float mean = s * (1.0f / 256.0f);
        float var  = q * (1.0f / 256.0f) - mean * mean;
        s_mean[tid] = mean;
        s_rstd[tid] = rsqrtf(var + EPS);
    }
    __syncthreads();

    // Normalize + store
#pragma unroll
    for (int i = 0; i < 4; ++i) {
        int o0 = wm * 64 + i * 16 + g;
        float g0 = gamma[o0], b0v = beta[o0];
        float g1 = gamma[o0 + 8], b1v = beta[o0 + 8];
#pragma unroll
        for (int jn = 0; jn < 4; ++jn) {
            int cl = wn * 32 + jn * 8 + tg * 2;
            float m0 = s_mean[cl],     r0 = s_rstd[cl];
            float m1 = s_mean[cl + 1], r1 = s_rstd[cl + 1];
            *(float2*)&out[((size_t)b * DIMC + o0) * NSP + n0 + cl] =
                make_float2((acc[i][jn][0] - m0) * r0 * g0 + b0v,
                            (acc[i][jn][1] - m1) * r1 * g0 + b0v);
            *(float2*)&out[((size_t)b * DIMC + o0 + 8) * NSP + n0 + cl] =
                make_float2((acc[i][jn][2] - m0) * r0 * g1 + b1v,
                            (acc[i][jn][3] - m1) * r1 * g1 + b1v);
        }
    }
}

// ---------------------------------------------------------------------------
extern "C" void kernel_launch(void* const* d_in, const int* in_sizes, int n_in,
                              void* d_out, int out_size) {
    const float* x     = (const float*)d_in[0];
    const float* w_qkv = (const float*)d_in[1];
    const float* w_out = (const float*)d_in[2];
    const float* b_out = (const float*)d_in[3];
    const float* g     = (const float*)d_in[4];
    const float* bb    = (const float*)d_in[5];
    float* out = (float*)d_out;

    qkv_mma<<<dim3(NSP / 128, THREE / 128, NB), 256, QKV_DYN>>>(w_qkv, x);
    k_softmax<<<NB * HID, 256>>>();
    ctx_slice<<<dim3(NB * HEADS, NSLICE), 256>>>();
    wf_kernel<<<NB * HEADS, 256>>>(w_out);
    out_ln_mma<<<dim3(NSP / 64, NB), 256, OUT_DYN>>>(b_out, g, bb, out);
}

// round 13
// speedup vs baseline: 4.0195x; 1.0974x over previous
#include <cuda_runtime.h>
#include <cuda_bf16.h>
#include <cuda_fp16.h>
#include <math.h>
#include <stdint.h>

// Problem constants
#define NB    32
#define DIMC  256
#define HEADS 4
#define DH    32
#define HID   128      // HEADS*DH
#define THREE 384      // 3*HID
#define NSP   4096     // 64*64 spatial
#define SCALE 0.17677669529663687f  // 32^-0.5
#define EPS   1e-5f
#define NSLICE 8       // ctx n-split

// Scratch (device globals)
__device__ __half g_qk [(size_t)NB * 2 * HID * NSP];            // q rows [0,128), k rows [128,256); 67 MB
__device__ float  g_v  [(size_t)NB * HID * NSP];                // 67 MB
__device__ float  g_ctxp[(size_t)NSLICE * NB * HEADS * DH * DH]; // 4 MB
__device__ __half g_wf [(size_t)NB * DIMC * HID];               // 2 MB

// ---------------------------------------------------------------------------
// Helpers: fp16 pack + m16n8k16 f16 MMA (fp32 accumulate)
// ---------------------------------------------------------------------------
__device__ __forceinline__ uint32_t pack_h2(float lo, float hi) {
    __half2 h = __floats2half2_rn(lo, hi);   // .x = lo (low 16 bits)
    return *(uint32_t*)&h;
}
__device__ __forceinline__ void mma_f16(float* d, const uint32_t* a, const uint32_t* b) {
    asm volatile(
        "mma.sync.aligned.m16n8k16.row.col.f32.f16.f16.f32 "
        "{%0,%1,%2,%3}, {%4,%5,%6,%7}, {%8,%9}, {%0,%1,%2,%3};\n"
        : "+f"(d[0]), "+f"(d[1]), "+f"(d[2]), "+f"(d[3])
        : "r"(a[0]), "r"(a[1]), "r"(a[2]), "r"(a[3]), "r"(b[0]), "r"(b[1]));
}

// Fragment layout (m16n8k16 f16), lane = 4*g + tg:
//  A half2-over-k index: a0:[g][tg] a1:[g+8][tg] a2:[g][tg+4] a3:[g+8][tg+4]
//  B packed (k even,k odd): b0:[tg][c] b1:[tg+4][c]
//  C: c0=C[g][2tg] c1=C[g][2tg+1] c2=C[g+8][2tg] c3=C[g+8][2tg+1]

#define QA_LD 20    // A half2 pitch: bank = 4g+tg (conflict-free)
#define QB_LD 136   // B half2 pitch: bank = 8tg+g (136 % 32 == 8)
#define QKV_DYN ((2 * 128 * QA_LD + 2 * 16 * QB_LD) * 4)   // 37888 bytes

// ---------------------------------------------------------------------------
// Kernel 1 (fp16 mma, double-buffered): qkv[b,o,n] = sum_c W[o,c] * X[b,c,n]
// CTA 128x128, BK=32, 8 warps (2M x 4N). m-block 0: fused q-softmax + half
// store; m-block 1: k half store; m-block 2: v float store.
// ---------------------------------------------------------------------------
__global__ __launch_bounds__(256) void qkv_mma(const float* __restrict__ W,
                                               const float* __restrict__ X) {
    extern __shared__ uint32_t qbuf[];
    uint32_t* As = qbuf;                       // 2 x 128 x QA_LD
    uint32_t* Bs = qbuf + 2 * 128 * QA_LD;     // 2 x 16 x QB_LD

    const int b  = blockIdx.z;
    const int m0 = blockIdx.y * 128;           // within 384
    const int n0 = blockIdx.x * 128;
    const float* Xb = X + (size_t)b * DIMC * NSP;

    const int tid = threadIdx.x, wid = tid >> 5, lane = tid & 31;
    const int wm = wid >> 2, wn = wid & 3;     // 2 x 4 warps
    const int g = lane >> 2, tg = lane & 3;

    const int a_row[4] = { (0 * 256 + tid) >> 3, (1 * 256 + tid) >> 3,
                           (2 * 256 + tid) >> 3, (3 * 256 + tid) >> 3 };
    const int a_q = tid & 7;
    const int b_k2[2] = { (0 * 256 + tid) >> 5, (1 * 256 + tid) >> 5 };
    const int b_n4 = (tid & 31) * 4;

    float4 ra[4], rb0[2], rb1[2];
#pragma unroll
    for (int j = 0; j < 4; ++j)
        ra[j] = *(const float4*)(W + (size_t)(m0 + a_row[j]) * DIMC + a_q * 4);
#pragma unroll
    for (int j = 0; j < 2; ++j) {
        rb0[j] = *(const float4*)(Xb + (size_t)(2 * b_k2[j])     * NSP + n0 + b_n4);
        rb1[j] = *(const float4*)(Xb + (size_t)(2 * b_k2[j] + 1) * NSP + n0 + b_n4);
    }
    {
        uint32_t* Ab = As; uint32_t* Bb = Bs;
#pragma unroll
        for (int j = 0; j < 4; ++j) {
            uint32_t* d = &Ab[a_row[j] * QA_LD + a_q * 2];
            d[0] = pack_h2(ra[j].x, ra[j].y);
            d[1] = pack_h2(ra[j].z, ra[j].w);
        }
#pragma unroll
        for (int j = 0; j < 2; ++j) {
            uint32_t* d = &Bb[b_k2[j] * QB_LD + b_n4];
            d[0] = pack_h2(rb0[j].x, rb1[j].x);
            d[1] = pack_h2(rb0[j].y, rb1[j].y);
            d[2] = pack_h2(rb0[j].z, rb1[j].z);
            d[3] = pack_h2(rb0[j].w, rb1[j].w);
        }
    }
    __syncthreads();

    float acc[4][4][4];
#pragma unroll
    for (int i = 0; i < 4; ++i)
#pragma unroll
        for (int j = 0; j < 4; ++j)
#pragma unroll
            for (int e = 0; e < 4; ++e) acc[i][j][e] = 0.f;

#pragma unroll 1
    for (int ch = 0; ch < 8; ++ch) {
        if (ch < 7) {
            const int k0 = (ch + 1) * 32;
#pragma unroll
            for (int j = 0; j < 4; ++j)
                ra[j] = *(const float4*)(W + (size_t)(m0 + a_row[j]) * DIMC + k0 + a_q * 4);
#pragma unroll
            for (int j = 0; j < 2; ++j) {
                rb0[j] = *(const float4*)(Xb + (size_t)(k0 + 2 * b_k2[j])     * NSP + n0 + b_n4);
                rb1[j] = *(const float4*)(Xb + (size_t)(k0 + 2 * b_k2[j] + 1) * NSP + n0 + b_n4);
            }
        }
        const uint32_t* Ab = As + (ch & 1) * 128 * QA_LD;
        const uint32_t* Bb = Bs + (ch & 1) * 16 * QB_LD;
#pragma unroll
        for (int ks2 = 0; ks2 < 16; ks2 += 8) {
            uint32_t af[4][4], bf[4][2];
#pragma unroll
            for (int i = 0; i < 4; ++i) {
                int r = wm * 64 + i * 16;
                af[i][0] = Ab[(r + g)     * QA_LD + ks2 + tg];
                af[i][1] = Ab[(r + g + 8) * QA_LD + ks2 + tg];
                af[i][2] = Ab[(r + g)     * QA_LD + ks2 + tg + 4];
                af[i][3] = Ab[(r + g + 8) * QA_LD + ks2 + tg + 4];
            }
#pragma unroll
            for (int jn = 0; jn < 4; ++jn) {
                int c = wn * 32 + jn * 8 + g;
                bf[jn][0] = Bb[(ks2 + tg)     * QB_LD + c];
                bf[jn][1] = Bb[(ks2 + tg + 4) * QB_LD + c];
            }
#pragma unroll
            for (int i = 0; i < 4; ++i)
#pragma unroll
                for (int jn = 0; jn < 4; ++jn)
                    mma_f16(acc[i][jn], af[i], bf[jn]);
        }
        if (ch < 7) {
            uint32_t* An = As + ((ch + 1) & 1) * 128 * QA_LD;
            uint32_t* Bn = Bs + ((ch + 1) & 1) * 16 * QB_LD;
#pragma unroll
            for (int j = 0; j < 4; ++j) {
                uint32_t* d = &An[a_row[j] * QA_LD + a_q * 2];
                d[0] = pack_h2(ra[j].x, ra[j].y);
                d[1] = pack_h2(ra[j].z, ra[j].w);
            }
#pragma unroll
            for (int j = 0; j < 2; ++j) {
                uint32_t* d = &Bn[b_k2[j] * QB_LD + b_n4];
                d[0] = pack_h2(rb0[j].x, rb1[j].x);
                d[1] = pack_h2(rb0[j].y, rb1[j].y);
                d[2] = pack_h2(rb0[j].z, rb1[j].z);
                d[3] = pack_h2(rb0[j].w, rb1[j].w);
            }
            __syncthreads();
        }
    }

    // Fused q softmax (m-block 0 only)
    if (m0 == 0) {
#pragma unroll
        for (int jn = 0; jn < 4; ++jn)
#pragma unroll
            for (int e = 0; e < 2; ++e)
#pragma unroll
                for (int hd = 0; hd < 2; ++hd) {
                    const int ib = hd * 2;
                    float v0 = acc[ib][jn][e],     v1 = acc[ib][jn][2 + e];
                    float v2 = acc[ib + 1][jn][e], v3 = acc[ib + 1][jn][2 + e];
                    float m = fmaxf(fmaxf(v0, v1), fmaxf(v2, v3));
#pragma unroll
                    for (int off = 4; off < 32; off <<= 1)
                        m = fmaxf(m, __shfl_xor_sync(0xffffffffu, m, off));
                    v0 = __expf(v0 - m); v1 = __expf(v1 - m);
                    v2 = __expf(v2 - m); v3 = __expf(v3 - m);
                    float s = (v0 + v1) + (v2 + v3);
#pragma unroll
                    for (int off = 4; off < 32; off <<= 1)
                        s += __shfl_xor_sync(0xffffffffu, s, off);
                    float inv = SCALE / s;
                    acc[ib][jn][e]         = v0 * inv;
                    acc[ib][jn][2 + e]     = v1 * inv;
                    acc[ib + 1][jn][e]     = v2 * inv;
                    acc[ib + 1][jn][2 + e] = v3 * inv;
                }
    }

    // Epilogue
    if (m0 < 256) {
        // q or k -> half store into g_qk rows [m0 .. m0+128)
        __half* Ch = g_qk + (size_t)b * (2 * HID) * NSP;
#pragma unroll
        for (int i = 0; i < 4; ++i) {
            int r0 = m0 + wm * 64 + i * 16 + g;
#pragma unroll
            for (int jn = 0; jn < 4; ++jn) {
                int c = n0 + wn * 32 + jn * 8 + tg * 2;
                *(uint32_t*)&Ch[(size_t)r0 * NSP + c] =
                    pack_h2(acc[i][jn][0], acc[i][jn][1]);
                *(uint32_t*)&Ch[(size_t)(r0 + 8) * NSP + c] =
                    pack_h2(acc[i][jn][2], acc[i][jn][3]);
            }
        }
    } else {
        // v -> float store into g_v rows [0,128)
        float* Cv = g_v + (size_t)b * HID * NSP;
#pragma unroll
        for (int i = 0; i < 4; ++i) {
            int r0 = (m0 - 256) + wm * 64 + i * 16 + g;
#pragma unroll
            for (int jn = 0; jn < 4; ++jn) {
                int c = n0 + wn * 32 + jn * 8 + tg * 2;
                *(float2*)&Cv[(size_t)r0 * NSP + c] =
                    make_float2(acc[i][jn][0], acc[i][jn][1]);
                *(float2*)&Cv[(size_t)(r0 + 8) * NSP + c] =
                    make_float2(acc[i][jn][2], acc[i][jn][3]);
            }
        }
    }
}

// ---------------------------------------------------------------------------
// Kernel 3: k softmax over n, fp16 in/out (rows [128,256) of g_qk).
// ---------------------------------------------------------------------------
__global__ __launch_bounds__(256) void k_softmax() {
    __shared__ float buf[NSP];
    __shared__ float red[256];
    int row = blockIdx.x;
    int b = row >> 7, r = row & 127;
    __half2* base2 = (__half2*)(g_qk + ((size_t)b * (2 * HID) + HID + r) * NSP);
    int tid = threadIdx.x;

    float mx = -1e30f;
    for (int i = tid; i < NSP / 2; i += 256) {
        float2 f = __half22float2(base2[i]);
        buf[2 * i] = f.x; buf[2 * i + 1] = f.y;
        mx = fmaxf(mx, fmaxf(f.x, f.y));
    }
    red[tid] = mx; __syncthreads();
    for (int s = 128; s > 0; s >>= 1) {
        if (tid < s) red[tid] = fmaxf(red[tid], red[tid + s]);
        __syncthreads();
    }
    mx = red[0]; __syncthreads();

    float sum = 0.f;
    for (int i = tid; i < NSP; i += 256) { float e = __expf(buf[i] - mx); buf[i] = e; sum += e; }
    red[tid] = sum; __syncthreads();
    for (int s = 128; s > 0; s >>= 1) {
        if (tid < s) red[tid] += red[tid + s];
        __syncthreads();
    }
    float inv = 1.0f / red[0];
    __syncthreads();
    for (int i = tid; i < NSP / 2; i += 256)
        base2[i] = __floats2half2_rn(buf[2 * i] * inv, buf[2 * i + 1] * inv);
}

// ---------------------------------------------------------------------------
// Kernel 4: context partials. k from g_qk (half), v from g_v (float).
// ---------------------------------------------------------------------------
__global__ __launch_bounds__(256) void ctx_slice() {
    __shared__ float Ks[4][32][33];
    __shared__ float Vs[4][32][33];
    __shared__ float racc[3][64][16];
    int bh = blockIdx.x;
    int sl = blockIdx.y;
    int b = bh >> 2, h = bh & 3;
    const __half* kbase = g_qk + ((size_t)b * (2 * HID) + HID + h * DH) * NSP;
    const float*  vbase = g_v  + ((size_t)b * HID + h * DH) * NSP;

    int tid = threadIdx.x;
    int grp = tid >> 6;
    int t   = tid & 63;
    int td = t >> 3, te = t & 7;

    float acc[4][4];
#pragma unroll
    for (int i = 0; i < 4; i++)
#pragma unroll
        for (int j = 0; j < 4; j++) acc[i][j] = 0.f;

    const int base_n = sl * (NSP / NSLICE) + grp * 128;
#pragma unroll 1
    for (int cc = 0; cc < 128; cc += 32) {
        int c0 = base_n + cc;
#pragma unroll
        for (int m = 0; m < 4; m++) {
            int fi = m * 64 + t;
            int dd = fi >> 3;
            int nn = (fi & 7) * 4;
            uint2 kw = *(const uint2*)&kbase[(size_t)dd * NSP + c0 + nn];
            float2 k01 = __half22float2(*(__half2*)&kw.x);
            float2 k23 = __half22float2(*(__half2*)&kw.y);
            float4 vv = *(const float4*)&vbase[(size_t)dd * NSP + c0 + nn];
            Ks[grp][dd][nn+0] = k01.x; Ks[grp][dd][nn+1] = k01.y;
            Ks[grp][dd][nn+2] = k23.x; Ks[grp][dd][nn+3] = k23.y;
            Vs[grp][dd][nn+0] = vv.x; Vs[grp][dd][nn+1] = vv.y;
            Vs[grp][dd][nn+2] = vv.z; Vs[grp][dd][nn+3] = vv.w;
        }
        __syncthreads();
#pragma unroll 4
        for (int n = 0; n < 32; n++) {
            float ka[4], vb[4];
#pragma unroll
            for (int i = 0; i < 4; i++) ka[i] = Ks[grp][td * 4 + i][n];
#pragma unroll
            for (int j = 0; j < 4; j++) vb[j] = Vs[grp][te * 4 + j][n];
#pragma unroll
            for (int i = 0; i < 4; i++)
#pragma unroll
                for (int j = 0; j < 4; j++) acc[i][j] += ka[i] * vb[j];
        }
        __syncthreads();
    }

    if (grp > 0) {
#pragma unroll
        for (int i = 0; i < 4; i++)
#pragma unroll
            for (int j = 0; j < 4; j++) racc[grp - 1][t][i * 4 + j] = acc[i][j];
    }
    __syncthreads();
    if (grp == 0) {
#pragma unroll
        for (int gg = 0; gg < 3; gg++)
#pragma unroll
            for (int i = 0; i < 4; i++)
#pragma unroll
                for (int j = 0; j < 4; j++) acc[i][j] += racc[gg][t][i * 4 + j];
        float* dst = g_ctxp + ((size_t)sl * NB * HEADS + bh) * (DH * DH);
#pragma unroll
        for (int i = 0; i < 4; i++)
#pragma unroll
            for (int j = 0; j < 4; j++)
                dst[(td * 4 + i) * DH + te * 4 + j] = acc[i][j];
    }
}

// ---------------------------------------------------------------------------
// Kernel 5: fused weight Wf -> half. Grid (NB*HEADS, 2): o split in halves.
// ---------------------------------------------------------------------------
__global__ __launch_bounds__(256) void wf_kernel(const float* __restrict__ w_out) {
    __shared__ float cs[DH][DH];          // 4 KB
    __shared__ float ws[128][DH + 1];     // 16.9 KB
    const int bh = blockIdx.x;
    const int o0 = blockIdx.y * 128;
    const int b = bh >> 2, h = bh & 3;
    const int tid = threadIdx.x;

    {
        const size_t ss = (size_t)NB * HEADS * DH * DH;
        const size_t base = (size_t)bh * DH * DH;
        for (int i = tid; i < DH * DH; i += 256) {
            float s = 0.f;
#pragma unroll
            for (int sl = 0; sl < NSLICE; ++sl)
                s += g_ctxp[sl * ss + base + i];
            ((float*)cs)[i] = s;
        }
    }
    // Stage w_out[o0..o0+128, h*32..h*32+31]: 128 rows x 8 float4 = 1024 tasks
#pragma unroll
    for (int it = 0; it < 4; ++it) {
        int idx = it * 256 + tid;
        int row = idx >> 3, e4 = idx & 7;
        float4 v = *(const float4*)&w_out[(o0 + row) * HID + h * DH + e4 * 4];
        ws[row][e4 * 4 + 0] = v.x; ws[row][e4 * 4 + 1] = v.y;
        ws[row][e4 * 4 + 2] = v.z; ws[row][e4 * 4 + 3] = v.w;
    }
    __syncthreads();

    if (tid < 128) {
        const int o = o0 + tid;
        float w[DH];
#pragma unroll
        for (int e = 0; e < DH; ++e) w[e] = ws[tid][e];

        __half* dst = g_wf + ((size_t)b * DIMC + o) * HID + h * DH;
#pragma unroll 4
        for (int d = 0; d < DH; d += 4) {
            float s0 = 0.f, s1 = 0.f, s2 = 0.f, s3 = 0.f;
#pragma unroll
            for (int e = 0; e < DH; ++e) {
                float we = w[e];
                s0 += we * cs[d + 0][e];
                s1 += we * cs[d + 1][e];
                s2 += we * cs[d + 2][e];
                s3 += we * cs[d + 3][e];
            }
            uint2 r;
            r.x = pack_h2(s0, s1);
            r.y = pack_h2(s2, s3);
            *(uint2*)&dst[d] = r;
        }
    }
}

// ---------------------------------------------------------------------------
// Kernel 6 (fp16 mma + fused LN): out[b,o,n] = Wf[b]·q[b] + b_out, LN over o.
// A (Wf) is fp16 in memory with layout == fragment layout: raw 8B copies.
// ---------------------------------------------------------------------------
#define OA_LD 20
#define OB_LD 72
#define OUT_DYN ((256 * OA_LD + 16 * OB_LD) * 4)   // 25088 bytes

__global__ __launch_bounds__(256) void out_ln_mma(const float* __restrict__ b_out,
                                                  const float* __restrict__ gamma,
                                                  const float* __restrict__ beta,
                                                  float* __restrict__ out) {
    extern __shared__ uint32_t dynbuf[];
    uint32_t* As = dynbuf;                 // 256 x OA_LD
    uint32_t* Bs = dynbuf + 256 * OA_LD;   // 16 x OB_LD
    __shared__ float s_sum[4][64];
    __shared__ float s_sq [4][64];
    __shared__ float s_mean[64], s_rstd[64];

    const int b  = blockIdx.y;
    const int n0 = blockIdx.x * 64;
    const __half* A = g_wf + (size_t)b * DIMC * HID;       // 256 x 128 half
    const __half* Q = g_qk + (size_t)b * (2 * HID) * NSP;  // rows [0,128): q half

    const int tid = threadIdx.x, wid = tid >> 5, lane = tid & 31;
    const int wm = wid >> 1, wn = wid & 1;    // 4 x 2 warps
    const int g = lane >> 2, tg = lane & 3;

    float acc[4][4][4];
#pragma unroll
    for (int i = 0; i < 4; ++i)
#pragma unroll
        for (int j = 0; j < 4; ++j)
#pragma unroll
            for (int e = 0; e < 4; ++e) acc[i][j][e] = 0.f;

#pragma unroll 1
    for (int k0 = 0; k0 < HID; k0 += 32) {
        // A: raw uint2 copies (memory layout == half2-over-k fragment layout)
#pragma unroll
        for (int j = 0; j < 8; ++j) {
            int fi = j * 256 + tid;                 // 2048 uint2 tasks
            int row = fi >> 3, q = fi & 7;
            uint2 v = *(const uint2*)(A + (size_t)row * HID + k0 + q * 4);
            uint32_t* d = &As[row * OA_LD + q * 2];
            d[0] = v.x; d[1] = v.y;
        }
        // B: q half rows (k even, k odd) interleave
        {
            int k2 = tid >> 4, n4 = (tid & 15) * 4;
            uint2 q0 = *(const uint2*)(Q + (size_t)(k0 + 2 * k2)     * NSP + n0 + n4);
            uint2 q1 = *(const uint2*)(Q + (size_t)(k0 + 2 * k2 + 1) * NSP + n0 + n4);
            __half2 e01 = *(__half2*)&q0.x, e23 = *(__half2*)&q0.y;
            __half2 o01 = *(__half2*)&q1.x, o23 = *(__half2*)&q1.y;
            __half2 p0 = __lows2half2 (e01, o01);
            __half2 p1 = __highs2half2(e01, o01);
            __half2 p2 = __lows2half2 (e23, o23);
            __half2 p3 = __highs2half2(e23, o23);
            uint32_t* d = &Bs[k2 * OB_LD + n4];
            d[0] = *(uint32_t*)&p0;
            d[1] = *(uint32_t*)&p1;
            d[2] = *(uint32_t*)&p2;
            d[3] = *(uint32_t*)&p3;
        }
        __syncthreads();

#pragma unroll
        for (int ks2 = 0; ks2 < 16; ks2 += 8) {
            uint32_t af[4][4], bf[4][2];
#pragma unroll
            for (int i = 0; i < 4; ++i) {
                int r = wm * 64 + i * 16;
                af[i][0] = As[(r + g)     * OA_LD + ks2 + tg];
                af[i][1] = As[(r + g + 8) * OA_LD + ks2 + tg];
                af[i][2] = As[(r + g)     * OA_LD + ks2 + tg + 4];
                af[i][3] = As[(r + g + 8) * OA_LD + ks2 + tg + 4];
            }
#pragma unroll
            for (int jn = 0; jn < 4; ++jn) {
                int c = wn * 32 + jn * 8 + g;
                bf[jn][0] = Bs[(ks2 + tg)     * OB_LD + c];
                bf[jn][1] = Bs[(ks2 + tg + 4) * OB_LD + c];
            }
#pragma unroll
            for (int i = 0; i < 4; ++i)
#pragma unroll
                for (int jn = 0; jn < 4; ++jn)
                    mma_f16(acc[i][jn], af[i], bf[jn]);
        }
        __syncthreads();
    }

    // Add bias into accumulators
#pragma unroll
    for (int i = 0; i < 4; ++i) {
        float bo0 = b_out[wm * 64 + i * 16 + g];
        float bo1 = b_out[wm * 64 + i * 16 + g + 8];
#pragma unroll
        for (int jn = 0; jn < 4; ++jn) {
            acc[i][jn][0] += bo0; acc[i][jn][1] += bo0;
            acc[i][jn][2] += bo1; acc[i][jn][3] += bo1;
        }
    }

    // Per-column (n) stats over the 256 channels.
    float ps[8], pq[8];
#pragma unroll
    for (int c = 0; c < 8; ++c) { ps[c] = 0.f; pq[c] = 0.f; }
#pragma unroll
    for (int i = 0; i < 4; ++i)
#pragma unroll
        for (int jn = 0; jn < 4; ++jn)
#pragma unroll
            for (int e = 0; e < 2; ++e) {
                float v0 = acc[i][jn][e];
                float v1 = acc[i][jn][2 + e];
                ps[jn * 2 + e] += v0 + v1;
                pq[jn * 2 + e] += v0 * v0 + v1 * v1;
            }
#pragma unroll
    for (int c = 0; c < 8; ++c) {
#pragma unroll
        for (int off = 4; off < 32; off <<= 1) {
            ps[c] += __shfl_xor_sync(0xffffffffu, ps[c], off);
            pq[c] += __shfl_xor_sync(0xffffffffu, pq[c], off);
        }
    }
    if (g == 0) {
#pragma unroll
        for (int jn = 0; jn < 4; ++jn)
#pragma unroll
            for (int e = 0; e < 2; ++e) {
                int col = wn * 32 + jn * 8 + tg * 2 + e;
                s_sum[wm][col] = ps[jn * 2 + e];
                s_sq [wm][col] = pq[jn * 2 + e];
            }
    }
    __syncthreads();
    if (tid < 64) {
        float s = s_sum[0][tid] + s_sum[1][tid] + s_sum[2][tid] + s_sum[3][tid];
        float q = s_sq [0][tid] + s_sq [1][tid] + s_sq [2][tid] + s_sq [3][tid];
        float mean = s * (1.0f / 256.0f);
        float var  = q * (1.0f / 256.0f) - mean * mean;
        s_mean[tid] = mean;
        s_rstd[tid] = rsqrtf(var + EPS);
    }
    __syncthreads();

    // Normalize + store
#pragma unroll
    for (int i = 0; i < 4; ++i) {
        int o0 = wm * 64 + i * 16 + g;
        float g0 = gamma[o0], b0v = beta[o0];
        float g1 = gamma[o0 + 8], b1v = beta[o0 + 8];
#pragma unroll
        for (int jn = 0; jn < 4; ++jn) {
            int cl = wn * 32 + jn * 8 + tg * 2;
            float m0 = s_mean[cl],     r0 = s_rstd[cl];
            float m1 = s_mean[cl + 1], r1 = s_rstd[cl + 1];
            *(float2*)&out[((size_t)b * DIMC + o0) * NSP + n0 + cl] =
                make_float2((acc[i][jn][0] - m0) * r0 * g0 + b0v,
                            (acc[i][jn][1] - m1) * r1 * g0 + b0v);
            *(float2*)&out[((size_t)b * DIMC + o0 + 8) * NSP + n0 + cl] =
                make_float2((acc[i][jn][2] - m0) * r0 * g1 + b1v,
                            (acc[i][jn][3] - m1) * r1 * g1 + b1v);
        }
    }
}

// ---------------------------------------------------------------------------
extern "C" void kernel_launch(void* const* d_in, const int* in_sizes, int n_in,
                              void* d_out, int out_size) {
    const float* x     = (const float*)d_in[0];
    const float* w_qkv = (const float*)d_in[1];
    const float* w_out = (const float*)d_in[2];
    const float* b_out = (const float*)d_in[3];
    const float* g     = (const float*)d_in[4];
    const float* bb    = (const float*)d_in[5];
    float* out = (float*)d_out;

    qkv_mma<<<dim3(NSP / 128, THREE / 128, NB), 256, QKV_DYN>>>(w_qkv, x);
    k_softmax<<<NB * HID, 256>>>();
    ctx_slice<<<dim3(NB * HEADS, NSLICE), 256>>>();
    wf_kernel<<<dim3(NB * HEADS, 2), 256>>>(w_out);
    out_ln_mma<<<dim3(NSP / 64, NB), 256, OUT_DYN>>>(b_out, g, bb, out);
}

// round 14
// speedup vs baseline: 4.0970x; 1.0193x over previous
#include <cuda_runtime.h>
#include <cuda_bf16.h>
#include <cuda_fp16.h>
#include <math.h>
#include <stdint.h>

// Problem constants
#define NB    32
#define DIMC  256
#define HEADS 4
#define DH    32
#define HID   128      // HEADS*DH
#define THREE 384      // 3*HID
#define NSP   4096     // 64*64 spatial
#define SCALE 0.17677669529663687f  // 32^-0.5
#define EPS   1e-5f
#define NSLICE 8       // ctx n-split

// Scratch (device globals)
__device__ __half g_qk [(size_t)NB * 2 * HID * NSP];             // q rows [0,128), k rows [128,256)
__device__ float  g_v  [(size_t)NB * HID * NSP];                 // 67 MB
__device__ float  g_ctxp[(size_t)NSLICE * NB * HEADS * DH * DH]; // 4 MB
__device__ __half g_wf [(size_t)NB * DIMC * HID];                // 2 MB

// ---------------------------------------------------------------------------
// Helpers
// ---------------------------------------------------------------------------
__device__ __forceinline__ uint32_t pack_h2(float lo, float hi) {
    __half2 h = __floats2half2_rn(lo, hi);
    return *(uint32_t*)&h;
}
__device__ __forceinline__ uint32_t smem_u32(const void* p) {
    uint32_t a;
    asm("{ .reg .u64 t; cvta.to.shared.u64 t, %1; cvt.u32.u64 %0, t; }"
        : "=r"(a) : "l"(p));
    return a;
}
__device__ __forceinline__ void mma_f16(float* d, const uint32_t* a, const uint32_t* b) {
    asm volatile(
        "mma.sync.aligned.m16n8k16.row.col.f32.f16.f16.f32 "
        "{%0,%1,%2,%3}, {%4,%5,%6,%7}, {%8,%9}, {%0,%1,%2,%3};\n"
        : "+f"(d[0]), "+f"(d[1]), "+f"(d[2]), "+f"(d[3])
        : "r"(a[0]), "r"(a[1]), "r"(a[2]), "r"(a[3]), "r"(b[0]), "r"(b[1]));
}
__device__ __forceinline__ void ldsm_x4(uint32_t* r, uint32_t addr) {
    asm volatile("ldmatrix.sync.aligned.m8n8.x4.shared.b16 {%0,%1,%2,%3}, [%4];"
        : "=r"(r[0]), "=r"(r[1]), "=r"(r[2]), "=r"(r[3]) : "r"(addr));
}
__device__ __forceinline__ void ldsm_x4_t(uint32_t* r, uint32_t addr) {
    asm volatile("ldmatrix.sync.aligned.m8n8.x4.trans.shared.b16 {%0,%1,%2,%3}, [%4];"
        : "=r"(r[0]), "=r"(r[1]), "=r"(r[2]), "=r"(r[3]) : "r"(addr));
}

// A smem: [row][k halves contiguous], pitch 20 words (80 B) -> ldmatrix-clean
// B smem (qkv): [k][n halves], pitch 68 words (272 B)       -> ldmatrix.trans-clean
#define QA_LD 20
#define QB_LDW 68                 // words per k-row
#define QA_BUF (128 * QA_LD)      // words per A buffer
#define QB_BUF (32 * QB_LDW)      // words per B buffer
#define QKV_DYN ((2 * QA_BUF + 2 * QB_BUF) * 4)   // 37888 bytes

// ---------------------------------------------------------------------------
// Kernel 1 (fp16 mma + ldmatrix, double-buffered): qkv = W * X
// CTA 128x128, BK=32, 8 warps (2M x 4N). m-block 0 fuses q-softmax.
// ---------------------------------------------------------------------------
__global__ __launch_bounds__(256) void qkv_mma(const float* __restrict__ W,
                                               const float* __restrict__ X) {
    extern __shared__ uint32_t qbuf[];
    uint32_t* As = qbuf;                 // 2 x QA_BUF
    uint32_t* Bs = qbuf + 2 * QA_BUF;    // 2 x QB_BUF

    const int b  = blockIdx.z;
    const int m0 = blockIdx.y * 128;
    const int n0 = blockIdx.x * 128;
    const float* Xb = X + (size_t)b * DIMC * NSP;

    const int tid = threadIdx.x, wid = tid >> 5, lane = tid & 31;
    const int wm = wid >> 2, wn = wid & 3;     // 2 x 4 warps
    const int g = lane >> 2, tg = lane & 3;

    const uint32_t As_u = smem_u32(As);
    const uint32_t Bs_u = smem_u32(Bs);
    // ldmatrix per-lane offsets
    const int lrow = (lane & 7) + (lane & 8);
    const uint32_t aOff = As_u + (uint32_t)(lrow * 80 + (lane >> 4) * 16)
                        + (uint32_t)(wm * 64 * 80);
    const uint32_t bOff = Bs_u + (uint32_t)(lrow * 272 + (lane >> 4) * 16)
                        + (uint32_t)(wn * 64);

    // Staging coordinates
    const int a_row[4] = { (0 * 256 + tid) >> 3, (1 * 256 + tid) >> 3,
                           (2 * 256 + tid) >> 3, (3 * 256 + tid) >> 3 };
    const int a_q = tid & 7;
    const int bt_k[4] = { (0 * 256 + tid) >> 5, (1 * 256 + tid) >> 5,
                          (2 * 256 + tid) >> 5, (3 * 256 + tid) >> 5 };
    const int bt_n4 = (tid & 31) * 4;

    float4 ra[4], rb[4];
#pragma unroll
    for (int j = 0; j < 4; ++j)
        ra[j] = *(const float4*)(W + (size_t)(m0 + a_row[j]) * DIMC + a_q * 4);
#pragma unroll
    for (int j = 0; j < 4; ++j)
        rb[j] = *(const float4*)(Xb + (size_t)bt_k[j] * NSP + n0 + bt_n4);
    {
#pragma unroll
        for (int j = 0; j < 4; ++j) {
            uint32_t* d = &As[a_row[j] * QA_LD + a_q * 2];
            d[0] = pack_h2(ra[j].x, ra[j].y);
            d[1] = pack_h2(ra[j].z, ra[j].w);
        }
#pragma unroll
        for (int j = 0; j < 4; ++j) {
            uint32_t* d = &Bs[bt_k[j] * QB_LDW + bt_n4 / 2];
            d[0] = pack_h2(rb[j].x, rb[j].y);
            d[1] = pack_h2(rb[j].z, rb[j].w);
        }
    }
    __syncthreads();

    float acc[4][4][4];
#pragma unroll
    for (int i = 0; i < 4; ++i)
#pragma unroll
        for (int j = 0; j < 4; ++j)
#pragma unroll
            for (int e = 0; e < 4; ++e) acc[i][j][e] = 0.f;

#pragma unroll 1
    for (int ch = 0; ch < 8; ++ch) {
        if (ch < 7) {
            const int k0 = (ch + 1) * 32;
#pragma unroll
            for (int j = 0; j < 4; ++j)
                ra[j] = *(const float4*)(W + (size_t)(m0 + a_row[j]) * DIMC + k0 + a_q * 4);
#pragma unroll
            for (int j = 0; j < 4; ++j)
                rb[j] = *(const float4*)(Xb + (size_t)(k0 + bt_k[j]) * NSP + n0 + bt_n4);
        }
        const uint32_t aB = aOff + (uint32_t)((ch & 1) * QA_BUF * 4);
        const uint32_t bB = bOff + (uint32_t)((ch & 1) * QB_BUF * 4);
#pragma unroll
        for (int ks2 = 0; ks2 < 2; ++ks2) {
            uint32_t af[4][4], bf[4][2];
#pragma unroll
            for (int i = 0; i < 4; ++i)
                ldsm_x4(af[i], aB + (uint32_t)(i * 16 * 80 + ks2 * 32));
            {
                uint32_t t[4];
                ldsm_x4_t(t, bB + (uint32_t)(ks2 * 16 * 272));
                bf[0][0] = t[0]; bf[0][1] = t[1]; bf[1][0] = t[2]; bf[1][1] = t[3];
                ldsm_x4_t(t, bB + (uint32_t)(ks2 * 16 * 272 + 32));
                bf[2][0] = t[0]; bf[2][1] = t[1]; bf[3][0] = t[2]; bf[3][1] = t[3];
            }
#pragma unroll
            for (int i = 0; i < 4; ++i)
#pragma unroll
                for (int jn = 0; jn < 4; ++jn)
                    mma_f16(acc[i][jn], af[i], bf[jn]);
        }
        if (ch < 7) {
            uint32_t* An = As + ((ch + 1) & 1) * QA_BUF;
            uint32_t* Bn = Bs + ((ch + 1) & 1) * QB_BUF;
#pragma unroll
            for (int j = 0; j < 4; ++j) {
                uint32_t* d = &An[a_row[j] * QA_LD + a_q * 2];
                d[0] = pack_h2(ra[j].x, ra[j].y);
                d[1] = pack_h2(ra[j].z, ra[j].w);
            }
#pragma unroll
            for (int j = 0; j < 4; ++j) {
                uint32_t* d = &Bn[bt_k[j] * QB_LDW + bt_n4 / 2];
                d[0] = pack_h2(rb[j].x, rb[j].y);
                d[1] = pack_h2(rb[j].z, rb[j].w);
            }
            __syncthreads();
        }
    }

    // Fused q softmax (m-block 0 only)
    if (m0 == 0) {
#pragma unroll
        for (int jn = 0; jn < 4; ++jn)
#pragma unroll
            for (int e = 0; e < 2; ++e)
#pragma unroll
                for (int hd = 0; hd < 2; ++hd) {
                    const int ib = hd * 2;
                    float v0 = acc[ib][jn][e],     v1 = acc[ib][jn][2 + e];
                    float v2 = acc[ib + 1][jn][e], v3 = acc[ib + 1][jn][2 + e];
                    float m = fmaxf(fmaxf(v0, v1), fmaxf(v2, v3));
#pragma unroll
                    for (int off = 4; off < 32; off <<= 1)
                        m = fmaxf(m, __shfl_xor_sync(0xffffffffu, m, off));
                    v0 = __expf(v0 - m); v1 = __expf(v1 - m);
                    v2 = __expf(v2 - m); v3 = __expf(v3 - m);
                    float s = (v0 + v1) + (v2 + v3);
#pragma unroll
                    for (int off = 4; off < 32; off <<= 1)
                        s += __shfl_xor_sync(0xffffffffu, s, off);
                    float inv = SCALE / s;
                    acc[ib][jn][e]         = v0 * inv;
                    acc[ib][jn][2 + e]     = v1 * inv;
                    acc[ib + 1][jn][e]     = v2 * inv;
                    acc[ib + 1][jn][2 + e] = v3 * inv;
                }
    }

    // Epilogue
    if (m0 < 256) {
        __half* Ch = g_qk + (size_t)b * (2 * HID) * NSP;
#pragma unroll
        for (int i = 0; i < 4; ++i) {
            int r0 = m0 + wm * 64 + i * 16 + g;
#pragma unroll
            for (int jn = 0; jn < 4; ++jn) {
                int c = n0 + wn * 32 + jn * 8 + tg * 2;
                *(uint32_t*)&Ch[(size_t)r0 * NSP + c] =
                    pack_h2(acc[i][jn][0], acc[i][jn][1]);
                *(uint32_t*)&Ch[(size_t)(r0 + 8) * NSP + c] =
                    pack_h2(acc[i][jn][2], acc[i][jn][3]);
            }
        }
    } else {
        float* Cv = g_v + (size_t)b * HID * NSP;
#pragma unroll
        for (int i = 0; i < 4; ++i) {
            int r0 = (m0 - 256) + wm * 64 + i * 16 + g;
#pragma unroll
            for (int jn = 0; jn < 4; ++jn) {
                int c = n0 + wn * 32 + jn * 8 + tg * 2;
                *(float2*)&Cv[(size_t)r0 * NSP + c] =
                    make_float2(acc[i][jn][0], acc[i][jn][1]);
                *(float2*)&Cv[(size_t)(r0 + 8) * NSP + c] =
                    make_float2(acc[i][jn][2], acc[i][jn][3]);
            }
        }
    }
}

// ---------------------------------------------------------------------------
// Kernel 3: k softmax over n, fp16 in/out (rows [128,256) of g_qk).
// ---------------------------------------------------------------------------
__global__ __launch_bounds__(256) void k_softmax() {
    __shared__ float buf[NSP];
    __shared__ float red[256];
    int row = blockIdx.x;
    int b = row >> 7, r = row & 127;
    __half2* base2 = (__half2*)(g_qk + ((size_t)b * (2 * HID) + HID + r) * NSP);
    int tid = threadIdx.x;

    float mx = -1e30f;
    for (int i = tid; i < NSP / 2; i += 256) {
        float2 f = __half22float2(base2[i]);
        buf[2 * i] = f.x; buf[2 * i + 1] = f.y;
        mx = fmaxf(mx, fmaxf(f.x, f.y));
    }
    red[tid] = mx; __syncthreads();
    for (int s = 128; s > 0; s >>= 1) {
        if (tid < s) red[tid] = fmaxf(red[tid], red[tid + s]);
        __syncthreads();
    }
    mx = red[0]; __syncthreads();

    float sum = 0.f;
    for (int i = tid; i < NSP; i += 256) { float e = __expf(buf[i] - mx); buf[i] = e; sum += e; }
    red[tid] = sum; __syncthreads();
    for (int s = 128; s > 0; s >>= 1) {
        if (tid < s) red[tid] += red[tid + s];
        __syncthreads();
    }
    float inv = 1.0f / red[0];
    __syncthreads();
    for (int i = tid; i < NSP / 2; i += 256)
        base2[i] = __floats2half2_rn(buf[2 * i] * inv, buf[2 * i + 1] * inv);
}

// ---------------------------------------------------------------------------
// Kernel 4: context partials. k from g_qk (half), v from g_v (float).
// ---------------------------------------------------------------------------
__global__ __launch_bounds__(256) void ctx_slice() {
    __shared__ float Ks[4][32][33];
    __shared__ float Vs[4][32][33];
    __shared__ float racc[3][64][16];
    int bh = blockIdx.x;
    int sl = blockIdx.y;
    int b = bh >> 2, h = bh & 3;
    const __half* kbase = g_qk + ((size_t)b * (2 * HID) + HID + h * DH) * NSP;
    const float*  vbase = g_v  + ((size_t)b * HID + h * DH) * NSP;

    int tid = threadIdx.x;
    int grp = tid >> 6;
    int t   = tid & 63;
    int td = t >> 3, te = t & 7;

    float acc[4][4];
#pragma unroll
    for (int i = 0; i < 4; i++)
#pragma unroll
        for (int j = 0; j < 4; j++) acc[i][j] = 0.f;

    const int base_n = sl * (NSP / NSLICE) + grp * 128;
#pragma unroll 1
    for (int cc = 0; cc < 128; cc += 32) {
        int c0 = base_n + cc;
#pragma unroll
        for (int m = 0; m < 4; m++) {
            int fi = m * 64 + t;
            int dd = fi >> 3;
            int nn = (fi & 7) * 4;
            uint2 kw = *(const uint2*)&kbase[(size_t)dd * NSP + c0 + nn];
            float2 k01 = __half22float2(*(__half2*)&kw.x);
            float2 k23 = __half22float2(*(__half2*)&kw.y);
            float4 vv = *(const float4*)&vbase[(size_t)dd * NSP + c0 + nn];
            Ks[grp][dd][nn+0] = k01.x; Ks[grp][dd][nn+1] = k01.y;
            Ks[grp][dd][nn+2] = k23.x; Ks[grp][dd][nn+3] = k23.y;
            Vs[grp][dd][nn+0] = vv.x; Vs[grp][dd][nn+1] = vv.y;
            Vs[grp][dd][nn+2] = vv.z; Vs[grp][dd][nn+3] = vv.w;
        }
        __syncthreads();
#pragma unroll 4
        for (int n = 0; n < 32; n++) {
            float ka[4], vb[4];
#pragma unroll
            for (int i = 0; i < 4; i++) ka[i] = Ks[grp][td * 4 + i][n];
#pragma unroll
            for (int j = 0; j < 4; j++) vb[j] = Vs[grp][te * 4 + j][n];
#pragma unroll
            for (int i = 0; i < 4; i++)
#pragma unroll
                for (int j = 0; j < 4; j++) acc[i][j] += ka[i] * vb[j];
        }
        __syncthreads();
    }

    if (grp > 0) {
#pragma unroll
        for (int i = 0; i < 4; i++)
#pragma unroll
            for (int j = 0; j < 4; j++) racc[grp - 1][t][i * 4 + j] = acc[i][j];
    }
    __syncthreads();
    if (grp == 0) {
#pragma unroll
        for (int gg = 0; gg < 3; gg++)
#pragma unroll
            for (int i = 0; i < 4; i++)
#pragma unroll
                for (int j = 0; j < 4; j++) acc[i][j] += racc[gg][t][i * 4 + j];
        float* dst = g_ctxp + ((size_t)sl * NB * HEADS + bh) * (DH * DH);
#pragma unroll
        for (int i = 0; i < 4; i++)
#pragma unroll
            for (int j = 0; j < 4; j++)
                dst[(td * 4 + i) * DH + te * 4 + j] = acc[i][j];
    }
}

// ---------------------------------------------------------------------------
// Kernel 5: fused weight Wf -> half. Grid (NB*HEADS, 2).
// ---------------------------------------------------------------------------
__global__ __launch_bounds__(256) void wf_kernel(const float* __restrict__ w_out) {
    __shared__ float cs[DH][DH];
    __shared__ float ws[128][DH + 1];
    const int bh = blockIdx.x;
    const int o0 = blockIdx.y * 128;
    const int b = bh >> 2, h = bh & 3;
    const int tid = threadIdx.x;

    {
        const size_t ss = (size_t)NB * HEADS * DH * DH;
        const size_t base = (size_t)bh * DH * DH;
        for (int i = tid; i < DH * DH; i += 256) {
            float s = 0.f;
#pragma unroll
            for (int sl = 0; sl < NSLICE; ++sl)
                s += g_ctxp[sl * ss + base + i];
            ((float*)cs)[i] = s;
        }
    }
#pragma unroll
    for (int it = 0; it < 4; ++it) {
        int idx = it * 256 + tid;
        int row = idx >> 3, e4 = idx & 7;
        float4 v = *(const float4*)&w_out[(o0 + row) * HID + h * DH + e4 * 4];
        ws[row][e4 * 4 + 0] = v.x; ws[row][e4 * 4 + 1] = v.y;
        ws[row][e4 * 4 + 2] = v.z; ws[row][e4 * 4 + 3] = v.w;
    }
    __syncthreads();

    if (tid < 128) {
        const int o = o0 + tid;
        float w[DH];
#pragma unroll
        for (int e = 0; e < DH; ++e) w[e] = ws[tid][e];

        __half* dst = g_wf + ((size_t)b * DIMC + o) * HID + h * DH;
#pragma unroll 4
        for (int d = 0; d < DH; d += 4) {
            float s0 = 0.f, s1 = 0.f, s2 = 0.f, s3 = 0.f;
#pragma unroll
            for (int e = 0; e < DH; ++e) {
                float we = w[e];
                s0 += we * cs[d + 0][e];
                s1 += we * cs[d + 1][e];
                s2 += we * cs[d + 2][e];
                s3 += we * cs[d + 3][e];
            }
            uint2 r;
            r.x = pack_h2(s0, s1);
            r.y = pack_h2(s2, s3);
            *(uint2*)&dst[d] = r;
        }
    }
}

// ---------------------------------------------------------------------------
// Kernel 6 (fp16 mma + ldmatrix + fused LN): out = Wf·q + b_out, LN over o.
// CTA 256(M) x 64(N), K=128, BK=32. 8 warps (4M x 2N).
// A raw-copied (layout == [row][k] halves); B raw-copied [k][n] halves.
// ---------------------------------------------------------------------------
#define OA_LD 20
#define OB_LDW 36                 // words per k-row (144 B)
#define OUT_DYN ((256 * OA_LD + 32 * OB_LDW) * 4)   // 25088 bytes

__global__ __launch_bounds__(256) void out_ln_mma(const float* __restrict__ b_out,
                                                  const float* __restrict__ gamma,
                                                  const float* __restrict__ beta,
                                                  float* __restrict__ out) {
    extern __shared__ uint32_t dynbuf[];
    uint32_t* As = dynbuf;                 // 256 x OA_LD
    uint32_t* Bs = dynbuf + 256 * OA_LD;   // 32 x OB_LDW
    __shared__ float s_sum[4][64];
    __shared__ float s_sq [4][64];
    __shared__ float s_mean[64], s_rstd[64];

    const int b  = blockIdx.y;
    const int n0 = blockIdx.x * 64;
    const __half* A = g_wf + (size_t)b * DIMC * HID;
    const __half* Q = g_qk + (size_t)b * (2 * HID) * NSP;

    const int tid = threadIdx.x, wid = tid >> 5, lane = tid & 31;
    const int wm = wid >> 1, wn = wid & 1;    // 4 x 2 warps
    const int g = lane >> 2, tg = lane & 3;

    const uint32_t As_u = smem_u32(As);
    const uint32_t Bs_u = smem_u32(Bs);
    const int lrow = (lane & 7) + (lane & 8);
    const uint32_t aOff = As_u + (uint32_t)(lrow * 80 + (lane >> 4) * 16)
                        + (uint32_t)(wm * 64 * 80);
    const uint32_t bOff = Bs_u + (uint32_t)(lrow * 144 + (lane >> 4) * 16)
                        + (uint32_t)(wn * 64);

    float acc[4][4][4];
#pragma unroll
    for (int i = 0; i < 4; ++i)
#pragma unroll
        for (int j = 0; j < 4; ++j)
#pragma unroll
            for (int e = 0; e < 4; ++e) acc[i][j][e] = 0.f;

#pragma unroll 1
    for (int k0 = 0; k0 < HID; k0 += 32) {
        // A: raw uint2 copies ([row][k] halves layout preserved)
#pragma unroll
        for (int j = 0; j < 8; ++j) {
            int fi = j * 256 + tid;
            int row = fi >> 3, q = fi & 7;
            uint2 v = *(const uint2*)(A + (size_t)row * HID + k0 + q * 4);
            uint32_t* d = &As[row * OA_LD + q * 2];
            d[0] = v.x; d[1] = v.y;
        }
        // B: raw uint2 copies of q rows -> [k][n] halves
#pragma unroll
        for (int j = 0; j < 2; ++j) {
            int fi = j * 256 + tid;
            int k = fi >> 4, u = fi & 15;
            uint2 v = *(const uint2*)(Q + (size_t)(k0 + k) * NSP + n0 + u * 4);
            uint32_t* d = &Bs[k * OB_LDW + u * 2];
            d[0] = v.x; d[1] = v.y;
        }
        __syncthreads();

#pragma unroll
        for (int ks2 = 0; ks2 < 2; ++ks2) {
            uint32_t af[4][4], bf[4][2];
#pragma unroll
            for (int i = 0; i < 4; ++i)
                ldsm_x4(af[i], aOff + (uint32_t)(i * 16 * 80 + ks2 * 32));
            {
                uint32_t t[4];
                ldsm_x4_t(t, bOff + (uint32_t)(ks2 * 16 * 144));
                bf[0][0] = t[0]; bf[0][1] = t[1]; bf[1][0] = t[2]; bf[1][1] = t[3];
                ldsm_x4_t(t, bOff + (uint32_t)(ks2 * 16 * 144 + 32));
                bf[2][0] = t[0]; bf[2][1] = t[1]; bf[3][0] = t[2]; bf[3][1] = t[3];
            }
#pragma unroll
            for (int i = 0; i < 4; ++i)
#pragma unroll
                for (int jn = 0; jn < 4; ++jn)
                    mma_f16(acc[i][jn], af[i], bf[jn]);
        }
        __syncthreads();
    }

    // Add bias into accumulators
#pragma unroll
    for (int i = 0; i < 4; ++i) {
        float bo0 = b_out[wm * 64 + i * 16 + g];
        float bo1 = b_out[wm * 64 + i * 16 + g + 8];
#pragma unroll
        for (int jn = 0; jn < 4; ++jn) {
            acc[i][jn][0] += bo0; acc[i][jn][1] += bo0;
            acc[i][jn][2] += bo1; acc[i][jn][3] += bo1;
        }
    }

    // Per-column (n) stats over the 256 channels.
    float ps[8], pq[8];
#pragma unroll
    for (int c = 0; c < 8; ++c) { ps[c] = 0.f; pq[c] = 0.f; }
#pragma unroll
    for (int i = 0; i < 4; ++i)
#pragma unroll
        for (int jn = 0; jn < 4; ++jn)
#pragma unroll
            for (int e = 0; e < 2; ++e) {
                float v0 = acc[i][jn][e];
                float v1 = acc[i][jn][2 + e];
                ps[jn * 2 + e] += v0 + v1;
                pq[jn * 2 + e] += v0 * v0 + v1 * v1;
            }
#pragma unroll
    for (int c = 0; c < 8; ++c) {
#pragma unroll
        for (int off = 4; off < 32; off <<= 1) {
            ps[c] += __shfl_xor_sync(0xffffffffu, ps[c], off);
            pq[c] += __shfl_xor_sync(0xffffffffu, pq[c], off);
        }
    }
    if (g == 0) {
#pragma unroll
        for (int jn = 0; jn < 4; ++jn)
#pragma unroll
            for (int e = 0; e < 2; ++e) {
                int col = wn * 32 + jn * 8 + tg * 2 + e;
                s_sum[wm][col] = ps[jn * 2 + e];
                s_sq [wm][col] = pq[jn * 2 + e];
            }
    }
    __syncthreads();
    if (tid < 64) {
        float s = s_sum[0][tid] + s_sum[1][tid] + s_sum[2][tid] + s_sum[3][tid];
        float q = s_sq [0][tid] + s_sq [1][tid] + s_sq [2][tid] + s_sq [3][tid];
        float mean = s * (1.0f / 256.0f);
        float var  = q * (1.0f / 256.0f) - mean * mean;
        s_mean[tid] = mean;
        s_rstd[tid] = rsqrtf(var + EPS);
    }
    __syncthreads();

    // Normalize + store
#pragma unroll
    for (int i = 0; i < 4; ++i) {
        int o0 = wm * 64 + i * 16 + g;
        float g0 = gamma[o0], b0v = beta[o0];
        float g1 = gamma[o0 + 8], b1v = beta[o0 + 8];
#pragma unroll
        for (int jn = 0; jn < 4; ++jn) {
            int cl = wn * 32 + jn * 8 + tg * 2;
            float m0 = s_mean[cl],     r0 = s_rstd[cl];
            float m1 = s_mean[cl + 1], r1 = s_rstd[cl + 1];
            *(float2*)&out[((size_t)b * DIMC + o0) * NSP + n0 + cl] =
                make_float2((acc[i][jn][0] - m0) * r0 * g0 + b0v,
                            (acc[i][jn][1] - m1) * r1 * g0 + b0v);
            *(float2*)&out[((size_t)b * DIMC + o0 + 8) * NSP + n0 + cl] =
                make_float2((acc[i][jn][2] - m0) * r0 * g1 + b1v,
                            (acc[i][jn][3] - m1) * r1 * g1 + b1v);
        }
    }
}

// ---------------------------------------------------------------------------
extern "C" void kernel_launch(void* const* d_in, const int* in_sizes, int n_in,
                              void* d_out, int out_size) {
    const float* x     = (const float*)d_in[0];
    const float* w_qkv = (const float*)d_in[1];
    const float* w_out = (const float*)d_in[2];
    const float* b_out = (const float*)d_in[3];
    const float* g     = (const float*)d_in[4];
    const float* bb    = (const float*)d_in[5];
    float* out = (float*)d_out;

    qkv_mma<<<dim3(NSP / 128, THREE / 128, NB), 256, QKV_DYN>>>(w_qkv, x);
    k_softmax<<<NB * HID, 256>>>();
    ctx_slice<<<dim3(NB * HEADS, NSLICE), 256>>>();
    wf_kernel<<<dim3(NB * HEADS, 2), 256>>>(w_out);
    out_ln_mma<<<dim3(NSP / 64, NB), 256, OUT_DYN>>>(b_out, g, bb, out);
}

// round 15
// speedup vs baseline: 4.2073x; 1.0269x over previous
#include <cuda_runtime.h>
#include <cuda_bf16.h>
#include <cuda_fp16.h>
#include <math.h>
#include <stdint.h>

// Problem constants
#define NB    32
#define DIMC  256
#define HEADS 4
#define DH    32
#define HID   128      // HEADS*DH
#define THREE 384      // 3*HID
#define NSP   4096     // 64*64 spatial
#define SCALE 0.17677669529663687f  // 32^-0.5
#define EPS   1e-5f
#define NSLICE 8       // ctx n-split

// Scratch (device globals)
__device__ __half g_qk [(size_t)NB * 2 * HID * NSP];             // q rows [0,128), k rows [128,256)
__device__ __half g_v  [(size_t)NB * HID * NSP];                 // 33.5 MB (half now)
__device__ float  g_ctxp[(size_t)NSLICE * NB * HEADS * DH * DH]; // 4 MB
__device__ __half g_wf [(size_t)NB * DIMC * HID];                // 2 MB

// ---------------------------------------------------------------------------
// Helpers
// ---------------------------------------------------------------------------
__device__ __forceinline__ uint32_t pack_h2(float lo, float hi) {
    __half2 h = __floats2half2_rn(lo, hi);
    return *(uint32_t*)&h;
}
__device__ __forceinline__ uint32_t smem_u32(const void* p) {
    uint32_t a;
    asm("{ .reg .u64 t; cvta.to.shared.u64 t, %1; cvt.u32.u64 %0, t; }"
        : "=r"(a) : "l"(p));
    return a;
}
__device__ __forceinline__ void mma_f16(float* d, const uint32_t* a, const uint32_t* b) {
    asm volatile(
        "mma.sync.aligned.m16n8k16.row.col.f32.f16.f16.f32 "
        "{%0,%1,%2,%3}, {%4,%5,%6,%7}, {%8,%9}, {%0,%1,%2,%3};\n"
        : "+f"(d[0]), "+f"(d[1]), "+f"(d[2]), "+f"(d[3])
        : "r"(a[0]), "r"(a[1]), "r"(a[2]), "r"(a[3]), "r"(b[0]), "r"(b[1]));
}
__device__ __forceinline__ void ldsm_x4(uint32_t* r, uint32_t addr) {
    asm volatile("ldmatrix.sync.aligned.m8n8.x4.shared.b16 {%0,%1,%2,%3}, [%4];"
        : "=r"(r[0]), "=r"(r[1]), "=r"(r[2]), "=r"(r[3]) : "r"(addr));
}
__device__ __forceinline__ void ldsm_x4_t(uint32_t* r, uint32_t addr) {
    asm volatile("ldmatrix.sync.aligned.m8n8.x4.trans.shared.b16 {%0,%1,%2,%3}, [%4];"
        : "=r"(r[0]), "=r"(r[1]), "=r"(r[2]), "=r"(r[3]) : "r"(addr));
}

// A smem: [row][k halves], pitch 20 words (80 B) -> ldmatrix-clean
// B smem: [k][n halves], pitch 68 words (272 B)  -> ldmatrix.trans-clean
#define QA_LD 20
#define QB_LDW 68                  // words per k-row
#define QA_BUF (128 * QA_LD)       // 2560 words per A buffer
#define QB_WORDS (256 * QB_LDW)    // 17408 words, full 256-K B tile
#define QKV_DYN ((QB_WORDS + 2 * QA_BUF) * 4)   // 90112 bytes

// ---------------------------------------------------------------------------
// Kernel 1: qkv = W * X. CTA owns one (b, 128-n tile); X tile staged to smem
// ONCE as fp16, then 3 m-tiles (q,k,v) sweep it. A double-buffered, BK=32.
// m-tile 0 fuses q-softmax. All outputs stored fp16.
// ---------------------------------------------------------------------------
__global__ __launch_bounds__(256) void qkv_mma(const float* __restrict__ W,
                                               const float* __restrict__ X) {
    extern __shared__ uint32_t qbuf[];
    uint32_t* Bs = qbuf;                 // QB_WORDS (full X tile)
    uint32_t* As = qbuf + QB_WORDS;      // 2 x QA_BUF

    const int b  = blockIdx.y;
    const int n0 = blockIdx.x * 128;
    const float* Xb = X + (size_t)b * DIMC * NSP;

    const int tid = threadIdx.x, wid = tid >> 5, lane = tid & 31;
    const int wm = wid >> 2, wn = wid & 3;     // 2 x 4 warps
    const int g = lane >> 2, tg = lane & 3;

    const uint32_t As_u = smem_u32(As);
    const uint32_t Bs_u = smem_u32(Bs);
    const int lrow = (lane & 7) + (lane & 8);
    const uint32_t aOff = As_u + (uint32_t)(lrow * 80 + (lane >> 4) * 16)
                        + (uint32_t)(wm * 64 * 80);
    const uint32_t bOff = Bs_u + (uint32_t)(lrow * 272 + (lane >> 4) * 16)
                        + (uint32_t)(wn * 64);

    // ---- Phase 1: stage full X tile (256 k x 128 n) as fp16 ----
    {
        const int n4 = (tid & 31) * 4;       // coalesced across n
        const int kb = tid >> 5;             // 0..7
#pragma unroll 8
        for (int k = kb; k < DIMC; k += 8) {
            float4 v = *(const float4*)(Xb + (size_t)k * NSP + n0 + n4);
            uint32_t* d = &Bs[k * QB_LDW + (n4 >> 1)];
            d[0] = pack_h2(v.x, v.y);
            d[1] = pack_h2(v.z, v.w);
        }
    }

    // A staging coordinates
    const int a_row[4] = { (0 * 256 + tid) >> 3, (1 * 256 + tid) >> 3,
                           (2 * 256 + tid) >> 3, (3 * 256 + tid) >> 3 };
    const int a_q = tid & 7;

    __half* Ch = g_qk + (size_t)b * (2 * HID) * NSP;
    __half* Cv = g_v  + (size_t)b * HID * NSP;

#pragma unroll 1
    for (int mt = 0; mt < 3; ++mt) {
        const int m0 = mt * 128;
        __syncthreads();   // B ready (mt=0) / previous m-tile done with As

        float4 ra[4];
#pragma unroll
        for (int j = 0; j < 4; ++j)
            ra[j] = *(const float4*)(W + (size_t)(m0 + a_row[j]) * DIMC + a_q * 4);
#pragma unroll
        for (int j = 0; j < 4; ++j) {
            uint32_t* d = &As[a_row[j] * QA_LD + a_q * 2];
            d[0] = pack_h2(ra[j].x, ra[j].y);
            d[1] = pack_h2(ra[j].z, ra[j].w);
        }
        __syncthreads();

        float acc[4][4][4];
#pragma unroll
        for (int i = 0; i < 4; ++i)
#pragma unroll
            for (int j = 0; j < 4; ++j)
#pragma unroll
                for (int e = 0; e < 4; ++e) acc[i][j][e] = 0.f;

#pragma unroll 1
        for (int ch = 0; ch < 8; ++ch) {
            if (ch < 7) {
                const int k0 = (ch + 1) * 32;
#pragma unroll
                for (int j = 0; j < 4; ++j)
                    ra[j] = *(const float4*)(W + (size_t)(m0 + a_row[j]) * DIMC + k0 + a_q * 4);
            }
            const uint32_t aB = aOff + (uint32_t)((ch & 1) * QA_BUF * 4);
#pragma unroll
            for (int ks2 = 0; ks2 < 2; ++ks2) {
                uint32_t af[4][4], bf[4][2];
#pragma unroll
                for (int i = 0; i < 4; ++i)
                    ldsm_x4(af[i], aB + (uint32_t)(i * 16 * 80 + ks2 * 32));
                {
                    const uint32_t kByte = (uint32_t)((ch * 32 + ks2 * 16) * 272);
                    uint32_t t[4];
                    ldsm_x4_t(t, bOff + kByte);
                    bf[0][0] = t[0]; bf[0][1] = t[1]; bf[1][0] = t[2]; bf[1][1] = t[3];
                    ldsm_x4_t(t, bOff + kByte + 32);
                    bf[2][0] = t[0]; bf[2][1] = t[1]; bf[3][0] = t[2]; bf[3][1] = t[3];
                }
#pragma unroll
                for (int i = 0; i < 4; ++i)
#pragma unroll
                    for (int jn = 0; jn < 4; ++jn)
                        mma_f16(acc[i][jn], af[i], bf[jn]);
            }
            if (ch < 7) {
                uint32_t* An = As + ((ch + 1) & 1) * QA_BUF;
#pragma unroll
                for (int j = 0; j < 4; ++j) {
                    uint32_t* d = &An[a_row[j] * QA_LD + a_q * 2];
                    d[0] = pack_h2(ra[j].x, ra[j].y);
                    d[1] = pack_h2(ra[j].z, ra[j].w);
                }
                __syncthreads();
            }
        }

        // Fused q softmax (m-tile 0 only)
        if (mt == 0) {
#pragma unroll
            for (int jn = 0; jn < 4; ++jn)
#pragma unroll
                for (int e = 0; e < 2; ++e)
#pragma unroll
                    for (int hd = 0; hd < 2; ++hd) {
                        const int ib = hd * 2;
                        float v0 = acc[ib][jn][e],     v1 = acc[ib][jn][2 + e];
                        float v2 = acc[ib + 1][jn][e], v3 = acc[ib + 1][jn][2 + e];
                        float m = fmaxf(fmaxf(v0, v1), fmaxf(v2, v3));
#pragma unroll
                        for (int off = 4; off < 32; off <<= 1)
                            m = fmaxf(m, __shfl_xor_sync(0xffffffffu, m, off));
                        v0 = __expf(v0 - m); v1 = __expf(v1 - m);
                        v2 = __expf(v2 - m); v3 = __expf(v3 - m);
                        float s = (v0 + v1) + (v2 + v3);
#pragma unroll
                        for (int off = 4; off < 32; off <<= 1)
                            s += __shfl_xor_sync(0xffffffffu, s, off);
                        float inv = SCALE / s;
                        acc[ib][jn][e]         = v0 * inv;
                        acc[ib][jn][2 + e]     = v1 * inv;
                        acc[ib + 1][jn][e]     = v2 * inv;
                        acc[ib + 1][jn][2 + e] = v3 * inv;
                    }
        }

        // Epilogue (all fp16)
        __half* dst = (mt < 2) ? Ch : Cv;
        const int rbase = (mt < 2) ? m0 : 0;
#pragma unroll
        for (int i = 0; i < 4; ++i) {
            int r0 = rbase + wm * 64 + i * 16 + g;
#pragma unroll
            for (int jn = 0; jn < 4; ++jn) {
                int c = n0 + wn * 32 + jn * 8 + tg * 2;
                *(uint32_t*)&dst[(size_t)r0 * NSP + c] =
                    pack_h2(acc[i][jn][0], acc[i][jn][1]);
                *(uint32_t*)&dst[(size_t)(r0 + 8) * NSP + c] =
                    pack_h2(acc[i][jn][2], acc[i][jn][3]);
            }
        }
    }
}

// ---------------------------------------------------------------------------
// Kernel 3: k softmax over n, fp16 in/out (rows [128,256) of g_qk).
// ---------------------------------------------------------------------------
__global__ __launch_bounds__(256) void k_softmax() {
    __shared__ float buf[NSP];
    __shared__ float red[256];
    int row = blockIdx.x;
    int b = row >> 7, r = row & 127;
    __half2* base2 = (__half2*)(g_qk + ((size_t)b * (2 * HID) + HID + r) * NSP);
    int tid = threadIdx.x;

    float mx = -1e30f;
    for (int i = tid; i < NSP / 2; i += 256) {
        float2 f = __half22float2(base2[i]);
        buf[2 * i] = f.x; buf[2 * i + 1] = f.y;
        mx = fmaxf(mx, fmaxf(f.x, f.y));
    }
    red[tid] = mx; __syncthreads();
    for (int s = 128; s > 0; s >>= 1) {
        if (tid < s) red[tid] = fmaxf(red[tid], red[tid + s]);
        __syncthreads();
    }
    mx = red[0]; __syncthreads();

    float sum = 0.f;
    for (int i = tid; i < NSP; i += 256) { float e = __expf(buf[i] - mx); buf[i] = e; sum += e; }
    red[tid] = sum; __syncthreads();
    for (int s = 128; s > 0; s >>= 1) {
        if (tid < s) red[tid] += red[tid + s];
        __syncthreads();
    }
    float inv = 1.0f / red[0];
    __syncthreads();
    for (int i = tid; i < NSP / 2; i += 256)
        base2[i] = __floats2half2_rn(buf[2 * i] * inv, buf[2 * i + 1] * inv);
}

// ---------------------------------------------------------------------------
// Kernel 4: context partials. k and v both fp16 now.
// ---------------------------------------------------------------------------
__global__ __launch_bounds__(256) void ctx_slice() {
    __shared__ float Ks[4][32][33];
    __shared__ float Vs[4][32][33];
    __shared__ float racc[3][64][16];
    int bh = blockIdx.x;
    int sl = blockIdx.y;
    int b = bh >> 2, h = bh & 3;
    const __half* kbase = g_qk + ((size_t)b * (2 * HID) + HID + h * DH) * NSP;
    const __half* vbase = g_v  + ((size_t)b * HID + h * DH) * NSP;

    int tid = threadIdx.x;
    int grp = tid >> 6;
    int t   = tid & 63;
    int td = t >> 3, te = t & 7;

    float acc[4][4];
#pragma unroll
    for (int i = 0; i < 4; i++)
#pragma unroll
        for (int j = 0; j < 4; j++) acc[i][j] = 0.f;

    const int base_n = sl * (NSP / NSLICE) + grp * 128;
#pragma unroll 1
    for (int cc = 0; cc < 128; cc += 32) {
        int c0 = base_n + cc;
#pragma unroll
        for (int m = 0; m < 4; m++) {
            int fi = m * 64 + t;
            int dd = fi >> 3;
            int nn = (fi & 7) * 4;
            uint2 kw = *(const uint2*)&kbase[(size_t)dd * NSP + c0 + nn];
            float2 k01 = __half22float2(*(__half2*)&kw.x);
            float2 k23 = __half22float2(*(__half2*)&kw.y);
            uint2 vw = *(const uint2*)&vbase[(size_t)dd * NSP + c0 + nn];
            float2 v01 = __half22float2(*(__half2*)&vw.x);
            float2 v23 = __half22float2(*(__half2*)&vw.y);
            Ks[grp][dd][nn+0] = k01.x; Ks[grp][dd][nn+1] = k01.y;
            Ks[grp][dd][nn+2] = k23.x; Ks[grp][dd][nn+3] = k23.y;
            Vs[grp][dd][nn+0] = v01.x; Vs[grp][dd][nn+1] = v01.y;
            Vs[grp][dd][nn+2] = v23.x; Vs[grp][dd][nn+3] = v23.y;
        }
        __syncthreads();
#pragma unroll 4
        for (int n = 0; n < 32; n++) {
            float ka[4], vb[4];
#pragma unroll
            for (int i = 0; i < 4; i++) ka[i] = Ks[grp][td * 4 + i][n];
#pragma unroll
            for (int j = 0; j < 4; j++) vb[j] = Vs[grp][te * 4 + j][n];
#pragma unroll
            for (int i = 0; i < 4; i++)
#pragma unroll
                for (int j = 0; j < 4; j++) acc[i][j] += ka[i] * vb[j];
        }
        __syncthreads();
    }

    if (grp > 0) {
#pragma unroll
        for (int i = 0; i < 4; i++)
#pragma unroll
            for (int j = 0; j < 4; j++) racc[grp - 1][t][i * 4 + j] = acc[i][j];
    }
    __syncthreads();
    if (grp == 0) {
#pragma unroll
        for (int gg = 0; gg < 3; gg++)
#pragma unroll
            for (int i = 0; i < 4; i++)
#pragma unroll
                for (int j = 0; j < 4; j++) acc[i][j] += racc[gg][t][i * 4 + j];
        float* dst = g_ctxp + ((size_t)sl * NB * HEADS + bh) * (DH * DH);
#pragma unroll
        for (int i = 0; i < 4; i++)
#pragma unroll
            for (int j = 0; j < 4; j++)
                dst[(td * 4 + i) * DH + te * 4 + j] = acc[i][j];
    }
}

// ---------------------------------------------------------------------------
// Kernel 5: fused weight Wf -> half. Grid (NB*HEADS, 2).
// ---------------------------------------------------------------------------
__global__ __launch_bounds__(256) void wf_kernel(const float* __restrict__ w_out) {
    __shared__ float cs[DH][DH];
    __shared__ float ws[128][DH + 1];
    const int bh = blockIdx.x;
    const int o0 = blockIdx.y * 128;
    const int b = bh >> 2, h = bh & 3;
    const int tid = threadIdx.x;

    {
        const size_t ss = (size_t)NB * HEADS * DH * DH;
        const size_t base = (size_t)bh * DH * DH;
        for (int i = tid; i < DH * DH; i += 256) {
            float s = 0.f;
#pragma unroll
            for (int sl = 0; sl < NSLICE; ++sl)
                s += g_ctxp[sl * ss + base + i];
            ((float*)cs)[i] = s;
        }
    }
#pragma unroll
    for (int it = 0; it < 4; ++it) {
        int idx = it * 256 + tid;
        int row = idx >> 3, e4 = idx & 7;
        float4 v = *(const float4*)&w_out[(o0 + row) * HID + h * DH + e4 * 4];
        ws[row][e4 * 4 + 0] = v.x; ws[row][e4 * 4 + 1] = v.y;
        ws[row][e4 * 4 + 2] = v.z; ws[row][e4 * 4 + 3] = v.w;
    }
    __syncthreads();

    if (tid < 128) {
        const int o = o0 + tid;
        float w[DH];
#pragma unroll
        for (int e = 0; e < DH; ++e) w[e] = ws[tid][e];

        __half* dst = g_wf + ((size_t)b * DIMC + o) * HID + h * DH;
#pragma unroll 4
        for (int d = 0; d < DH; d += 4) {
            float s0 = 0.f, s1 = 0.f, s2 = 0.f, s3 = 0.f;
#pragma unroll
            for (int e = 0; e < DH; ++e) {
                float we = w[e];
                s0 += we * cs[d + 0][e];
                s1 += we * cs[d + 1][e];
                s2 += we * cs[d + 2][e];
                s3 += we * cs[d + 3][e];
            }
            uint2 r;
            r.x = pack_h2(s0, s1);
            r.y = pack_h2(s2, s3);
            *(uint2*)&dst[d] = r;
        }
    }
}

// ---------------------------------------------------------------------------
// Kernel 6 (fp16 mma + ldmatrix + fused LN): out = Wf·q + b_out, LN over o.
// ---------------------------------------------------------------------------
#define OA_LD 20
#define OB_LDW 36
#define OUT_DYN ((256 * OA_LD + 32 * OB_LDW) * 4)   // 25088 bytes

__global__ __launch_bounds__(256) void out_ln_mma(const float* __restrict__ b_out,
                                                  const float* __restrict__ gamma,
                                                  const float* __restrict__ beta,
                                                  float* __restrict__ out) {
    extern __shared__ uint32_t dynbuf[];
    uint32_t* As = dynbuf;
    uint32_t* Bs = dynbuf + 256 * OA_LD;
    __shared__ float s_sum[4][64];
    __shared__ float s_sq [4][64];
    __shared__ float s_mean[64], s_rstd[64];

    const int b  = blockIdx.y;
    const int n0 = blockIdx.x * 64;
    const __half* A = g_wf + (size_t)b * DIMC * HID;
    const __half* Q = g_qk + (size_t)b * (2 * HID) * NSP;

    const int tid = threadIdx.x, wid = tid >> 5, lane = tid & 31;
    const int wm = wid >> 1, wn = wid & 1;
    const int g = lane >> 2, tg = lane & 3;

    const uint32_t As_u = smem_u32(As);
    const uint32_t Bs_u = smem_u32(Bs);
    const int lrow = (lane & 7) + (lane & 8);
    const uint32_t aOff = As_u + (uint32_t)(lrow * 80 + (lane >> 4) * 16)
                        + (uint32_t)(wm * 64 * 80);
    const uint32_t bOff = Bs_u + (uint32_t)(lrow * 144 + (lane >> 4) * 16)
                        + (uint32_t)(wn * 64);

    float acc[4][4][4];
#pragma unroll
    for (int i = 0; i < 4; ++i)
#pragma unroll
        for (int j = 0; j < 4; ++j)
#pragma unroll
            for (int e = 0; e < 4; ++e) acc[i][j][e] = 0.f;

#pragma unroll 1
    for (int k0 = 0; k0 < HID; k0 += 32) {
#pragma unroll
        for (int j = 0; j < 8; ++j) {
            int fi = j * 256 + tid;
            int row = fi >> 3, q = fi & 7;
            uint2 v = *(const uint2*)(A + (size_t)row * HID + k0 + q * 4);
            uint32_t* d = &As[row * OA_LD + q * 2];
            d[0] = v.x; d[1] = v.y;
        }
#pragma unroll
        for (int j = 0; j < 2; ++j) {
            int fi = j * 256 + tid;
            int k = fi >> 4, u = fi & 15;
            uint2 v = *(const uint2*)(Q + (size_t)(k0 + k) * NSP + n0 + u * 4);
            uint32_t* d = &Bs[k * OB_LDW + u * 2];
            d[0] = v.x; d[1] = v.y;
        }
        __syncthreads();

#pragma unroll
        for (int ks2 = 0; ks2 < 2; ++ks2) {
            uint32_t af[4][4], bf[4][2];
#pragma unroll
            for (int i = 0; i < 4; ++i)
                ldsm_x4(af[i], aOff + (uint32_t)(i * 16 * 80 + ks2 * 32));
            {
                uint32_t t[4];
                ldsm_x4_t(t, bOff + (uint32_t)(ks2 * 16 * 144));
                bf[0][0] = t[0]; bf[0][1] = t[1]; bf[1][0] = t[2]; bf[1][1] = t[3];
                ldsm_x4_t(t, bOff + (uint32_t)(ks2 * 16 * 144 + 32));
                bf[2][0] = t[0]; bf[2][1] = t[1]; bf[3][0] = t[2]; bf[3][1] = t[3];
            }
#pragma unroll
            for (int i = 0; i < 4; ++i)
#pragma unroll
                for (int jn = 0; jn < 4; ++jn)
                    mma_f16(acc[i][jn], af[i], bf[jn]);
        }
        __syncthreads();
    }

#pragma unroll
    for (int i = 0; i < 4; ++i) {
        float bo0 = b_out[wm * 64 + i * 16 + g];
        float bo1 = b_out[wm * 64 + i * 16 + g + 8];
#pragma unroll
        for (int jn = 0; jn < 4; ++jn) {
            acc[i][jn][0] += bo0; acc[i][jn][1] += bo0;
            acc[i][jn][2] += bo1; acc[i][jn][3] += bo1;
        }
    }

    float ps[8], pq[8];
#pragma unroll
    for (int c = 0; c < 8; ++c) { ps[c] = 0.f; pq[c] = 0.f; }
#pragma unroll
    for (int i = 0; i < 4; ++i)
#pragma unroll
        for (int jn = 0; jn < 4; ++jn)
#pragma unroll
            for (int e = 0; e < 2; ++e) {
                float v0 = acc[i][jn][e];
                float v1 = acc[i][jn][2 + e];
                ps[jn * 2 + e] += v0 + v1;
                pq[jn * 2 + e] += v0 * v0 + v1 * v1;
            }
#pragma unroll
    for (int c = 0; c < 8; ++c) {
#pragma unroll
        for (int off = 4; off < 32; off <<= 1) {
            ps[c] += __shfl_xor_sync(0xffffffffu, ps[c], off);
            pq[c] += __shfl_xor_sync(0xffffffffu, pq[c], off);
        }
    }
    if (g == 0) {
#pragma unroll
        for (int jn = 0; jn < 4; ++jn)
#pragma unroll
            for (int e = 0; e < 2; ++e) {
                int col = wn * 32 + jn * 8 + tg * 2 + e;
                s_sum[wm][col] = ps[jn * 2 + e];
                s_sq [wm][col] = pq[jn * 2 + e];
            }
    }
    __syncthreads();
    if (tid < 64) {
        float s = s_sum[0][tid] + s_sum[1][tid] + s_sum[2][tid] + s_sum[3][tid];
        float q = s_sq [0][tid] + s_sq [1][tid] + s_sq [2][tid] + s_sq [3][tid];
        float mean = s * (1.0f / 256.0f);
        float var  = q * (1.0f / 256.0f) - mean * mean;
        s_mean[tid] = mean;
        s_rstd[tid] = rsqrtf(var + EPS);
    }
    __syncthreads();

#pragma unroll
    for (int i = 0; i < 4; ++i) {
        int o0 = wm * 64 + i * 16 + g;
        float g0 = gamma[o0], b0v = beta[o0];
        float g1 = gamma[o0 + 8], b1v = beta[o0 + 8];
#pragma unroll
        for (int jn = 0; jn < 4; ++jn) {
            int cl = wn * 32 + jn * 8 + tg * 2;
            float m0 = s_mean[cl],     r0 = s_rstd[cl];
            float m1 = s_mean[cl + 1], r1 = s_rstd[cl + 1];
            *(float2*)&out[((size_t)b * DIMC + o0) * NSP + n0 + cl] =
                make_float2((acc[i][jn][0] - m0) * r0 * g0 + b0v,
                            (acc[i][jn][1] - m1) * r1 * g0 + b0v);
            *(float2*)&out[((size_t)b * DIMC + o0 + 8) * NSP + n0 + cl] =
                make_float2((acc[i][jn][2] - m0) * r0 * g1 + b1v,
                            (acc[i][jn][3] - m1) * r1 * g1 + b1v);
        }
    }
}

// ---------------------------------------------------------------------------
extern "C" void kernel_launch(void* const* d_in, const int* in_sizes, int n_in,
                              void* d_out, int out_size) {
    const float* x     = (const float*)d_in[0];
    const float* w_qkv = (const float*)d_in[1];
    const float* w_out = (const float*)d_in[2];
    const float* b_out = (const float*)d_in[3];
    const float* g     = (const float*)d_in[4];
    const float* bb    = (const float*)d_in[5];
    float* out = (float*)d_out;

    cudaFuncSetAttribute(qkv_mma, cudaFuncAttributeMaxDynamicSharedMemorySize, QKV_DYN);

    qkv_mma<<<dim3(NSP / 128, NB), 256, QKV_DYN>>>(w_qkv, x);
    k_softmax<<<NB * HID, 256>>>();
    ctx_slice<<<dim3(NB * HEADS, NSLICE), 256>>>();
    wf_kernel<<<dim3(NB * HEADS, 2), 256>>>(w_out);
    out_ln_mma<<<dim3(NSP / 64, NB), 256, OUT_DYN>>>(b_out, g, bb, out);
}

// round 16
// speedup vs baseline: 4.6255x; 1.0994x over previous
#include <cuda_runtime.h>
#include <cuda_bf16.h>
#include <cuda_fp16.h>
#include <math.h>
#include <stdint.h>

// Problem constants
#define NB    32
#define DIMC  256
#define HEADS 4
#define DH    32
#define HID   128      // HEADS*DH
#define THREE 384      // 3*HID
#define NSP   4096     // 64*64 spatial
#define SCALE 0.17677669529663687f  // 32^-0.5
#define EPS   1e-5f
#define NSLICE 8       // ctx n-split

// Scratch (device globals)
__device__ __half g_qk [(size_t)NB * 2 * HID * NSP];             // q rows [0,128), k logits rows [128,256)
__device__ __half g_v  [(size_t)NB * HID * NSP];                 // 33.5 MB
__device__ float  g_kms[(size_t)NB * HID * 2];                   // per k-row (M, 1/Z)
__device__ float  g_ctxp[(size_t)NSLICE * NB * HEADS * DH * DH]; // 4 MB
__device__ __half g_wf [(size_t)NB * DIMC * HID];                // 2 MB

// ---------------------------------------------------------------------------
// Helpers
// ---------------------------------------------------------------------------
__device__ __forceinline__ uint32_t pack_h2(float lo, float hi) {
    __half2 h = __floats2half2_rn(lo, hi);
    return *(uint32_t*)&h;
}
__device__ __forceinline__ uint32_t smem_u32(const void* p) {
    uint32_t a;
    asm("{ .reg .u64 t; cvta.to.shared.u64 t, %1; cvt.u32.u64 %0, t; }"
        : "=r"(a) : "l"(p));
    return a;
}
__device__ __forceinline__ void mma_f16(float* d, const uint32_t* a, const uint32_t* b) {
    asm volatile(
        "mma.sync.aligned.m16n8k16.row.col.f32.f16.f16.f32 "
        "{%0,%1,%2,%3}, {%4,%5,%6,%7}, {%8,%9}, {%0,%1,%2,%3};\n"
        : "+f"(d[0]), "+f"(d[1]), "+f"(d[2]), "+f"(d[3])
        : "r"(a[0]), "r"(a[1]), "r"(a[2]), "r"(a[3]), "r"(b[0]), "r"(b[1]));
}
__device__ __forceinline__ void ldsm_x4(uint32_t* r, uint32_t addr) {
    asm volatile("ldmatrix.sync.aligned.m8n8.x4.shared.b16 {%0,%1,%2,%3}, [%4];"
        : "=r"(r[0]), "=r"(r[1]), "=r"(r[2]), "=r"(r[3]) : "r"(addr));
}
__device__ __forceinline__ void ldsm_x4_t(uint32_t* r, uint32_t addr) {
    asm volatile("ldmatrix.sync.aligned.m8n8.x4.trans.shared.b16 {%0,%1,%2,%3}, [%4];"
        : "=r"(r[0]), "=r"(r[1]), "=r"(r[2]), "=r"(r[3]) : "r"(addr));
}
__device__ __forceinline__ void cp_async16(uint32_t dst, const void* src) {
    asm volatile("cp.async.cg.shared.global [%0], [%1], 16;" :: "r"(dst), "l"(src));
}
#define CP_COMMIT() asm volatile("cp.async.commit_group;" ::: "memory")
#define CP_WAIT(n)  asm volatile("cp.async.wait_group %0;" :: "n"(n) : "memory")

// A smem: [row][k halves], pitch 20 words (80 B) -> ldmatrix-clean
// B smem (qkv): [k][n halves], pitch 68 words (272 B) -> ldmatrix.trans-clean
#define QA_LD 20
#define QB_LDW 68
#define QA_BUF (128 * QA_LD)
#define QB_WORDS (256 * QB_LDW)
#define QKV_DYN ((QB_WORDS + 2 * QA_BUF) * 4)   // 90112 bytes

// ---------------------------------------------------------------------------
// Kernel 1: qkv = W * X (unchanged from R15). X staged once; 3 m-tiles sweep.
// ---------------------------------------------------------------------------
__global__ __launch_bounds__(256) void qkv_mma(const float* __restrict__ W,
                                               const float* __restrict__ X) {
    extern __shared__ uint32_t qbuf[];
    uint32_t* Bs = qbuf;
    uint32_t* As = qbuf + QB_WORDS;

    const int b  = blockIdx.y;
    const int n0 = blockIdx.x * 128;
    const float* Xb = X + (size_t)b * DIMC * NSP;

    const int tid = threadIdx.x, wid = tid >> 5, lane = tid & 31;
    const int wm = wid >> 2, wn = wid & 3;
    const int g = lane >> 2, tg = lane & 3;

    const uint32_t As_u = smem_u32(As);
    const uint32_t Bs_u = smem_u32(Bs);
    const int lrow = (lane & 7) + (lane & 8);
    const uint32_t aOff = As_u + (uint32_t)(lrow * 80 + (lane >> 4) * 16)
                        + (uint32_t)(wm * 64 * 80);
    const uint32_t bOff = Bs_u + (uint32_t)(lrow * 272 + (lane >> 4) * 16)
                        + (uint32_t)(wn * 64);

    {
        const int n4 = (tid & 31) * 4;
        const int kb = tid >> 5;
#pragma unroll 8
        for (int k = kb; k < DIMC; k += 8) {
            float4 v = *(const float4*)(Xb + (size_t)k * NSP + n0 + n4);
            uint32_t* d = &Bs[k * QB_LDW + (n4 >> 1)];
            d[0] = pack_h2(v.x, v.y);
            d[1] = pack_h2(v.z, v.w);
        }
    }

    const int a_row[4] = { (0 * 256 + tid) >> 3, (1 * 256 + tid) >> 3,
                           (2 * 256 + tid) >> 3, (3 * 256 + tid) >> 3 };
    const int a_q = tid & 7;

    __half* Ch = g_qk + (size_t)b * (2 * HID) * NSP;
    __half* Cv = g_v  + (size_t)b * HID * NSP;

#pragma unroll 1
    for (int mt = 0; mt < 3; ++mt) {
        const int m0 = mt * 128;
        __syncthreads();

        float4 ra[4];
#pragma unroll
        for (int j = 0; j < 4; ++j)
            ra[j] = *(const float4*)(W + (size_t)(m0 + a_row[j]) * DIMC + a_q * 4);
#pragma unroll
        for (int j = 0; j < 4; ++j) {
            uint32_t* d = &As[a_row[j] * QA_LD + a_q * 2];
            d[0] = pack_h2(ra[j].x, ra[j].y);
            d[1] = pack_h2(ra[j].z, ra[j].w);
        }
        __syncthreads();

        float acc[4][4][4];
#pragma unroll
        for (int i = 0; i < 4; ++i)
#pragma unroll
            for (int j = 0; j < 4; ++j)
#pragma unroll
                for (int e = 0; e < 4; ++e) acc[i][j][e] = 0.f;

#pragma unroll 1
        for (int ch = 0; ch < 8; ++ch) {
            if (ch < 7) {
                const int k0 = (ch + 1) * 32;
#pragma unroll
                for (int j = 0; j < 4; ++j)
                    ra[j] = *(const float4*)(W + (size_t)(m0 + a_row[j]) * DIMC + k0 + a_q * 4);
            }
            const uint32_t aB = aOff + (uint32_t)((ch & 1) * QA_BUF * 4);
#pragma unroll
            for (int ks2 = 0; ks2 < 2; ++ks2) {
                uint32_t af[4][4], bf[4][2];
#pragma unroll
                for (int i = 0; i < 4; ++i)
                    ldsm_x4(af[i], aB + (uint32_t)(i * 16 * 80 + ks2 * 32));
                {
                    const uint32_t kByte = (uint32_t)((ch * 32 + ks2 * 16) * 272);
                    uint32_t t[4];
                    ldsm_x4_t(t, bOff + kByte);
                    bf[0][0] = t[0]; bf[0][1] = t[1]; bf[1][0] = t[2]; bf[1][1] = t[3];
                    ldsm_x4_t(t, bOff + kByte + 32);
                    bf[2][0] = t[0]; bf[2][1] = t[1]; bf[3][0] = t[2]; bf[3][1] = t[3];
                }
#pragma unroll
                for (int i = 0; i < 4; ++i)
#pragma unroll
                    for (int jn = 0; jn < 4; ++jn)
                        mma_f16(acc[i][jn], af[i], bf[jn]);
            }
            if (ch < 7) {
                uint32_t* An = As + ((ch + 1) & 1) * QA_BUF;
#pragma unroll
                for (int j = 0; j < 4; ++j) {
                    uint32_t* d = &An[a_row[j] * QA_LD + a_q * 2];
                    d[0] = pack_h2(ra[j].x, ra[j].y);
                    d[1] = pack_h2(ra[j].z, ra[j].w);
                }
                __syncthreads();
            }
        }

        if (mt == 0) {
#pragma unroll
            for (int jn = 0; jn < 4; ++jn)
#pragma unroll
                for (int e = 0; e < 2; ++e)
#pragma unroll
                    for (int hd = 0; hd < 2; ++hd) {
                        const int ib = hd * 2;
                        float v0 = acc[ib][jn][e],     v1 = acc[ib][jn][2 + e];
                        float v2 = acc[ib + 1][jn][e], v3 = acc[ib + 1][jn][2 + e];
                        float m = fmaxf(fmaxf(v0, v1), fmaxf(v2, v3));
#pragma unroll
                        for (int off = 4; off < 32; off <<= 1)
                            m = fmaxf(m, __shfl_xor_sync(0xffffffffu, m, off));
                        v0 = __expf(v0 - m); v1 = __expf(v1 - m);
                        v2 = __expf(v2 - m); v3 = __expf(v3 - m);
                        float s = (v0 + v1) + (v2 + v3);
#pragma unroll
                        for (int off = 4; off < 32; off <<= 1)
                            s += __shfl_xor_sync(0xffffffffu, s, off);
                        float inv = SCALE / s;
                        acc[ib][jn][e]         = v0 * inv;
                        acc[ib][jn][2 + e]     = v1 * inv;
                        acc[ib + 1][jn][e]     = v2 * inv;
                        acc[ib + 1][jn][2 + e] = v3 * inv;
                    }
        }

        __half* dst = (mt < 2) ? Ch : Cv;
        const int rbase = (mt < 2) ? m0 : 0;
#pragma unroll
        for (int i = 0; i < 4; ++i) {
            int r0 = rbase + wm * 64 + i * 16 + g;
#pragma unroll
            for (int jn = 0; jn < 4; ++jn) {
                int c = n0 + wn * 32 + jn * 8 + tg * 2;
                *(uint32_t*)&dst[(size_t)r0 * NSP + c] =
                    pack_h2(acc[i][jn][0], acc[i][jn][1]);
                *(uint32_t*)&dst[(size_t)(r0 + 8) * NSP + c] =
                    pack_h2(acc[i][jn][2], acc[i][jn][3]);
            }
        }
    }
}

// ---------------------------------------------------------------------------
// Kernel 2: krow — per k-row online (max, sum-exp). Warp per row.
// ---------------------------------------------------------------------------
__global__ __launch_bounds__(256) void krow() {
    const int row  = blockIdx.x * 8 + (threadIdx.x >> 5);
    const int lane = threadIdx.x & 31;
    const int b = row >> 7, r = row & 127;
    const __half2* p = (const __half2*)(g_qk + ((size_t)b * (2 * HID) + HID + r) * NSP);

    float m = -1e30f, s = 0.f;
#pragma unroll 4
    for (int i = lane; i < NSP / 2; i += 32) {
        float2 f = __half22float2(p[i]);
        float mx = fmaxf(f.x, f.y);
        if (mx > m) { s *= __expf(m - mx); m = mx; }
        s += __expf(f.x - m) + __expf(f.y - m);
    }
#pragma unroll
    for (int off = 16; off > 0; off >>= 1) {
        float mo = __shfl_xor_sync(0xffffffffu, m, off);
        float so = __shfl_xor_sync(0xffffffffu, s, off);
        float mn = fmaxf(m, mo);
        s = s * __expf(m - mn) + so * __expf(mo - mn);
        m = mn;
    }
    if (lane == 0) {
        g_kms[2 * row]     = m;
        g_kms[2 * row + 1] = 1.0f / s;
    }
}

// ---------------------------------------------------------------------------
// Kernel 3: context partials; softmax exp applied to k logits at fill time.
// ---------------------------------------------------------------------------
__global__ __launch_bounds__(256) void ctx_slice() {
    __shared__ float Ks[4][32][33];
    __shared__ float Vs[4][32][33];
    __shared__ float racc[3][64][16];
    __shared__ float Ms[32], Zs[32];
    int bh = blockIdx.x;
    int sl = blockIdx.y;
    int b = bh >> 2, h = bh & 3;
    const __half* kbase = g_qk + ((size_t)b * (2 * HID) + HID + h * DH) * NSP;
    const __half* vbase = g_v  + ((size_t)b * HID + h * DH) * NSP;

    int tid = threadIdx.x;
    int grp = tid >> 6;
    int t   = tid & 63;
    int td = t >> 3, te = t & 7;

    if (tid < 32) {
        Ms[tid] = g_kms[2 * (b * HID + h * DH + tid)];
    } else if (tid < 64) {
        Zs[tid - 32] = g_kms[2 * (b * HID + h * DH + (tid - 32)) + 1];
    }
    __syncthreads();

    float acc[4][4];
#pragma unroll
    for (int i = 0; i < 4; i++)
#pragma unroll
        for (int j = 0; j < 4; j++) acc[i][j] = 0.f;

    const int base_n = sl * (NSP / NSLICE) + grp * 128;
#pragma unroll 1
    for (int cc = 0; cc < 128; cc += 32) {
        int c0 = base_n + cc;
#pragma unroll
        for (int m = 0; m < 4; m++) {
            int fi = m * 64 + t;
            int dd = fi >> 3;
            int nn = (fi & 7) * 4;
            float mM = Ms[dd], zZ = Zs[dd];
            uint2 kw = *(const uint2*)&kbase[(size_t)dd * NSP + c0 + nn];
            float2 k01 = __half22float2(*(__half2*)&kw.x);
            float2 k23 = __half22float2(*(__half2*)&kw.y);
            uint2 vw = *(const uint2*)&vbase[(size_t)dd * NSP + c0 + nn];
            float2 v01 = __half22float2(*(__half2*)&vw.x);
            float2 v23 = __half22float2(*(__half2*)&vw.y);
            Ks[grp][dd][nn+0] = __expf(k01.x - mM) * zZ;
            Ks[grp][dd][nn+1] = __expf(k01.y - mM) * zZ;
            Ks[grp][dd][nn+2] = __expf(k23.x - mM) * zZ;
            Ks[grp][dd][nn+3] = __expf(k23.y - mM) * zZ;
            Vs[grp][dd][nn+0] = v01.x; Vs[grp][dd][nn+1] = v01.y;
            Vs[grp][dd][nn+2] = v23.x; Vs[grp][dd][nn+3] = v23.y;
        }
        __syncthreads();
#pragma unroll 4
        for (int n = 0; n < 32; n++) {
            float ka[4], vb[4];
#pragma unroll
            for (int i = 0; i < 4; i++) ka[i] = Ks[grp][td * 4 + i][n];
#pragma unroll
            for (int j = 0; j < 4; j++) vb[j] = Vs[grp][te * 4 + j][n];
#pragma unroll
            for (int i = 0; i < 4; i++)
#pragma unroll
                for (int j = 0; j < 4; j++) acc[i][j] += ka[i] * vb[j];
        }
        __syncthreads();
    }

    if (grp > 0) {
#pragma unroll
        for (int i = 0; i < 4; i++)
#pragma unroll
            for (int j = 0; j < 4; j++) racc[grp - 1][t][i * 4 + j] = acc[i][j];
    }
    __syncthreads();
    if (grp == 0) {
#pragma unroll
        for (int gg = 0; gg < 3; gg++)
#pragma unroll
            for (int i = 0; i < 4; i++)
#pragma unroll
                for (int j = 0; j < 4; j++) acc[i][j] += racc[gg][t][i * 4 + j];
        float* dst = g_ctxp + ((size_t)sl * NB * HEADS + bh) * (DH * DH);
#pragma unroll
        for (int i = 0; i < 4; i++)
#pragma unroll
            for (int j = 0; j < 4; j++)
                dst[(td * 4 + i) * DH + te * 4 + j] = acc[i][j];
    }
}

// ---------------------------------------------------------------------------
// Kernel 4: fused weight Wf -> half. Grid (NB*HEADS, 2).
// ---------------------------------------------------------------------------
__global__ __launch_bounds__(256) void wf_kernel(const float* __restrict__ w_out) {
    __shared__ float cs[DH][DH];
    __shared__ float ws[128][DH + 1];
    const int bh = blockIdx.x;
    const int o0 = blockIdx.y * 128;
    const int b = bh >> 2, h = bh & 3;
    const int tid = threadIdx.x;

    {
        const size_t ss = (size_t)NB * HEADS * DH * DH;
        const size_t base = (size_t)bh * DH * DH;
        for (int i = tid; i < DH * DH; i += 256) {
            float s = 0.f;
#pragma unroll
            for (int sl = 0; sl < NSLICE; ++sl)
                s += g_ctxp[sl * ss + base + i];
            ((float*)cs)[i] = s;
        }
    }
#pragma unroll
    for (int it = 0; it < 4; ++it) {
        int idx = it * 256 + tid;
        int row = idx >> 3, e4 = idx & 7;
        float4 v = *(const float4*)&w_out[(o0 + row) * HID + h * DH + e4 * 4];
        ws[row][e4 * 4 + 0] = v.x; ws[row][e4 * 4 + 1] = v.y;
        ws[row][e4 * 4 + 2] = v.z; ws[row][e4 * 4 + 3] = v.w;
    }
    __syncthreads();

    if (tid < 128) {
        const int o = o0 + tid;
        float w[DH];
#pragma unroll
        for (int e = 0; e < DH; ++e) w[e] = ws[tid][e];

        __half* dst = g_wf + ((size_t)b * DIMC + o) * HID + h * DH;
#pragma unroll 4
        for (int d = 0; d < DH; d += 4) {
            float s0 = 0.f, s1 = 0.f, s2 = 0.f, s3 = 0.f;
#pragma unroll
            for (int e = 0; e < DH; ++e) {
                float we = w[e];
                s0 += we * cs[d + 0][e];
                s1 += we * cs[d + 1][e];
                s2 += we * cs[d + 2][e];
                s3 += we * cs[d + 3][e];
            }
            uint2 r;
            r.x = pack_h2(s0, s1);
            r.y = pack_h2(s2, s3);
            *(uint2*)&dst[d] = r;
        }
    }
}

// ---------------------------------------------------------------------------
// Kernel 5 (fp16 mma + ldmatrix + cp.async double-buffer + fused LN)
// out = Wf·q + b_out, LN over o. CTA 256(M) x 64(N), K=128, BK=32.
// ---------------------------------------------------------------------------
#define OA_LD 20
#define OB_LDW 36
#define OST_WORDS (256 * OA_LD + 32 * OB_LDW)   // 6272 words
#define OST_BYTES (OST_WORDS * 4)               // 25088
#define OAB_OFF   (256 * OA_LD * 4)             // 20480 bytes, B offset in stage
#define OUT_DYN   (2 * OST_BYTES)               // 50176 bytes

__global__ __launch_bounds__(256) void out_ln_mma(const float* __restrict__ b_out,
                                                  const float* __restrict__ gamma,
                                                  const float* __restrict__ beta,
                                                  float* __restrict__ out) {
    extern __shared__ uint32_t dynbuf[];
    __shared__ float s_sum[4][64];
    __shared__ float s_sq [4][64];
    __shared__ float s_mean[64], s_rstd[64];

    const int b  = blockIdx.y;
    const int n0 = blockIdx.x * 64;
    const __half* A = g_wf + (size_t)b * DIMC * HID;
    const __half* Q = g_qk + (size_t)b * (2 * HID) * NSP;

    const int tid = threadIdx.x, wid = tid >> 5, lane = tid & 31;
    const int wm = wid >> 1, wn = wid & 1;
    const int g = lane >> 2, tg = lane & 3;

    const uint32_t base_u = smem_u32(dynbuf);
    const int lrow = (lane & 7) + (lane & 8);
    const uint32_t aOff = base_u + (uint32_t)(lrow * 80 + (lane >> 4) * 16)
                        + (uint32_t)(wm * 64 * 80);
    const uint32_t bOff = base_u + OAB_OFF + (uint32_t)(lrow * 144 + (lane >> 4) * 16)
                        + (uint32_t)(wn * 64);

    // cp.async staging coordinates (16B granules)
    const int ar = tid >> 2, aq = tid & 3;       // A: rows tid>>2 + j*64, quad aq
    const int bk = tid >> 3, bu = tid & 7;       // B: k row, 16B unit

    // Issue one chunk's loads into stage s
    auto issue = [&](int k0, int s) {
        uint32_t st = base_u + (uint32_t)(s * OST_BYTES);
#pragma unroll
        for (int j = 0; j < 4; ++j) {
            int row = j * 64 + ar;
            cp_async16(st + (uint32_t)(row * 80 + aq * 16),
                       A + (size_t)row * HID + k0 + aq * 8);
        }
        cp_async16(st + (uint32_t)(OAB_OFF + bk * 144 + bu * 16),
                   Q + (size_t)(k0 + bk) * NSP + n0 + bu * 8);
    };

    float acc[4][4][4];
#pragma unroll
    for (int i = 0; i < 4; ++i)
#pragma unroll
        for (int j = 0; j < 4; ++j)
#pragma unroll
            for (int e = 0; e < 4; ++e) acc[i][j][e] = 0.f;

    issue(0, 0); CP_COMMIT();

#pragma unroll 1
    for (int ch = 0; ch < 4; ++ch) {
        if (ch < 3) { issue((ch + 1) * 32, (ch + 1) & 1); CP_COMMIT(); CP_WAIT(1); }
        else        { CP_WAIT(0); }
        __syncthreads();

        const uint32_t sb = (uint32_t)((ch & 1) * OST_BYTES);
#pragma unroll
        for (int ks2 = 0; ks2 < 2; ++ks2) {
            uint32_t af[4][4], bf[4][2];
#pragma unroll
            for (int i = 0; i < 4; ++i)
                ldsm_x4(af[i], aOff + sb + (uint32_t)(i * 16 * 80 + ks2 * 32));
            {
                uint32_t t[4];
                ldsm_x4_t(t, bOff + sb + (uint32_t)(ks2 * 16 * 144));
                bf[0][0] = t[0]; bf[0][1] = t[1]; bf[1][0] = t[2]; bf[1][1] = t[3];
                ldsm_x4_t(t, bOff + sb + (uint32_t)(ks2 * 16 * 144 + 32));
                bf[2][0] = t[0]; bf[2][1] = t[1]; bf[3][0] = t[2]; bf[3][1] = t[3];
            }
#pragma unroll
            for (int i = 0; i < 4; ++i)
#pragma unroll
                for (int jn = 0; jn < 4; ++jn)
                    mma_f16(acc[i][jn], af[i], bf[jn]);
        }
        __syncthreads();
    }

#pragma unroll
    for (int i = 0; i < 4; ++i) {
        float bo0 = b_out[wm * 64 + i * 16 + g];
        float bo1 = b_out[wm * 64 + i * 16 + g + 8];
#pragma unroll
        for (int jn = 0; jn < 4; ++jn) {
            acc[i][jn][0] += bo0; acc[i][jn][1] += bo0;
            acc[i][jn][2] += bo1; acc[i][jn][3] += bo1;
        }
    }

    float ps[8], pq[8];
#pragma unroll
    for (int c = 0; c < 8; ++c) { ps[c] = 0.f; pq[c] = 0.f; }
#pragma unroll
    for (int i = 0; i < 4; ++i)
#pragma unroll
        for (int jn = 0; jn < 4; ++jn)
#pragma unroll
            for (int e = 0; e < 2; ++e) {
                float v0 = acc[i][jn][e];
                float v1 = acc[i][jn][2 + e];
                ps[jn * 2 + e] += v0 + v1;
                pq[jn * 2 + e] += v0 * v0 + v1 * v1;
            }
#pragma unroll
    for (int c = 0; c < 8; ++c) {
#pragma unroll
        for (int off = 4; off < 32; off <<= 1) {
            ps[c] += __shfl_xor_sync(0xffffffffu, ps[c], off);
            pq[c] += __shfl_xor_sync(0xffffffffu, pq[c], off);
        }
    }
    if (g == 0) {
#pragma unroll
        for (int jn = 0; jn < 4; ++jn)
#pragma unroll
            for (int e = 0; e < 2; ++e) {
                int col = wn * 32 + jn * 8 + tg * 2 + e;
                s_sum[wm][col] = ps[jn * 2 + e];
                s_sq [wm][col] = pq[jn * 2 + e];
            }
    }
    __syncthreads();
    if (tid < 64) {
        float s = s_sum[0][tid] + s_sum[1][tid] + s_sum[2][tid] + s_sum[3][tid];
        float q = s_sq [0][tid] + s_sq [1][tid] + s_sq [2][tid] + s_sq [3][tid];
        float mean = s * (1.0f / 256.0f);
        float var  = q * (1.0f / 256.0f) - mean * mean;
        s_mean[tid] = mean;
        s_rstd[tid] = rsqrtf(var + EPS);
    }
    __syncthreads();

#pragma unroll
    for (int i = 0; i < 4; ++i) {
        int o0 = wm * 64 + i * 16 + g;
        float g0 = gamma[o0], b0v = beta[o0];
        float g1 = gamma[o0 + 8], b1v = beta[o0 + 8];
#pragma unroll
        for (int jn = 0; jn < 4; ++jn) {
            int cl = wn * 32 + jn * 8 + tg * 2;
            float m0 = s_mean[cl],     r0 = s_rstd[cl];
            float m1 = s_mean[cl + 1], r1 = s_rstd[cl + 1];
            *(float2*)&out[((size_t)b * DIMC + o0) * NSP + n0 + cl] =
                make_float2((acc[i][jn][0] - m0) * r0 * g0 + b0v,
                            (acc[i][jn][1] - m1) * r1 * g0 + b0v);
            *(float2*)&out[((size_t)b * DIMC + o0 + 8) * NSP + n0 + cl] =
                make_float2((acc[i][jn][2] - m0) * r0 * g1 + b1v,
                            (acc[i][jn][3] - m1) * r1 * g1 + b1v);
        }
    }
}

// ---------------------------------------------------------------------------
extern "C" void kernel_launch(void* const* d_in, const int* in_sizes, int n_in,
                              void* d_out, int out_size) {
    const float* x     = (const float*)d_in[0];
    const float* w_qkv = (const float*)d_in[1];
    const float* w_out = (const float*)d_in[2];
    const float* b_out = (const float*)d_in[3];
    const float* g     = (const float*)d_in[4];
    const float* bb    = (const float*)d_in[5];
    float* out = (float*)d_out;

    cudaFuncSetAttribute(qkv_mma, cudaFuncAttributeMaxDynamicSharedMemorySize, QKV_DYN);
    cudaFuncSetAttribute(out_ln_mma, cudaFuncAttributeMaxDynamicSharedMemorySize, OUT_DYN);

    qkv_mma<<<dim3(NSP / 128, NB), 256, QKV_DYN>>>(w_qkv, x);
    krow<<<NB * HID / 8, 256>>>();
    ctx_slice<<<dim3(NB * HEADS, NSLICE), 256>>>();
    wf_kernel<<<dim3(NB * HEADS, 2), 256>>>(w_out);
    out_ln_mma<<<dim3(NSP / 64, NB), 256, OUT_DYN>>>(b_out, g, bb, out);
}